// round 8
// baseline (speedup 1.0000x reference)
#include <cuda_runtime.h>
#include <cuda_bf16.h>
#include <cstdint>

#define BB 2
#define LL 4096
#define EMBED 2048
#define DIN 4096
#define NH 32
#define HD 128
#define DS 64
#define CONVDIM 4224   // DIN + 2*DS
#define DPROJ 8352     // 2*DIN + 2*DS + NH
#define CHUNK 256
#define NCH 16         // LL / CHUNK
#define NBC (BB*NCH)   // 32

// ------------------- scratch (device globals; no cudaMalloc allowed) ---------
__device__ float g_zx[(size_t)BB*LL*DPROJ];        // in_proj output
__device__ float g_xbc[(size_t)BB*LL*CONVDIM];     // conv+silu output
__device__ float g_dt[BB*LL*NH];                   // softplus(dt)
__device__ float g_a[NBC*CHUNK*NH];                // cumsum(dA) per chunk
__device__ float g_alast[NBC*NH];
__device__ float g_scores[(size_t)NBC*CHUNK*CHUNK];
__device__ float g_states[(size_t)NBC*NH*HD*DS];   // [b,c,h,p,n]
__device__ float g_prev[(size_t)NBC*NH*HD*DS];     // state entering chunk c
__device__ float g_y[(size_t)BB*LL*DIN];

// bf16 hi/lo split buffers
__device__ __nv_bfloat16 g_uh[(size_t)BB*LL*EMBED];
__device__ __nv_bfloat16 g_ul[(size_t)BB*LL*EMBED];
__device__ __nv_bfloat16 g_w1h[(size_t)DPROJ*EMBED];
__device__ __nv_bfloat16 g_w1l[(size_t)DPROJ*EMBED];
__device__ __nv_bfloat16 g_w2h[(size_t)EMBED*DIN];
__device__ __nv_bfloat16 g_w2l[(size_t)EMBED*DIN];
__device__ __nv_bfloat16 g_ynh[(size_t)BB*LL*DIN];
__device__ __nv_bfloat16 g_ynl[(size_t)BB*LL*DIN];

// ------------------- PTX helpers (sm_80-era: valid on base sm_103 target) ----
__device__ __forceinline__ uint32_t s2u(const void* p) {
    uint32_t a;
    asm("{ .reg .u64 t; cvta.to.shared.u64 t, %1; cvt.u32.u64 %0, t; }" : "=r"(a) : "l"(p));
    return a;
}
__device__ __forceinline__ void cpasync16(uint32_t s, const void* g, int srcsize) {
    asm volatile("cp.async.ca.shared.global [%0], [%1], 16, %2;"
                 :: "r"(s), "l"(g), "r"(srcsize));
}
__device__ __forceinline__ void cpcommit() {
    asm volatile("cp.async.commit_group;" ::: "memory");
}
template <int N>
__device__ __forceinline__ void cpwait() {
    asm volatile("cp.async.wait_group %0;" :: "n"(N) : "memory");
}
__device__ __forceinline__ void ldsm4(uint32_t* r, uint32_t addr) {
    asm volatile("ldmatrix.sync.aligned.m8n8.x4.shared.b16 {%0,%1,%2,%3}, [%4];"
                 : "=r"(r[0]), "=r"(r[1]), "=r"(r[2]), "=r"(r[3]) : "r"(addr));
}
__device__ __forceinline__ void mma16816(float* c, const uint32_t* a, const uint32_t* b) {
    asm volatile(
        "mma.sync.aligned.m16n8k16.row.col.f32.bf16.bf16.f32 "
        "{%0,%1,%2,%3},{%4,%5,%6,%7},{%8,%9},{%0,%1,%2,%3};"
        : "+f"(c[0]), "+f"(c[1]), "+f"(c[2]), "+f"(c[3])
        : "r"(a[0]), "r"(a[1]), "r"(a[2]), "r"(a[3]), "r"(b[0]), "r"(b[1]));
}

// ------------------- fp32 -> bf16 hi/lo split --------------------------------
__global__ void split_k(const float* __restrict__ s, __nv_bfloat16* __restrict__ hi,
                        __nv_bfloat16* __restrict__ lo, int n4)
{
    int i = blockIdx.x * 256 + threadIdx.x;
    if (i >= n4) return;
    float4 v = ((const float4*)s)[i];
    __nv_bfloat16 h0 = __float2bfloat16(v.x), h1 = __float2bfloat16(v.y);
    __nv_bfloat16 h2 = __float2bfloat16(v.z), h3 = __float2bfloat16(v.w);
    __nv_bfloat162* H = (__nv_bfloat162*)hi;
    __nv_bfloat162* L = (__nv_bfloat162*)lo;
    H[i*2+0] = __nv_bfloat162(h0, h1);
    H[i*2+1] = __nv_bfloat162(h2, h3);
    L[i*2+0] = __nv_bfloat162(__float2bfloat16(v.x - __bfloat162float(h0)),
                              __float2bfloat16(v.y - __bfloat162float(h1)));
    L[i*2+1] = __nv_bfloat162(__float2bfloat16(v.z - __bfloat162float(h2)),
                              __float2bfloat16(v.w - __bfloat162float(h3)));
}

// ------------------- HMMA bf16x3 GEMM: C[M,N] = A[M,K] @ B[N,K]^T ------------
// CTA tile 128x64, BK=64, 256 threads = 4x2 warps, warp tile 32x32.
// Per-thread code identical to the proven round-3 config; smaller CTA gives
// 2 CTAs/SM (two independent barrier domains) at the same 16 warps/SM.
#define HBM 128
#define HBN 64
#define HBK 64
#define HLD 72                       // padded leading dim (bf16 elems)
#define HAMB (128*HLD*2)             // A matrix bytes per stage (18432)
#define HBMB (64*HLD*2)              // B matrix bytes per stage (9216)
#define HSTAGEB (2*HAMB + 2*HBMB)    // bytes per stage (55296)

__global__ __launch_bounds__(256) void hgemm3(
    int M, int N, int K,
    const __nv_bfloat16* __restrict__ Ah, const __nv_bfloat16* __restrict__ Al,
    const __nv_bfloat16* __restrict__ Bh, const __nv_bfloat16* __restrict__ Bl,
    float* __restrict__ C)
{
    extern __shared__ char smem[];
    const int tid = threadIdx.x;
    const int lane = tid & 31, wid = tid >> 5;
    const int wm = wid & 3, wn = wid >> 2;   // 4(m) x 2(n) warp grid, warp tile 32x32
    const int bm = blockIdx.y * HBM, bn = blockIdx.x * HBN;
    const uint32_t sbase = s2u(smem);

    // ldmatrix lane mapping
    const int arow = lane & 15, akoff = (lane >> 4) << 3;
    const int bnl = (lane & 7) + ((lane >> 4) << 3);
    const int bkl = ((lane >> 3) & 1) << 3;

    float acc[2][4][4];
    #pragma unroll
    for (int mt = 0; mt < 2; mt++)
        #pragma unroll
        for (int nt = 0; nt < 4; nt++)
            #pragma unroll
            for (int i = 0; i < 4; i++) acc[mt][nt][i] = 0.f;

    const int nk = K / HBK;

    // ---- stage loader: A 1024 16B-chunks, B 512 16B-chunks, per matrix ----
    auto load_stage = [&](int st, int k0) {
        uint32_t sb = sbase + st * HSTAGEB;
        #pragma unroll
        for (int i = 0; i < 4; i++) {
            int chunk = tid + i * 256;
            int row = chunk >> 3, c = chunk & 7;
            uint32_t so = (uint32_t)(row * HLD + c * 8) * 2;
            size_t ga = (size_t)(bm + row) * K + k0 + c * 8;
            cpasync16(sb + so,        Ah + ga, 16);
            cpasync16(sb + HAMB + so, Al + ga, 16);
        }
        #pragma unroll
        for (int i = 0; i < 2; i++) {
            int chunk = tid + i * 256;
            int row = chunk >> 3, c = chunk & 7;
            uint32_t so = (uint32_t)(row * HLD + c * 8) * 2;
            int brow = bn + row;
            int sz = (brow < N) ? 16 : 0;
            int bcl = (brow < N) ? brow : 0;
            size_t gb = (size_t)bcl * K + k0 + c * 8;
            cpasync16(sb + 2*HAMB + so,        Bh + gb, sz);
            cpasync16(sb + 2*HAMB + HBMB + so, Bl + gb, sz);
        }
        cpcommit();
    };

    load_stage(0, 0);

    for (int kt = 0; kt < nk; ++kt) {
        if (kt + 1 < nk) {
            load_stage((kt + 1) & 1, (kt + 1) * HBK);
            cpwait<1>();
        } else {
            cpwait<0>();
        }
        __syncthreads();

        uint32_t sb = sbase + (kt & 1) * HSTAGEB;
        uint32_t sAh = sb, sAl = sb + HAMB, sBh = sb + 2*HAMB, sBl = sb + 2*HAMB + HBMB;

        #pragma unroll
        for (int kh = 0; kh < 4; kh++) {
            int k = kh * 16;
            uint32_t bfh[2][4], bfl[2][4];
            #pragma unroll
            for (int ntp = 0; ntp < 2; ntp++) {
                uint32_t off = (uint32_t)((wn * 32 + ntp * 16 + bnl) * HLD + k + bkl) * 2;
                ldsm4(bfh[ntp], sBh + off);
                ldsm4(bfl[ntp], sBl + off);
            }
            #pragma unroll
            for (int mt = 0; mt < 2; mt++) {
                uint32_t aoff = (uint32_t)((wm * 32 + mt * 16 + arow) * HLD + k + akoff) * 2;
                uint32_t af[4];
                ldsm4(af, sAh + aoff);
                #pragma unroll
                for (int nt = 0; nt < 4; nt++)
                    mma16816(acc[mt][nt], af, &bfh[nt >> 1][(nt & 1) * 2]);
                #pragma unroll
                for (int nt = 0; nt < 4; nt++)
                    mma16816(acc[mt][nt], af, &bfl[nt >> 1][(nt & 1) * 2]);
                ldsm4(af, sAl + aoff);
                #pragma unroll
                for (int nt = 0; nt < 4; nt++)
                    mma16816(acc[mt][nt], af, &bfh[nt >> 1][(nt & 1) * 2]);
            }
        }
        __syncthreads();
    }

    // ---- epilogue ----
    #pragma unroll
    for (int mt = 0; mt < 2; mt++) {
        int row0 = bm + wm * 32 + mt * 16 + (lane >> 2);
        #pragma unroll
        for (int nt = 0; nt < 4; nt++) {
            int col = bn + wn * 32 + nt * 8 + (lane & 3) * 2;
            if (col < N) {
                *(float2*)&C[(size_t)row0 * N + col] =
                    make_float2(acc[mt][nt][0], acc[mt][nt][1]);
                *(float2*)&C[(size_t)(row0 + 8) * N + col] =
                    make_float2(acc[mt][nt][2], acc[mt][nt][3]);
            }
        }
    }
}

// ------------------- depthwise causal conv (k=4) + silu ----------------------
__global__ void conv_silu_k(const float* __restrict__ cw, const float* __restrict__ cb)
{
    int idx = blockIdx.x * 256 + threadIdx.x;
    const int total = BB * LL * CONVDIM;
    if (idx >= total) return;
    int ch = idx % CONVDIM;
    int bl = idx / CONVDIM;
    int l = bl % LL, b = bl / LL;
    float acc = cb[ch];
    #pragma unroll
    for (int k = 0; k < 4; k++) {
        int ll = l - 3 + k;
        if (ll >= 0)
            acc += g_zx[(size_t)(b * LL + ll) * DPROJ + DIN + ch] * cw[ch * 4 + k];
    }
    g_xbc[idx] = acc / (1.f + __expf(-acc));
}

// ------------------- per-chunk cumsum of dA (fused softplus + warp scan) -----
__global__ void cumsum_k(const float* __restrict__ A_log, const float* __restrict__ dt_bias)
{
    int bch = blockIdx.x;            // bc*NH + h
    int h = bch & 31, bc = bch >> 5;
    int b = bc / NCH, c = bc % NCH;
    int t = threadIdx.x;             // 32
    float Ah = -__expf(A_log[h]);
    float bias = dt_bias[h];
    size_t row0 = (size_t)(b * LL + c * CHUNK) + t * 8;
    float v[8];
    #pragma unroll
    for (int j = 0; j < 8; j++) {
        float x = g_zx[(row0 + j) * DPROJ + DIN + CONVDIM + h] + bias;
        float sp = (x > 20.f) ? x : log1pf(__expf(x));
        g_dt[(row0 + j) * NH + h] = sp;
        v[j] = sp * Ah;
    }
    float loc = 0.f;
    #pragma unroll
    for (int j = 0; j < 8; j++) { loc += v[j]; v[j] = loc; }
    float pre = loc;
    #pragma unroll
    for (int o = 1; o < 32; o <<= 1) {
        float nv = __shfl_up_sync(0xffffffffu, pre, o);
        if (t >= o) pre += nv;
    }
    pre -= loc;   // exclusive prefix
    #pragma unroll
    for (int j = 0; j < 8; j++) g_a[(bc * CHUNK + t * 8 + j) * NH + h] = pre + v[j];
    if (t == 31) g_alast[bc * NH + h] = pre + loc;
}

// ------------------- scores = C @ B^T per chunk (lower tiles only) -----------
__global__ __launch_bounds__(256) void scores_k()
{
    int jt = blockIdx.x, it = blockIdx.y, bc = blockIdx.z;
    if (jt > it) return;
    int b = bc / NCH, c = bc % NCH;
    __shared__ float CtT[64][65];
    __shared__ float BtT[64][65];
    int tid = threadIdx.x;
    for (int t = tid; t < 64 * 64; t += 256) {
        int r = t >> 6, n = t & 63;
        int rowC = b * LL + c * CHUNK + it * 64 + r;
        int rowB = b * LL + c * CHUNK + jt * 64 + r;
        CtT[n][r] = g_xbc[(size_t)rowC * CONVDIM + DIN + DS + n];
        BtT[n][r] = g_xbc[(size_t)rowB * CONVDIM + DIN + n];
    }
    __syncthreads();
    int ty = tid >> 4, tx = tid & 15;
    float acc[4][4];
    #pragma unroll
    for (int i = 0; i < 4; i++)
        #pragma unroll
        for (int j = 0; j < 4; j++) acc[i][j] = 0.f;
    for (int n = 0; n < 64; n++) {
        float a[4], w[4];
        #pragma unroll
        for (int i = 0; i < 4; i++) a[i] = CtT[n][ty * 4 + i];
        #pragma unroll
        for (int j = 0; j < 4; j++) w[j] = BtT[n][tx * 4 + j];
        #pragma unroll
        for (int i = 0; i < 4; i++)
            #pragma unroll
            for (int j = 0; j < 4; j++) acc[i][j] += a[i] * w[j];
    }
    #pragma unroll
    for (int i = 0; i < 4; i++)
        #pragma unroll
        for (int j = 0; j < 4; j++)
            g_scores[((size_t)bc << 16) + (it * 64 + ty * 4 + i) * 256 + jt * 64 + tx * 4 + j] = acc[i][j];
}

// ------------------- per-chunk states[h,p,n] ---------------------------------
__global__ __launch_bounds__(256) void states_k()
{
    int bch = blockIdx.x;              // bc*NH + h
    int h = bch % NH, bc = bch / NH;
    int b = bc / NCH, c = bc % NCH;
    __shared__ float Xq[32][128];
    __shared__ float Bco[32][64];
    __shared__ float coef[32];
    int tid = threadIdx.x;
    float alast = g_alast[bc * NH + h];
    int tp = tid >> 4, tn = tid & 15;
    float acc[8][4];
    #pragma unroll
    for (int i = 0; i < 8; i++)
        #pragma unroll
        for (int j = 0; j < 4; j++) acc[i][j] = 0.f;

    for (int q0 = 0; q0 < CHUNK; q0 += 32) {
        __syncthreads();
        if (tid < 32) {
            int gq = q0 + tid;
            float aq = g_a[(bc * CHUNK + gq) * NH + h];
            float dtq = g_dt[(size_t)(b * LL + c * CHUNK + gq) * NH + h];
            coef[tid] = dtq * __expf(alast - aq);
        }
        #pragma unroll
        for (int t = 0; t < 16; t++) {
            int idx = tid + t * 256;
            int q = idx >> 7, p = idx & 127;
            Xq[q][p] = g_xbc[(size_t)(b * LL + c * CHUNK + q0 + q) * CONVDIM + h * HD + p];
        }
        __syncthreads();
        #pragma unroll
        for (int t = 0; t < 8; t++) {
            int idx = tid + t * 256;
            int q = idx >> 6, n = idx & 63;
            Bco[q][n] = g_xbc[(size_t)(b * LL + c * CHUNK + q0 + q) * CONVDIM + DIN + n] * coef[q];
        }
        __syncthreads();
        for (int q = 0; q < 32; q++) {
            float xv[8], bv[4];
            #pragma unroll
            for (int i = 0; i < 8; i++) xv[i] = Xq[q][tp * 8 + i];
            #pragma unroll
            for (int j = 0; j < 4; j++) bv[j] = Bco[q][tn * 4 + j];
            #pragma unroll
            for (int i = 0; i < 8; i++)
                #pragma unroll
                for (int j = 0; j < 4; j++) acc[i][j] += xv[i] * bv[j];
        }
    }
    size_t base = (size_t)bch * HD * DS;
    #pragma unroll
    for (int i = 0; i < 8; i++)
        #pragma unroll
        for (int j = 0; j < 4; j++)
            g_states[base + (tp * 8 + i) * DS + tn * 4 + j] = acc[i][j];
}

// ------------------- sequential inter-chunk scan (split over 16 slices) ------
__global__ void scan_k()
{
    int bh = blockIdx.x;            // b*NH + h
    int b = bh >> 5, h = bh & 31;
    int e = blockIdx.y * 512 + threadIdx.x;   // element in HD*DS plane
    float s = 0.f;
    for (int c = 0; c < NCH; c++) {
        int bc = b * NCH + c;
        float dec = __expf(g_alast[bc * NH + h]);
        size_t base = (size_t)(bc * NH + h) * HD * DS;
        g_prev[base + e] = s;
        s = s * dec + g_states[base + e];
    }
}

// ------------------- y = intra + inter + D*x ---------------------------------
__global__ __launch_bounds__(256) void ych_k(const float* __restrict__ D_skip)
{
    int it = blockIdx.x;   // 0..3 (64-row tile)
    int h  = blockIdx.y;   // 0..31
    int bc = blockIdx.z;   // 0..31
    int b = bc / NCH, c = bc % NCH;
    __shared__ float sh[6400];
    float* ai = sh;          // 64
    float* Wt = sh + 64;     // 64*33 (phase1) / 32*64 CtT (phase2)
    float* Xt = sh + 2176;   // 32*128 (phase1) / 32*132 prevT (phase2)
    int tid = threadIdx.x;
    int ty = tid >> 5, tx = tid & 31;
    int row0 = b * LL + c * CHUNK;
    if (tid < 64) ai[tid] = g_a[(bc * CHUNK + it * 64 + tid) * NH + h];
    float acc[8][4];
    #pragma unroll
    for (int i = 0; i < 8; i++)
        #pragma unroll
        for (int j = 0; j < 4; j++) acc[i][j] = 0.f;
    __syncthreads();

    int jtmax = 2 * it + 1;
    for (int jt = 0; jt <= jtmax; jt++) {
        int j0 = jt * 32;
        #pragma unroll
        for (int t = 0; t < 8; t++) {
            int idx = tid + t * 256;
            int i = idx >> 5, j = idx & 31;
            int gi = it * 64 + i, gj = j0 + j;
            float w = 0.f;
            if (gj <= gi) {
                float aj = g_a[(bc * CHUNK + gj) * NH + h];
                float dtj = g_dt[(size_t)(row0 + gj) * NH + h];
                w = g_scores[((size_t)bc << 16) + gi * 256 + gj] * __expf(ai[i] - aj) * dtj;
            }
            Wt[i * 33 + j] = w;
        }
        #pragma unroll
        for (int t = 0; t < 16; t++) {
            int idx = tid + t * 256;
            int j = idx >> 7, p = idx & 127;
            Xt[j * 128 + p] = g_xbc[(size_t)(row0 + j0 + j) * CONVDIM + h * HD + p];
        }
        __syncthreads();
        for (int j = 0; j < 32; j++) {
            float4 xv = *(float4*)&Xt[j * 128 + tx * 4];
            #pragma unroll
            for (int i = 0; i < 8; i++) {
                float w = Wt[(ty * 8 + i) * 33 + j];
                acc[i][0] += w * xv.x; acc[i][1] += w * xv.y;
                acc[i][2] += w * xv.z; acc[i][3] += w * xv.w;
            }
        }
        __syncthreads();
    }

    float acc2[8][4];
    #pragma unroll
    for (int i = 0; i < 8; i++)
        #pragma unroll
        for (int j = 0; j < 4; j++) acc2[i][j] = 0.f;
    size_t pbase = (size_t)(bc * NH + h) * HD * DS;
    for (int nt = 0; nt < 2; nt++) {
        int n0 = nt * 32;
        #pragma unroll
        for (int t = 0; t < 8; t++) {
            int idx = tid + t * 256;
            int i = idx >> 5, n = idx & 31;
            Wt[n * 64 + i] = g_xbc[(size_t)(row0 + it * 64 + i) * CONVDIM + DIN + DS + n0 + n];
        }
        #pragma unroll
        for (int t = 0; t < 16; t++) {
            int idx = tid + t * 256;
            int p = idx >> 5, n = idx & 31;
            Xt[n * 132 + p] = g_prev[pbase + (size_t)p * DS + n0 + n];
        }
        __syncthreads();
        for (int n = 0; n < 32; n++) {
            float4 pv = *(float4*)&Xt[n * 132 + tx * 4];
            #pragma unroll
            for (int i = 0; i < 8; i++) {
                float cv = Wt[n * 64 + ty * 8 + i];
                acc2[i][0] += cv * pv.x; acc2[i][1] += cv * pv.y;
                acc2[i][2] += cv * pv.z; acc2[i][3] += cv * pv.w;
            }
        }
        __syncthreads();
    }

    float Dh = D_skip[h];
    #pragma unroll
    for (int i = 0; i < 8; i++) {
        int li = ty * 8 + i;
        int gi = it * 64 + li;
        float ea = __expf(ai[li]);
        float4 xv = *(const float4*)&g_xbc[(size_t)(row0 + gi) * CONVDIM + h * HD + tx * 4];
        float4 o;
        o.x = acc[i][0] + ea * acc2[i][0] + Dh * xv.x;
        o.y = acc[i][1] + ea * acc2[i][1] + Dh * xv.y;
        o.z = acc[i][2] + ea * acc2[i][2] + Dh * xv.z;
        o.w = acc[i][3] + ea * acc2[i][3] + Dh * xv.w;
        *(float4*)&g_y[(size_t)(row0 + gi) * DIN + h * HD + tx * 4] = o;
    }
}

// ------------------- gate by sigmoid(z), per-head RMS norm, write hi/lo ------
__global__ void gate_rms_k(const float* __restrict__ norm_w)
{
    int h = blockIdx.x & 31;
    int bl = blockIdx.x >> 5;
    int p = threadIdx.x;   // 128
    float y = g_y[(size_t)bl * DIN + h * HD + p];
    float z = g_zx[(size_t)bl * DPROJ + h * HD + p];
    float v = y / (1.f + __expf(-z));
    float v2 = v * v;
    #pragma unroll
    for (int o = 16; o; o >>= 1) v2 += __shfl_xor_sync(0xffffffffu, v2, o);
    __shared__ float ws[4];
    if ((p & 31) == 0) ws[p >> 5] = v2;
    __syncthreads();
    float tot = ws[0] + ws[1] + ws[2] + ws[3];
    float inv = rsqrtf(tot * (1.f / HD) + 1e-6f);
    float r = v * inv * norm_w[h * HD + p];
    size_t oi = (size_t)bl * DIN + h * HD + p;
    __nv_bfloat16 rh = __float2bfloat16(r);
    g_ynh[oi] = rh;
    g_ynl[oi] = __float2bfloat16(r - __bfloat162float(rh));
}

// ------------------- launch ---------------------------------------------------
extern "C" void kernel_launch(void* const* d_in, const int* in_sizes, int n_in,
                              void* d_out, int out_size)
{
    const float* u         = (const float*)d_in[0];
    const float* in_proj_w = (const float*)d_in[1];
    const float* conv_w    = (const float*)d_in[2];
    const float* conv_b    = (const float*)d_in[3];
    const float* A_log     = (const float*)d_in[4];
    const float* dt_bias   = (const float*)d_in[5];
    const float* D_skip    = (const float*)d_in[6];
    const float* norm_w    = (const float*)d_in[7];
    const float* o_proj_w  = (const float*)d_in[8];
    float* out = (float*)d_out;

    float* zx = nullptr;
    cudaGetSymbolAddress((void**)&zx, g_zx);
    __nv_bfloat16 *uh, *ul, *w1h, *w1l, *w2h, *w2l, *ynh, *ynl;
    cudaGetSymbolAddress((void**)&uh,  g_uh);
    cudaGetSymbolAddress((void**)&ul,  g_ul);
    cudaGetSymbolAddress((void**)&w1h, g_w1h);
    cudaGetSymbolAddress((void**)&w1l, g_w1l);
    cudaGetSymbolAddress((void**)&w2h, g_w2h);
    cudaGetSymbolAddress((void**)&w2l, g_w2l);
    cudaGetSymbolAddress((void**)&ynh, g_ynh);
    cudaGetSymbolAddress((void**)&ynl, g_ynl);

    const int SMEM_GEMM = 2 * HSTAGEB;   // 110592 -> 2 CTAs/SM
    cudaFuncSetAttribute(hgemm3, cudaFuncAttributeMaxDynamicSharedMemorySize, SMEM_GEMM);

    const int M = BB * LL;   // 8192

    // 0) hi/lo splits of GEMM inputs
    {
        int n4;
        n4 = (M * EMBED) / 4;
        split_k<<<(n4 + 255) / 256, 256>>>(u, uh, ul, n4);
        n4 = (DPROJ * EMBED) / 4;
        split_k<<<(n4 + 255) / 256, 256>>>(in_proj_w, w1h, w1l, n4);
        n4 = (EMBED * DIN) / 4;
        split_k<<<(n4 + 255) / 256, 256>>>(o_proj_w, w2h, w2l, n4);
    }
    // 1) in_proj: zx = u @ W1^T  (HMMA bf16x3)
    hgemm3<<<dim3((DPROJ + HBN - 1) / HBN, M / HBM), 256, SMEM_GEMM>>>(
        M, DPROJ, EMBED, uh, ul, w1h, w1l, zx);
    // 2) causal depthwise conv + silu
    conv_silu_k<<<(BB * LL * CONVDIM + 255) / 256, 256>>>(conv_w, conv_b);
    // 3) fused dt softplus + per-chunk cumsum (parallel scan)
    cumsum_k<<<NBC * NH, 32>>>(A_log, dt_bias);
    // 4) chunk attention scores (lower tiles)
    scores_k<<<dim3(4, 4, NBC), 256>>>();
    // 5) per-chunk end states
    states_k<<<NBC * NH, 256>>>();
    // 6) inter-chunk scan (16 slices per (b,h))
    scan_k<<<dim3(BB * NH, 16), 512>>>();
    // 7) y = intra + inter + D*x
    ych_k<<<dim3(4, NH, NBC), 256>>>(D_skip);
    // 8) gating + RMS norm (writes bf16 hi/lo)
    gate_rms_k<<<BB * LL * NH, 128>>>(norm_w);
    // 9) o_proj: out = yn @ W2^T  (HMMA bf16x3)
    hgemm3<<<dim3(EMBED / HBN, M / HBM), 256, SMEM_GEMM>>>(
        M, EMBED, DIN, ynh, ynl, w2h, w2l, out);
}

// round 9
// speedup vs baseline: 1.1103x; 1.1103x over previous
#include <cuda_runtime.h>
#include <cuda_bf16.h>
#include <cstdint>

#define BB 2
#define LL 4096
#define EMBED 2048
#define DIN 4096
#define NH 32
#define HD 128
#define DS 64
#define CONVDIM 4224   // DIN + 2*DS
#define DPROJ 8352     // 2*DIN + 2*DS + NH
#define CHUNK 256
#define NCH 16         // LL / CHUNK
#define NBC (BB*NCH)   // 32

// ------------------- scratch (device globals; no cudaMalloc allowed) ---------
__device__ float g_zx[(size_t)BB*LL*DPROJ];        // in_proj output
__device__ float g_xbc[(size_t)BB*LL*CONVDIM];     // conv+silu output
__device__ float g_dt[BB*LL*NH];                   // softplus(dt)
__device__ float g_a[NBC*CHUNK*NH];                // cumsum(dA) per chunk
__device__ float g_alast[NBC*NH];
__device__ float g_scores[(size_t)NBC*CHUNK*CHUNK];
__device__ float g_states[(size_t)NBC*NH*HD*DS];   // [b,c,h,p,n]
__device__ float g_prev[(size_t)NBC*NH*HD*DS];     // state entering chunk c

// bf16 hi/lo split buffers
__device__ __nv_bfloat16 g_uh[(size_t)BB*LL*EMBED];
__device__ __nv_bfloat16 g_ul[(size_t)BB*LL*EMBED];
__device__ __nv_bfloat16 g_w1h[(size_t)DPROJ*EMBED];
__device__ __nv_bfloat16 g_w1l[(size_t)DPROJ*EMBED];
__device__ __nv_bfloat16 g_w2h[(size_t)EMBED*DIN];
__device__ __nv_bfloat16 g_w2l[(size_t)EMBED*DIN];
__device__ __nv_bfloat16 g_ynh[(size_t)BB*LL*DIN];
__device__ __nv_bfloat16 g_ynl[(size_t)BB*LL*DIN];

// ------------------- PTX helpers (sm_80-era: valid on base sm_103 target) ----
__device__ __forceinline__ uint32_t s2u(const void* p) {
    uint32_t a;
    asm("{ .reg .u64 t; cvta.to.shared.u64 t, %1; cvt.u32.u64 %0, t; }" : "=r"(a) : "l"(p));
    return a;
}
__device__ __forceinline__ void cpasync16(uint32_t s, const void* g, int srcsize) {
    asm volatile("cp.async.ca.shared.global [%0], [%1], 16, %2;"
                 :: "r"(s), "l"(g), "r"(srcsize));
}
__device__ __forceinline__ void cpcommit() {
    asm volatile("cp.async.commit_group;" ::: "memory");
}
template <int N>
__device__ __forceinline__ void cpwait() {
    asm volatile("cp.async.wait_group %0;" :: "n"(N) : "memory");
}
__device__ __forceinline__ void ldsm4(uint32_t* r, uint32_t addr) {
    asm volatile("ldmatrix.sync.aligned.m8n8.x4.shared.b16 {%0,%1,%2,%3}, [%4];"
                 : "=r"(r[0]), "=r"(r[1]), "=r"(r[2]), "=r"(r[3]) : "r"(addr));
}
__device__ __forceinline__ void mma16816(float* c, const uint32_t* a, const uint32_t* b) {
    asm volatile(
        "mma.sync.aligned.m16n8k16.row.col.f32.bf16.bf16.f32 "
        "{%0,%1,%2,%3},{%4,%5,%6,%7},{%8,%9},{%0,%1,%2,%3};"
        : "+f"(c[0]), "+f"(c[1]), "+f"(c[2]), "+f"(c[3])
        : "r"(a[0]), "r"(a[1]), "r"(a[2]), "r"(a[3]), "r"(b[0]), "r"(b[1]));
}

// ------------------- fp32 -> bf16 hi/lo split --------------------------------
__global__ void split_k(const float* __restrict__ s, __nv_bfloat16* __restrict__ hi,
                        __nv_bfloat16* __restrict__ lo, int n4)
{
    int i = blockIdx.x * 256 + threadIdx.x;
    if (i >= n4) return;
    float4 v = ((const float4*)s)[i];
    __nv_bfloat16 h0 = __float2bfloat16(v.x), h1 = __float2bfloat16(v.y);
    __nv_bfloat16 h2 = __float2bfloat16(v.z), h3 = __float2bfloat16(v.w);
    __nv_bfloat162* H = (__nv_bfloat162*)hi;
    __nv_bfloat162* L = (__nv_bfloat162*)lo;
    H[i*2+0] = __nv_bfloat162(h0, h1);
    H[i*2+1] = __nv_bfloat162(h2, h3);
    L[i*2+0] = __nv_bfloat162(__float2bfloat16(v.x - __bfloat162float(h0)),
                              __float2bfloat16(v.y - __bfloat162float(h1)));
    L[i*2+1] = __nv_bfloat162(__float2bfloat16(v.z - __bfloat162float(h2)),
                              __float2bfloat16(v.w - __bfloat162float(h3)));
}

// ------------------- HMMA bf16x3 GEMM: C[M,N] = A[M,K] @ B[N,K]^T ------------
// CTA tile 128x128, BK=64, 512 threads = 4x4 warps, warp tile 32x32.
// Double-buffered cp.async stages. fp32 accumulate in registers.
// (EXACT round-3/7 configuration — proven fastest; FROZEN.)
#define HBM 128
#define HBN 128
#define HBK 64
#define HLD 72                       // padded leading dim (bf16 elems)
#define HMATB (128*HLD*2)            // bytes per matrix per stage (18432)
#define HSTAGEB (4*HMATB)            // bytes per stage (73728)

__global__ __launch_bounds__(512) void hgemm3(
    int M, int N, int K,
    const __nv_bfloat16* __restrict__ Ah, const __nv_bfloat16* __restrict__ Al,
    const __nv_bfloat16* __restrict__ Bh, const __nv_bfloat16* __restrict__ Bl,
    float* __restrict__ C)
{
    extern __shared__ char smem[];
    const int tid = threadIdx.x;
    const int lane = tid & 31, wid = tid >> 5;
    const int wm = wid & 3, wn = wid >> 2;   // 4 x 4 warp grid
    const int bm = blockIdx.y * HBM, bn = blockIdx.x * HBN;
    const uint32_t sbase = s2u(smem);

    // ldmatrix lane mapping
    const int arow = lane & 15, akoff = (lane >> 4) << 3;
    const int bnl = (lane & 7) + ((lane >> 4) << 3);
    const int bkl = ((lane >> 3) & 1) << 3;

    float acc[2][4][4];
    #pragma unroll
    for (int mt = 0; mt < 2; mt++)
        #pragma unroll
        for (int nt = 0; nt < 4; nt++)
            #pragma unroll
            for (int i = 0; i < 4; i++) acc[mt][nt][i] = 0.f;

    const int nk = K / HBK;

    // ---- stage loader ----
    auto load_stage = [&](int st, int k0) {
        uint32_t sb = sbase + st * HSTAGEB;
        #pragma unroll
        for (int i = 0; i < 2; i++) {
            int chunk = tid + i * 512;
            int row = chunk >> 3, c = chunk & 7;
            uint32_t so = (uint32_t)(row * HLD + c * 8) * 2;
            size_t ga = (size_t)(bm + row) * K + k0 + c * 8;
            cpasync16(sb + so,             Ah + ga, 16);
            cpasync16(sb + HMATB + so,     Al + ga, 16);
            int brow = bn + row;
            int sz = (brow < N) ? 16 : 0;
            int bcl = (brow < N) ? brow : 0;
            size_t gb = (size_t)bcl * K + k0 + c * 8;
            cpasync16(sb + 2*HMATB + so,   Bh + gb, sz);
            cpasync16(sb + 3*HMATB + so,   Bl + gb, sz);
        }
        cpcommit();
    };

    load_stage(0, 0);

    for (int kt = 0; kt < nk; ++kt) {
        if (kt + 1 < nk) {
            load_stage((kt + 1) & 1, (kt + 1) * HBK);
            cpwait<1>();
        } else {
            cpwait<0>();
        }
        __syncthreads();

        uint32_t sb = sbase + (kt & 1) * HSTAGEB;
        uint32_t sAh = sb, sAl = sb + HMATB, sBh = sb + 2*HMATB, sBl = sb + 3*HMATB;

        #pragma unroll
        for (int kh = 0; kh < 4; kh++) {
            int k = kh * 16;
            uint32_t bfh[2][4], bfl[2][4];
            #pragma unroll
            for (int ntp = 0; ntp < 2; ntp++) {
                uint32_t off = (uint32_t)((wn * 32 + ntp * 16 + bnl) * HLD + k + bkl) * 2;
                ldsm4(bfh[ntp], sBh + off);
                ldsm4(bfl[ntp], sBl + off);
            }
            #pragma unroll
            for (int mt = 0; mt < 2; mt++) {
                uint32_t aoff = (uint32_t)((wm * 32 + mt * 16 + arow) * HLD + k + akoff) * 2;
                uint32_t af[4];
                ldsm4(af, sAh + aoff);
                #pragma unroll
                for (int nt = 0; nt < 4; nt++)
                    mma16816(acc[mt][nt], af, &bfh[nt >> 1][(nt & 1) * 2]);
                #pragma unroll
                for (int nt = 0; nt < 4; nt++)
                    mma16816(acc[mt][nt], af, &bfl[nt >> 1][(nt & 1) * 2]);
                ldsm4(af, sAl + aoff);
                #pragma unroll
                for (int nt = 0; nt < 4; nt++)
                    mma16816(acc[mt][nt], af, &bfh[nt >> 1][(nt & 1) * 2]);
            }
        }
        __syncthreads();
    }

    // ---- epilogue ----
    #pragma unroll
    for (int mt = 0; mt < 2; mt++) {
        int row0 = bm + wm * 32 + mt * 16 + (lane >> 2);
        #pragma unroll
        for (int nt = 0; nt < 4; nt++) {
            int col = bn + wn * 32 + nt * 8 + (lane & 3) * 2;
            if (col < N) {
                *(float2*)&C[(size_t)row0 * N + col] =
                    make_float2(acc[mt][nt][0], acc[mt][nt][1]);
                *(float2*)&C[(size_t)(row0 + 8) * N + col] =
                    make_float2(acc[mt][nt][2], acc[mt][nt][3]);
            }
        }
    }
}

// ------------------- depthwise causal conv (k=4) + silu ----------------------
__global__ void conv_silu_k(const float* __restrict__ cw, const float* __restrict__ cb)
{
    int idx = blockIdx.x * 256 + threadIdx.x;
    const int total = BB * LL * CONVDIM;
    if (idx >= total) return;
    int ch = idx % CONVDIM;
    int bl = idx / CONVDIM;
    int l = bl % LL, b = bl / LL;
    float acc = cb[ch];
    #pragma unroll
    for (int k = 0; k < 4; k++) {
        int ll = l - 3 + k;
        if (ll >= 0)
            acc += g_zx[(size_t)(b * LL + ll) * DPROJ + DIN + ch] * cw[ch * 4 + k];
    }
    g_xbc[idx] = acc / (1.f + __expf(-acc));
}

// ------------------- per-chunk cumsum of dA (fused softplus + warp scan) -----
__global__ void cumsum_k(const float* __restrict__ A_log, const float* __restrict__ dt_bias)
{
    int bch = blockIdx.x;            // bc*NH + h
    int h = bch & 31, bc = bch >> 5;
    int b = bc / NCH, c = bc % NCH;
    int t = threadIdx.x;             // 32
    float Ah = -__expf(A_log[h]);
    float bias = dt_bias[h];
    size_t row0 = (size_t)(b * LL + c * CHUNK) + t * 8;
    float v[8];
    #pragma unroll
    for (int j = 0; j < 8; j++) {
        float x = g_zx[(row0 + j) * DPROJ + DIN + CONVDIM + h] + bias;
        float sp = (x > 20.f) ? x : log1pf(__expf(x));
        g_dt[(row0 + j) * NH + h] = sp;
        v[j] = sp * Ah;
    }
    float loc = 0.f;
    #pragma unroll
    for (int j = 0; j < 8; j++) { loc += v[j]; v[j] = loc; }
    float pre = loc;
    #pragma unroll
    for (int o = 1; o < 32; o <<= 1) {
        float nv = __shfl_up_sync(0xffffffffu, pre, o);
        if (t >= o) pre += nv;
    }
    pre -= loc;   // exclusive prefix
    #pragma unroll
    for (int j = 0; j < 8; j++) g_a[(bc * CHUNK + t * 8 + j) * NH + h] = pre + v[j];
    if (t == 31) g_alast[bc * NH + h] = pre + loc;
}

// ------------------- scores = C @ B^T per chunk (lower tiles only) -----------
__global__ __launch_bounds__(256) void scores_k()
{
    int jt = blockIdx.x, it = blockIdx.y, bc = blockIdx.z;
    if (jt > it) return;
    int b = bc / NCH, c = bc % NCH;
    __shared__ float CtT[64][65];
    __shared__ float BtT[64][65];
    int tid = threadIdx.x;
    for (int t = tid; t < 64 * 64; t += 256) {
        int r = t >> 6, n = t & 63;
        int rowC = b * LL + c * CHUNK + it * 64 + r;
        int rowB = b * LL + c * CHUNK + jt * 64 + r;
        CtT[n][r] = g_xbc[(size_t)rowC * CONVDIM + DIN + DS + n];
        BtT[n][r] = g_xbc[(size_t)rowB * CONVDIM + DIN + n];
    }
    __syncthreads();
    int ty = tid >> 4, tx = tid & 15;
    float acc[4][4];
    #pragma unroll
    for (int i = 0; i < 4; i++)
        #pragma unroll
        for (int j = 0; j < 4; j++) acc[i][j] = 0.f;
    for (int n = 0; n < 64; n++) {
        float a[4], w[4];
        #pragma unroll
        for (int i = 0; i < 4; i++) a[i] = CtT[n][ty * 4 + i];
        #pragma unroll
        for (int j = 0; j < 4; j++) w[j] = BtT[n][tx * 4 + j];
        #pragma unroll
        for (int i = 0; i < 4; i++)
            #pragma unroll
            for (int j = 0; j < 4; j++) acc[i][j] += a[i] * w[j];
    }
    #pragma unroll
    for (int i = 0; i < 4; i++)
        #pragma unroll
        for (int j = 0; j < 4; j++)
            g_scores[((size_t)bc << 16) + (it * 64 + ty * 4 + i) * 256 + jt * 64 + tx * 4 + j] = acc[i][j];
}

// ------------------- per-chunk states[h,p,n] ---------------------------------
__global__ __launch_bounds__(256) void states_k()
{
    int bch = blockIdx.x;              // bc*NH + h
    int h = bch % NH, bc = bch / NH;
    int b = bc / NCH, c = bc % NCH;
    __shared__ float Xq[32][128];
    __shared__ float Bco[32][64];
    __shared__ float coef[32];
    int tid = threadIdx.x;
    float alast = g_alast[bc * NH + h];
    int tp = tid >> 4, tn = tid & 15;
    float acc[8][4];
    #pragma unroll
    for (int i = 0; i < 8; i++)
        #pragma unroll
        for (int j = 0; j < 4; j++) acc[i][j] = 0.f;

    for (int q0 = 0; q0 < CHUNK; q0 += 32) {
        __syncthreads();
        if (tid < 32) {
            int gq = q0 + tid;
            float aq = g_a[(bc * CHUNK + gq) * NH + h];
            float dtq = g_dt[(size_t)(b * LL + c * CHUNK + gq) * NH + h];
            coef[tid] = dtq * __expf(alast - aq);
        }
        #pragma unroll
        for (int t = 0; t < 16; t++) {
            int idx = tid + t * 256;
            int q = idx >> 7, p = idx & 127;
            Xq[q][p] = g_xbc[(size_t)(b * LL + c * CHUNK + q0 + q) * CONVDIM + h * HD + p];
        }
        __syncthreads();
        #pragma unroll
        for (int t = 0; t < 8; t++) {
            int idx = tid + t * 256;
            int q = idx >> 6, n = idx & 63;
            Bco[q][n] = g_xbc[(size_t)(b * LL + c * CHUNK + q0 + q) * CONVDIM + DIN + n] * coef[q];
        }
        __syncthreads();
        for (int q = 0; q < 32; q++) {
            float xv[8], bv[4];
            #pragma unroll
            for (int i = 0; i < 8; i++) xv[i] = Xq[q][tp * 8 + i];
            #pragma unroll
            for (int j = 0; j < 4; j++) bv[j] = Bco[q][tn * 4 + j];
            #pragma unroll
            for (int i = 0; i < 8; i++)
                #pragma unroll
                for (int j = 0; j < 4; j++) acc[i][j] += xv[i] * bv[j];
        }
    }
    size_t base = (size_t)bch * HD * DS;
    #pragma unroll
    for (int i = 0; i < 8; i++)
        #pragma unroll
        for (int j = 0; j < 4; j++)
            g_states[base + (tp * 8 + i) * DS + tn * 4 + j] = acc[i][j];
}

// ------------------- sequential inter-chunk scan (split over 16 slices) ------
__global__ void scan_k()
{
    int bh = blockIdx.x;            // b*NH + h
    int b = bh >> 5, h = bh & 31;
    int e = blockIdx.y * 512 + threadIdx.x;   // element in HD*DS plane
    float s = 0.f;
    for (int c = 0; c < NCH; c++) {
        int bc = b * NCH + c;
        float dec = __expf(g_alast[bc * NH + h]);
        size_t base = (size_t)(bc * NH + h) * HD * DS;
        g_prev[base + e] = s;
        s = s * dec + g_states[base + e];
    }
}

// ------ y = intra + inter + D*x, FUSED gate(sigmoid z) + per-head RMS norm ---
__global__ __launch_bounds__(256) void ych_k(const float* __restrict__ D_skip,
                                             const float* __restrict__ norm_w)
{
    int it = blockIdx.x;   // 0..3 (64-row tile)
    int h  = blockIdx.y;   // 0..31
    int bc = blockIdx.z;   // 0..31
    int b = bc / NCH, c = bc % NCH;
    __shared__ float sh[6400];
    float* ai = sh;          // 64
    float* Wt = sh + 64;     // 64*33 (phase1) / 32*64 CtT (phase2)
    float* Xt = sh + 2176;   // 32*128 (phase1) / 32*132 prevT (phase2)
    int tid = threadIdx.x;
    int ty = tid >> 5, tx = tid & 31;
    int row0 = b * LL + c * CHUNK;
    if (tid < 64) ai[tid] = g_a[(bc * CHUNK + it * 64 + tid) * NH + h];
    float acc[8][4];
    #pragma unroll
    for (int i = 0; i < 8; i++)
        #pragma unroll
        for (int j = 0; j < 4; j++) acc[i][j] = 0.f;
    __syncthreads();

    int jtmax = 2 * it + 1;
    for (int jt = 0; jt <= jtmax; jt++) {
        int j0 = jt * 32;
        #pragma unroll
        for (int t = 0; t < 8; t++) {
            int idx = tid + t * 256;
            int i = idx >> 5, j = idx & 31;
            int gi = it * 64 + i, gj = j0 + j;
            float w = 0.f;
            if (gj <= gi) {
                float aj = g_a[(bc * CHUNK + gj) * NH + h];
                float dtj = g_dt[(size_t)(row0 + gj) * NH + h];
                w = g_scores[((size_t)bc << 16) + gi * 256 + gj] * __expf(ai[i] - aj) * dtj;
            }
            Wt[i * 33 + j] = w;
        }
        #pragma unroll
        for (int t = 0; t < 16; t++) {
            int idx = tid + t * 256;
            int j = idx >> 7, p = idx & 127;
            Xt[j * 128 + p] = g_xbc[(size_t)(row0 + j0 + j) * CONVDIM + h * HD + p];
        }
        __syncthreads();
        for (int j = 0; j < 32; j++) {
            float4 xv = *(float4*)&Xt[j * 128 + tx * 4];
            #pragma unroll
            for (int i = 0; i < 8; i++) {
                float w = Wt[(ty * 8 + i) * 33 + j];
                acc[i][0] += w * xv.x; acc[i][1] += w * xv.y;
                acc[i][2] += w * xv.z; acc[i][3] += w * xv.w;
            }
        }
        __syncthreads();
    }

    float acc2[8][4];
    #pragma unroll
    for (int i = 0; i < 8; i++)
        #pragma unroll
        for (int j = 0; j < 4; j++) acc2[i][j] = 0.f;
    size_t pbase = (size_t)(bc * NH + h) * HD * DS;
    for (int nt = 0; nt < 2; nt++) {
        int n0 = nt * 32;
        #pragma unroll
        for (int t = 0; t < 8; t++) {
            int idx = tid + t * 256;
            int i = idx >> 5, n = idx & 31;
            Wt[n * 64 + i] = g_xbc[(size_t)(row0 + it * 64 + i) * CONVDIM + DIN + DS + n0 + n];
        }
        #pragma unroll
        for (int t = 0; t < 16; t++) {
            int idx = tid + t * 256;
            int p = idx >> 5, n = idx & 31;
            Xt[n * 132 + p] = g_prev[pbase + (size_t)p * DS + n0 + n];
        }
        __syncthreads();
        for (int n = 0; n < 32; n++) {
            float4 pv = *(float4*)&Xt[n * 132 + tx * 4];
            #pragma unroll
            for (int i = 0; i < 8; i++) {
                float cv = Wt[n * 64 + ty * 8 + i];
                acc2[i][0] += cv * pv.x; acc2[i][1] += cv * pv.y;
                acc2[i][2] += cv * pv.z; acc2[i][3] += cv * pv.w;
            }
        }
        __syncthreads();
    }

    // ---- combine + D skip + gate + per-head RMS norm + bf16 hi/lo store ----
    float Dh = D_skip[h];
    float4 nw = *(const float4*)&norm_w[h * HD + tx * 4];
    #pragma unroll
    for (int i = 0; i < 8; i++) {
        int li = ty * 8 + i;
        int gi = it * 64 + li;
        float ea = __expf(ai[li]);
        float4 xv = *(const float4*)&g_xbc[(size_t)(row0 + gi) * CONVDIM + h * HD + tx * 4];
        float4 o;
        o.x = acc[i][0] + ea * acc2[i][0] + Dh * xv.x;
        o.y = acc[i][1] + ea * acc2[i][1] + Dh * xv.y;
        o.z = acc[i][2] + ea * acc2[i][2] + Dh * xv.z;
        o.w = acc[i][3] + ea * acc2[i][3] + Dh * xv.w;
        // gate by sigmoid(z)
        float4 zv = *(const float4*)&g_zx[(size_t)(row0 + gi) * DPROJ + h * HD + tx * 4];
        float4 v;
        v.x = o.x / (1.f + __expf(-zv.x));
        v.y = o.y / (1.f + __expf(-zv.y));
        v.z = o.z / (1.f + __expf(-zv.z));
        v.w = o.w / (1.f + __expf(-zv.w));
        // warp-level RMS over the 128 p-values of this row (4 per lane x 32 lanes)
        float ss = v.x * v.x + v.y * v.y + v.z * v.z + v.w * v.w;
        #pragma unroll
        for (int off = 16; off; off >>= 1) ss += __shfl_xor_sync(0xffffffffu, ss, off);
        float inv = rsqrtf(ss * (1.f / HD) + 1e-6f);
        float r0 = v.x * inv * nw.x;
        float r1 = v.y * inv * nw.y;
        float r2 = v.z * inv * nw.z;
        float r3 = v.w * inv * nw.w;
        size_t oi = (size_t)(row0 + gi) * DIN + h * HD + tx * 4;
        __nv_bfloat16 h0 = __float2bfloat16(r0), h1 = __float2bfloat16(r1);
        __nv_bfloat16 h2 = __float2bfloat16(r2), h3 = __float2bfloat16(r3);
        *(__nv_bfloat162*)&g_ynh[oi]     = __nv_bfloat162(h0, h1);
        *(__nv_bfloat162*)&g_ynh[oi + 2] = __nv_bfloat162(h2, h3);
        *(__nv_bfloat162*)&g_ynl[oi]     = __nv_bfloat162(
            __float2bfloat16(r0 - __bfloat162float(h0)),
            __float2bfloat16(r1 - __bfloat162float(h1)));
        *(__nv_bfloat162*)&g_ynl[oi + 2] = __nv_bfloat162(
            __float2bfloat16(r2 - __bfloat162float(h2)),
            __float2bfloat16(r3 - __bfloat162float(h3)));
    }
}

// ------------------- launch ---------------------------------------------------
extern "C" void kernel_launch(void* const* d_in, const int* in_sizes, int n_in,
                              void* d_out, int out_size)
{
    const float* u         = (const float*)d_in[0];
    const float* in_proj_w = (const float*)d_in[1];
    const float* conv_w    = (const float*)d_in[2];
    const float* conv_b    = (const float*)d_in[3];
    const float* A_log     = (const float*)d_in[4];
    const float* dt_bias   = (const float*)d_in[5];
    const float* D_skip    = (const float*)d_in[6];
    const float* norm_w    = (const float*)d_in[7];
    const float* o_proj_w  = (const float*)d_in[8];
    float* out = (float*)d_out;

    float* zx = nullptr;
    cudaGetSymbolAddress((void**)&zx, g_zx);
    __nv_bfloat16 *uh, *ul, *w1h, *w1l, *w2h, *w2l, *ynh, *ynl;
    cudaGetSymbolAddress((void**)&uh,  g_uh);
    cudaGetSymbolAddress((void**)&ul,  g_ul);
    cudaGetSymbolAddress((void**)&w1h, g_w1h);
    cudaGetSymbolAddress((void**)&w1l, g_w1l);
    cudaGetSymbolAddress((void**)&w2h, g_w2h);
    cudaGetSymbolAddress((void**)&w2l, g_w2l);
    cudaGetSymbolAddress((void**)&ynh, g_ynh);
    cudaGetSymbolAddress((void**)&ynl, g_ynl);

    const int SMEM_GEMM = 2 * HSTAGEB;   // 147456
    cudaFuncSetAttribute(hgemm3, cudaFuncAttributeMaxDynamicSharedMemorySize, SMEM_GEMM);

    const int M = BB * LL;   // 8192

    // 0) hi/lo splits of GEMM inputs
    {
        int n4;
        n4 = (M * EMBED) / 4;
        split_k<<<(n4 + 255) / 256, 256>>>(u, uh, ul, n4);
        n4 = (DPROJ * EMBED) / 4;
        split_k<<<(n4 + 255) / 256, 256>>>(in_proj_w, w1h, w1l, n4);
        n4 = (EMBED * DIN) / 4;
        split_k<<<(n4 + 255) / 256, 256>>>(o_proj_w, w2h, w2l, n4);
    }
    // 1) in_proj: zx = u @ W1^T  (HMMA bf16x3)
    hgemm3<<<dim3((DPROJ + HBN - 1) / HBN, M / HBM), 512, SMEM_GEMM>>>(
        M, DPROJ, EMBED, uh, ul, w1h, w1l, zx);
    // 2) causal depthwise conv + silu
    conv_silu_k<<<(BB * LL * CONVDIM + 255) / 256, 256>>>(conv_w, conv_b);
    // 3) fused dt softplus + per-chunk cumsum (parallel scan)
    cumsum_k<<<NBC * NH, 32>>>(A_log, dt_bias);
    // 4) chunk attention scores (lower tiles)
    scores_k<<<dim3(4, 4, NBC), 256>>>();
    // 5) per-chunk end states
    states_k<<<NBC * NH, 256>>>();
    // 6) inter-chunk scan (16 slices per (b,h))
    scan_k<<<dim3(BB * NH, 16), 512>>>();
    // 7) y = intra + inter + D*x, fused gate + RMS norm (writes bf16 hi/lo)
    ych_k<<<dim3(4, NH, NBC), 256>>>(D_skip, norm_w);
    // 8) o_proj: out = yn @ W2^T  (HMMA bf16x3)
    hgemm3<<<dim3(EMBED / HBN, M / HBM), 512, SMEM_GEMM>>>(
        M, EMBED, DIN, ynh, ynl, w2h, w2l, out);
}

// round 10
// speedup vs baseline: 1.1442x; 1.0305x over previous
#include <cuda_runtime.h>
#include <cuda_bf16.h>
#include <cstdint>

#define BB 2
#define LL 4096
#define EMBED 2048
#define DIN 4096
#define NH 32
#define HD 128
#define DS 64
#define CONVDIM 4224   // DIN + 2*DS
#define DPROJ 8352     // 2*DIN + 2*DS + NH
#define CHUNK 256
#define NCH 16         // LL / CHUNK
#define NBC (BB*NCH)   // 32

// ------------------- scratch (device globals; no cudaMalloc allowed) ---------
__device__ float g_zx[(size_t)BB*LL*DPROJ];        // in_proj output
__device__ float g_xbc[(size_t)BB*LL*CONVDIM];     // conv+silu output
__device__ float g_dt[BB*LL*NH];                   // softplus(dt)
__device__ float g_a[NBC*CHUNK*NH];                // cumsum(dA) per chunk
__device__ float g_alast[NBC*NH];
__device__ float g_scores[(size_t)NBC*CHUNK*CHUNK];
__device__ float g_states[(size_t)NBC*NH*HD*DS];   // [b,c,h,p,n]
__device__ float g_prev[(size_t)NBC*NH*HD*DS];     // state entering chunk c

// bf16 hi/lo split buffers
__device__ __nv_bfloat16 g_uh[(size_t)BB*LL*EMBED];
__device__ __nv_bfloat16 g_ul[(size_t)BB*LL*EMBED];
__device__ __nv_bfloat16 g_w1h[(size_t)DPROJ*EMBED];
__device__ __nv_bfloat16 g_w1l[(size_t)DPROJ*EMBED];
__device__ __nv_bfloat16 g_w2h[(size_t)EMBED*DIN];
__device__ __nv_bfloat16 g_w2l[(size_t)EMBED*DIN];
__device__ __nv_bfloat16 g_ynh[(size_t)BB*LL*DIN];
__device__ __nv_bfloat16 g_ynl[(size_t)BB*LL*DIN];

// ------------------- PTX helpers (sm_80-era: valid on base sm_103 target) ----
__device__ __forceinline__ uint32_t s2u(const void* p) {
    uint32_t a;
    asm("{ .reg .u64 t; cvta.to.shared.u64 t, %1; cvt.u32.u64 %0, t; }" : "=r"(a) : "l"(p));
    return a;
}
__device__ __forceinline__ void cpasync16(uint32_t s, const void* g, int srcsize) {
    asm volatile("cp.async.ca.shared.global [%0], [%1], 16, %2;"
                 :: "r"(s), "l"(g), "r"(srcsize));
}
__device__ __forceinline__ void cpcommit() {
    asm volatile("cp.async.commit_group;" ::: "memory");
}
template <int N>
__device__ __forceinline__ void cpwait() {
    asm volatile("cp.async.wait_group %0;" :: "n"(N) : "memory");
}
__device__ __forceinline__ void ldsm4(uint32_t* r, uint32_t addr) {
    asm volatile("ldmatrix.sync.aligned.m8n8.x4.shared.b16 {%0,%1,%2,%3}, [%4];"
                 : "=r"(r[0]), "=r"(r[1]), "=r"(r[2]), "=r"(r[3]) : "r"(addr));
}
__device__ __forceinline__ void mma16816(float* c, const uint32_t* a, const uint32_t* b) {
    asm volatile(
        "mma.sync.aligned.m16n8k16.row.col.f32.bf16.bf16.f32 "
        "{%0,%1,%2,%3},{%4,%5,%6,%7},{%8,%9},{%0,%1,%2,%3};"
        : "+f"(c[0]), "+f"(c[1]), "+f"(c[2]), "+f"(c[3])
        : "r"(a[0]), "r"(a[1]), "r"(a[2]), "r"(a[3]), "r"(b[0]), "r"(b[1]));
}

// ------------------- fp32 -> bf16 hi/lo split --------------------------------
__global__ void split_k(const float* __restrict__ s, __nv_bfloat16* __restrict__ hi,
                        __nv_bfloat16* __restrict__ lo, int n4)
{
    int i = blockIdx.x * 256 + threadIdx.x;
    if (i >= n4) return;
    float4 v = ((const float4*)s)[i];
    __nv_bfloat16 h0 = __float2bfloat16(v.x), h1 = __float2bfloat16(v.y);
    __nv_bfloat16 h2 = __float2bfloat16(v.z), h3 = __float2bfloat16(v.w);
    __nv_bfloat162* H = (__nv_bfloat162*)hi;
    __nv_bfloat162* L = (__nv_bfloat162*)lo;
    H[i*2+0] = __nv_bfloat162(h0, h1);
    H[i*2+1] = __nv_bfloat162(h2, h3);
    L[i*2+0] = __nv_bfloat162(__float2bfloat16(v.x - __bfloat162float(h0)),
                              __float2bfloat16(v.y - __bfloat162float(h1)));
    L[i*2+1] = __nv_bfloat162(__float2bfloat16(v.z - __bfloat162float(h2)),
                              __float2bfloat16(v.w - __bfloat162float(h3)));
}

// ------------------- HMMA bf16x3 GEMM: C[M,N] = A[M,K] @ B[N,K]^T ------------
// CTA tile 128x128, BK=64, 512 threads = 4x4 warps, warp tile 32x32.
// Double-buffered cp.async stages. fp32 accumulate in registers.
// (EXACT round-3/7 configuration — proven fastest; FROZEN.)
#define HBM 128
#define HBN 128
#define HBK 64
#define HLD 72                       // padded leading dim (bf16 elems)
#define HMATB (128*HLD*2)            // bytes per matrix per stage (18432)
#define HSTAGEB (4*HMATB)            // bytes per stage (73728)

__global__ __launch_bounds__(512) void hgemm3(
    int M, int N, int K,
    const __nv_bfloat16* __restrict__ Ah, const __nv_bfloat16* __restrict__ Al,
    const __nv_bfloat16* __restrict__ Bh, const __nv_bfloat16* __restrict__ Bl,
    float* __restrict__ C)
{
    extern __shared__ char smem[];
    const int tid = threadIdx.x;
    const int lane = tid & 31, wid = tid >> 5;
    const int wm = wid & 3, wn = wid >> 2;   // 4 x 4 warp grid
    const int bm = blockIdx.y * HBM, bn = blockIdx.x * HBN;
    const uint32_t sbase = s2u(smem);

    // ldmatrix lane mapping
    const int arow = lane & 15, akoff = (lane >> 4) << 3;
    const int bnl = (lane & 7) + ((lane >> 4) << 3);
    const int bkl = ((lane >> 3) & 1) << 3;

    float acc[2][4][4];
    #pragma unroll
    for (int mt = 0; mt < 2; mt++)
        #pragma unroll
        for (int nt = 0; nt < 4; nt++)
            #pragma unroll
            for (int i = 0; i < 4; i++) acc[mt][nt][i] = 0.f;

    const int nk = K / HBK;

    // ---- stage loader ----
    auto load_stage = [&](int st, int k0) {
        uint32_t sb = sbase + st * HSTAGEB;
        #pragma unroll
        for (int i = 0; i < 2; i++) {
            int chunk = tid + i * 512;
            int row = chunk >> 3, c = chunk & 7;
            uint32_t so = (uint32_t)(row * HLD + c * 8) * 2;
            size_t ga = (size_t)(bm + row) * K + k0 + c * 8;
            cpasync16(sb + so,             Ah + ga, 16);
            cpasync16(sb + HMATB + so,     Al + ga, 16);
            int brow = bn + row;
            int sz = (brow < N) ? 16 : 0;
            int bcl = (brow < N) ? brow : 0;
            size_t gb = (size_t)bcl * K + k0 + c * 8;
            cpasync16(sb + 2*HMATB + so,   Bh + gb, sz);
            cpasync16(sb + 3*HMATB + so,   Bl + gb, sz);
        }
        cpcommit();
    };

    load_stage(0, 0);

    for (int kt = 0; kt < nk; ++kt) {
        if (kt + 1 < nk) {
            load_stage((kt + 1) & 1, (kt + 1) * HBK);
            cpwait<1>();
        } else {
            cpwait<0>();
        }
        __syncthreads();

        uint32_t sb = sbase + (kt & 1) * HSTAGEB;
        uint32_t sAh = sb, sAl = sb + HMATB, sBh = sb + 2*HMATB, sBl = sb + 3*HMATB;

        #pragma unroll
        for (int kh = 0; kh < 4; kh++) {
            int k = kh * 16;
            uint32_t bfh[2][4], bfl[2][4];
            #pragma unroll
            for (int ntp = 0; ntp < 2; ntp++) {
                uint32_t off = (uint32_t)((wn * 32 + ntp * 16 + bnl) * HLD + k + bkl) * 2;
                ldsm4(bfh[ntp], sBh + off);
                ldsm4(bfl[ntp], sBl + off);
            }
            #pragma unroll
            for (int mt = 0; mt < 2; mt++) {
                uint32_t aoff = (uint32_t)((wm * 32 + mt * 16 + arow) * HLD + k + akoff) * 2;
                uint32_t af[4];
                ldsm4(af, sAh + aoff);
                #pragma unroll
                for (int nt = 0; nt < 4; nt++)
                    mma16816(acc[mt][nt], af, &bfh[nt >> 1][(nt & 1) * 2]);
                #pragma unroll
                for (int nt = 0; nt < 4; nt++)
                    mma16816(acc[mt][nt], af, &bfl[nt >> 1][(nt & 1) * 2]);
                ldsm4(af, sAl + aoff);
                #pragma unroll
                for (int nt = 0; nt < 4; nt++)
                    mma16816(acc[mt][nt], af, &bfh[nt >> 1][(nt & 1) * 2]);
            }
        }
        __syncthreads();
    }

    // ---- epilogue ----
    #pragma unroll
    for (int mt = 0; mt < 2; mt++) {
        int row0 = bm + wm * 32 + mt * 16 + (lane >> 2);
        #pragma unroll
        for (int nt = 0; nt < 4; nt++) {
            int col = bn + wn * 32 + nt * 8 + (lane & 3) * 2;
            if (col < N) {
                *(float2*)&C[(size_t)row0 * N + col] =
                    make_float2(acc[mt][nt][0], acc[mt][nt][1]);
                *(float2*)&C[(size_t)(row0 + 8) * N + col] =
                    make_float2(acc[mt][nt][2], acc[mt][nt][3]);
            }
        }
    }
}

// ------------------- depthwise causal conv (k=4) + silu ----------------------
__global__ void conv_silu_k(const float* __restrict__ cw, const float* __restrict__ cb)
{
    int idx = blockIdx.x * 256 + threadIdx.x;
    const int total = BB * LL * CONVDIM;
    if (idx >= total) return;
    int ch = idx % CONVDIM;
    int bl = idx / CONVDIM;
    int l = bl % LL, b = bl / LL;
    float acc = cb[ch];
    #pragma unroll
    for (int k = 0; k < 4; k++) {
        int ll = l - 3 + k;
        if (ll >= 0)
            acc += g_zx[(size_t)(b * LL + ll) * DPROJ + DIN + ch] * cw[ch * 4 + k];
    }
    g_xbc[idx] = acc / (1.f + __expf(-acc));
}

// ------------------- per-chunk cumsum of dA (fused softplus + warp scan) -----
__global__ void cumsum_k(const float* __restrict__ A_log, const float* __restrict__ dt_bias)
{
    int bch = blockIdx.x;            // bc*NH + h
    int h = bch & 31, bc = bch >> 5;
    int b = bc / NCH, c = bc % NCH;
    int t = threadIdx.x;             // 32
    float Ah = -__expf(A_log[h]);
    float bias = dt_bias[h];
    size_t row0 = (size_t)(b * LL + c * CHUNK) + t * 8;
    float v[8];
    #pragma unroll
    for (int j = 0; j < 8; j++) {
        float x = g_zx[(row0 + j) * DPROJ + DIN + CONVDIM + h] + bias;
        float sp = (x > 20.f) ? x : log1pf(__expf(x));
        g_dt[(row0 + j) * NH + h] = sp;
        v[j] = sp * Ah;
    }
    float loc = 0.f;
    #pragma unroll
    for (int j = 0; j < 8; j++) { loc += v[j]; v[j] = loc; }
    float pre = loc;
    #pragma unroll
    for (int o = 1; o < 32; o <<= 1) {
        float nv = __shfl_up_sync(0xffffffffu, pre, o);
        if (t >= o) pre += nv;
    }
    pre -= loc;   // exclusive prefix
    #pragma unroll
    for (int j = 0; j < 8; j++) g_a[(bc * CHUNK + t * 8 + j) * NH + h] = pre + v[j];
    if (t == 31) g_alast[bc * NH + h] = pre + loc;
}

// ------------------- scores = C @ B^T per chunk (lower tiles only) -----------
__global__ __launch_bounds__(256) void scores_k()
{
    int jt = blockIdx.x, it = blockIdx.y, bc = blockIdx.z;
    if (jt > it) return;
    int b = bc / NCH, c = bc % NCH;
    __shared__ float CtT[64][65];
    __shared__ float BtT[64][65];
    int tid = threadIdx.x;
    for (int t = tid; t < 64 * 64; t += 256) {
        int r = t >> 6, n = t & 63;
        int rowC = b * LL + c * CHUNK + it * 64 + r;
        int rowB = b * LL + c * CHUNK + jt * 64 + r;
        CtT[n][r] = g_xbc[(size_t)rowC * CONVDIM + DIN + DS + n];
        BtT[n][r] = g_xbc[(size_t)rowB * CONVDIM + DIN + n];
    }
    __syncthreads();
    int ty = tid >> 4, tx = tid & 15;
    float acc[4][4];
    #pragma unroll
    for (int i = 0; i < 4; i++)
        #pragma unroll
        for (int j = 0; j < 4; j++) acc[i][j] = 0.f;
    for (int n = 0; n < 64; n++) {
        float a[4], w[4];
        #pragma unroll
        for (int i = 0; i < 4; i++) a[i] = CtT[n][ty * 4 + i];
        #pragma unroll
        for (int j = 0; j < 4; j++) w[j] = BtT[n][tx * 4 + j];
        #pragma unroll
        for (int i = 0; i < 4; i++)
            #pragma unroll
            for (int j = 0; j < 4; j++) acc[i][j] += a[i] * w[j];
    }
    #pragma unroll
    for (int i = 0; i < 4; i++)
        #pragma unroll
        for (int j = 0; j < 4; j++)
            g_scores[((size_t)bc << 16) + (it * 64 + ty * 4 + i) * 256 + jt * 64 + tx * 4 + j] = acc[i][j];
}

// ------------------- per-chunk states[h,p,n] ---------------------------------
__global__ __launch_bounds__(256) void states_k()
{
    int bch = blockIdx.x;              // bc*NH + h
    int h = bch % NH, bc = bch / NH;
    int b = bc / NCH, c = bc % NCH;
    __shared__ float Xq[32][128];
    __shared__ float Bco[32][64];
    __shared__ float coef[32];
    int tid = threadIdx.x;
    float alast = g_alast[bc * NH + h];
    int tp = tid >> 4, tn = tid & 15;
    float acc[8][4];
    #pragma unroll
    for (int i = 0; i < 8; i++)
        #pragma unroll
        for (int j = 0; j < 4; j++) acc[i][j] = 0.f;

    for (int q0 = 0; q0 < CHUNK; q0 += 32) {
        __syncthreads();
        if (tid < 32) {
            int gq = q0 + tid;
            float aq = g_a[(bc * CHUNK + gq) * NH + h];
            float dtq = g_dt[(size_t)(b * LL + c * CHUNK + gq) * NH + h];
            coef[tid] = dtq * __expf(alast - aq);
        }
        #pragma unroll
        for (int t = 0; t < 16; t++) {
            int idx = tid + t * 256;
            int q = idx >> 7, p = idx & 127;
            Xq[q][p] = g_xbc[(size_t)(b * LL + c * CHUNK + q0 + q) * CONVDIM + h * HD + p];
        }
        __syncthreads();
        #pragma unroll
        for (int t = 0; t < 8; t++) {
            int idx = tid + t * 256;
            int q = idx >> 6, n = idx & 63;
            Bco[q][n] = g_xbc[(size_t)(b * LL + c * CHUNK + q0 + q) * CONVDIM + DIN + n] * coef[q];
        }
        __syncthreads();
        for (int q = 0; q < 32; q++) {
            float xv[8], bv[4];
            #pragma unroll
            for (int i = 0; i < 8; i++) xv[i] = Xq[q][tp * 8 + i];
            #pragma unroll
            for (int j = 0; j < 4; j++) bv[j] = Bco[q][tn * 4 + j];
            #pragma unroll
            for (int i = 0; i < 8; i++)
                #pragma unroll
                for (int j = 0; j < 4; j++) acc[i][j] += xv[i] * bv[j];
        }
    }
    size_t base = (size_t)bch * HD * DS;
    #pragma unroll
    for (int i = 0; i < 8; i++)
        #pragma unroll
        for (int j = 0; j < 4; j++)
            g_states[base + (tp * 8 + i) * DS + tn * 4 + j] = acc[i][j];
}

// ------------------- sequential inter-chunk scan (split over 16 slices) ------
__global__ void scan_k()
{
    int bh = blockIdx.x;            // b*NH + h
    int b = bh >> 5, h = bh & 31;
    int e = blockIdx.y * 512 + threadIdx.x;   // element in HD*DS plane
    float s = 0.f;
    for (int c = 0; c < NCH; c++) {
        int bc = b * NCH + c;
        float dec = __expf(g_alast[bc * NH + h]);
        size_t base = (size_t)(bc * NH + h) * HD * DS;
        g_prev[base + e] = s;
        s = s * dec + g_states[base + e];
    }
}

// ------ y = intra + inter + D*x, FUSED gate(sigmoid z) + per-head RMS norm ---
// Off-diagonal W tiles use factorized exp: w = score * er[i] * ec[j],
// er[i]=exp(ai-aref)<=1, ec[j]=exp(aref-aj)*dt_j (aref = a at tile start).
__global__ __launch_bounds__(256) void ych_k(const float* __restrict__ D_skip,
                                             const float* __restrict__ norm_w)
{
    int it = blockIdx.x;   // 0..3 (64-row tile)
    int h  = blockIdx.y;   // 0..31
    int bc = blockIdx.z;   // 0..31
    int b = bc / NCH, c = bc % NCH;
    __shared__ float sh[6464];
    float* ai = sh;          // 64
    float* Wt = sh + 64;     // 64*33 (phase1) / 32*64 CtT (phase2)
    float* Xt = sh + 2176;   // 32*128 (phase1) / 32*132 prevT (phase2)
    float* er = sh + 6400;   // 64 row exp factors
    int tid = threadIdx.x;
    int ty = tid >> 5, tx = tid & 31;
    int row0 = b * LL + c * CHUNK;
    float aref = g_a[(bc * CHUNK + it * 64) * NH + h];
    if (tid < 64) {
        float av = g_a[(bc * CHUNK + it * 64 + tid) * NH + h];
        ai[tid] = av;
        er[tid] = __expf(av - aref);
    }
    float acc[8][4];
    #pragma unroll
    for (int i = 0; i < 8; i++)
        #pragma unroll
        for (int j = 0; j < 4; j++) acc[i][j] = 0.f;
    __syncthreads();

    int jtmax = 2 * it + 1;
    for (int jt = 0; jt <= jtmax; jt++) {
        int j0 = jt * 32;
        if (jt < 2 * it) {
            // ---- off-diagonal: all gj < it*64 <= gi; factorized exp ----
            int j = tid & 31;           // constant per thread across t
            int gj = j0 + j;
            float ec = __expf(aref - g_a[(bc * CHUNK + gj) * NH + h]) *
                       g_dt[(size_t)(row0 + gj) * NH + h];
            #pragma unroll
            for (int t = 0; t < 8; t++) {
                int i = (tid >> 5) + t * 8;
                int gi = it * 64 + i;
                Wt[i * 33 + j] =
                    g_scores[((size_t)bc << 16) + gi * 256 + gj] * er[i] * ec;
            }
        } else {
            // ---- diagonal region: elementwise exp with causal mask ----
            #pragma unroll
            for (int t = 0; t < 8; t++) {
                int idx = tid + t * 256;
                int i = idx >> 5, j = idx & 31;
                int gi = it * 64 + i, gj = j0 + j;
                float w = 0.f;
                if (gj <= gi) {
                    float aj = g_a[(bc * CHUNK + gj) * NH + h];
                    float dtj = g_dt[(size_t)(row0 + gj) * NH + h];
                    w = g_scores[((size_t)bc << 16) + gi * 256 + gj] * __expf(ai[i] - aj) * dtj;
                }
                Wt[i * 33 + j] = w;
            }
        }
        #pragma unroll
        for (int t = 0; t < 16; t++) {
            int idx = tid + t * 256;
            int j = idx >> 7, p = idx & 127;
            Xt[j * 128 + p] = g_xbc[(size_t)(row0 + j0 + j) * CONVDIM + h * HD + p];
        }
        __syncthreads();
        for (int j = 0; j < 32; j++) {
            float4 xv = *(float4*)&Xt[j * 128 + tx * 4];
            #pragma unroll
            for (int i = 0; i < 8; i++) {
                float w = Wt[(ty * 8 + i) * 33 + j];
                acc[i][0] += w * xv.x; acc[i][1] += w * xv.y;
                acc[i][2] += w * xv.z; acc[i][3] += w * xv.w;
            }
        }
        __syncthreads();
    }

    float acc2[8][4];
    #pragma unroll
    for (int i = 0; i < 8; i++)
        #pragma unroll
        for (int j = 0; j < 4; j++) acc2[i][j] = 0.f;
    size_t pbase = (size_t)(bc * NH + h) * HD * DS;
    for (int nt = 0; nt < 2; nt++) {
        int n0 = nt * 32;
        #pragma unroll
        for (int t = 0; t < 8; t++) {
            int idx = tid + t * 256;
            int i = idx >> 5, n = idx & 31;
            Wt[n * 64 + i] = g_xbc[(size_t)(row0 + it * 64 + i) * CONVDIM + DIN + DS + n0 + n];
        }
        #pragma unroll
        for (int t = 0; t < 16; t++) {
            int idx = tid + t * 256;
            int p = idx >> 5, n = idx & 31;
            Xt[n * 132 + p] = g_prev[pbase + (size_t)p * DS + n0 + n];
        }
        __syncthreads();
        for (int n = 0; n < 32; n++) {
            float4 pv = *(float4*)&Xt[n * 132 + tx * 4];
            #pragma unroll
            for (int i = 0; i < 8; i++) {
                float cv = Wt[n * 64 + ty * 8 + i];
                acc2[i][0] += cv * pv.x; acc2[i][1] += cv * pv.y;
                acc2[i][2] += cv * pv.z; acc2[i][3] += cv * pv.w;
            }
        }
        __syncthreads();
    }

    // ---- combine + D skip + gate + per-head RMS norm + bf16 hi/lo store ----
    float Dh = D_skip[h];
    float4 nw = *(const float4*)&norm_w[h * HD + tx * 4];
    #pragma unroll
    for (int i = 0; i < 8; i++) {
        int li = ty * 8 + i;
        int gi = it * 64 + li;
        float ea = __expf(ai[li]);
        float4 xv = *(const float4*)&g_xbc[(size_t)(row0 + gi) * CONVDIM + h * HD + tx * 4];
        float4 o;
        o.x = acc[i][0] + ea * acc2[i][0] + Dh * xv.x;
        o.y = acc[i][1] + ea * acc2[i][1] + Dh * xv.y;
        o.z = acc[i][2] + ea * acc2[i][2] + Dh * xv.z;
        o.w = acc[i][3] + ea * acc2[i][3] + Dh * xv.w;
        // gate by sigmoid(z)
        float4 zv = *(const float4*)&g_zx[(size_t)(row0 + gi) * DPROJ + h * HD + tx * 4];
        float4 v;
        v.x = o.x / (1.f + __expf(-zv.x));
        v.y = o.y / (1.f + __expf(-zv.y));
        v.z = o.z / (1.f + __expf(-zv.z));
        v.w = o.w / (1.f + __expf(-zv.w));
        // warp-level RMS over the 128 p-values of this row (4 per lane x 32 lanes)
        float ss = v.x * v.x + v.y * v.y + v.z * v.z + v.w * v.w;
        #pragma unroll
        for (int off = 16; off; off >>= 1) ss += __shfl_xor_sync(0xffffffffu, ss, off);
        float inv = rsqrtf(ss * (1.f / HD) + 1e-6f);
        float r0 = v.x * inv * nw.x;
        float r1 = v.y * inv * nw.y;
        float r2 = v.z * inv * nw.z;
        float r3 = v.w * inv * nw.w;
        size_t oi = (size_t)(row0 + gi) * DIN + h * HD + tx * 4;
        __nv_bfloat16 h0 = __float2bfloat16(r0), h1 = __float2bfloat16(r1);
        __nv_bfloat16 h2 = __float2bfloat16(r2), h3 = __float2bfloat16(r3);
        *(__nv_bfloat162*)&g_ynh[oi]     = __nv_bfloat162(h0, h1);
        *(__nv_bfloat162*)&g_ynh[oi + 2] = __nv_bfloat162(h2, h3);
        *(__nv_bfloat162*)&g_ynl[oi]     = __nv_bfloat162(
            __float2bfloat16(r0 - __bfloat162float(h0)),
            __float2bfloat16(r1 - __bfloat162float(h1)));
        *(__nv_bfloat162*)&g_ynl[oi + 2] = __nv_bfloat162(
            __float2bfloat16(r2 - __bfloat162float(h2)),
            __float2bfloat16(r3 - __bfloat162float(h3)));
    }
}

// ------------------- launch ---------------------------------------------------
extern "C" void kernel_launch(void* const* d_in, const int* in_sizes, int n_in,
                              void* d_out, int out_size)
{
    const float* u         = (const float*)d_in[0];
    const float* in_proj_w = (const float*)d_in[1];
    const float* conv_w    = (const float*)d_in[2];
    const float* conv_b    = (const float*)d_in[3];
    const float* A_log     = (const float*)d_in[4];
    const float* dt_bias   = (const float*)d_in[5];
    const float* D_skip    = (const float*)d_in[6];
    const float* norm_w    = (const float*)d_in[7];
    const float* o_proj_w  = (const float*)d_in[8];
    float* out = (float*)d_out;

    float* zx = nullptr;
    cudaGetSymbolAddress((void**)&zx, g_zx);
    __nv_bfloat16 *uh, *ul, *w1h, *w1l, *w2h, *w2l, *ynh, *ynl;
    cudaGetSymbolAddress((void**)&uh,  g_uh);
    cudaGetSymbolAddress((void**)&ul,  g_ul);
    cudaGetSymbolAddress((void**)&w1h, g_w1h);
    cudaGetSymbolAddress((void**)&w1l, g_w1l);
    cudaGetSymbolAddress((void**)&w2h, g_w2h);
    cudaGetSymbolAddress((void**)&w2l, g_w2l);
    cudaGetSymbolAddress((void**)&ynh, g_ynh);
    cudaGetSymbolAddress((void**)&ynl, g_ynl);

    const int SMEM_GEMM = 2 * HSTAGEB;   // 147456
    cudaFuncSetAttribute(hgemm3, cudaFuncAttributeMaxDynamicSharedMemorySize, SMEM_GEMM);

    const int M = BB * LL;   // 8192

    // 0) hi/lo splits of GEMM inputs
    {
        int n4;
        n4 = (M * EMBED) / 4;
        split_k<<<(n4 + 255) / 256, 256>>>(u, uh, ul, n4);
        n4 = (DPROJ * EMBED) / 4;
        split_k<<<(n4 + 255) / 256, 256>>>(in_proj_w, w1h, w1l, n4);
        n4 = (EMBED * DIN) / 4;
        split_k<<<(n4 + 255) / 256, 256>>>(o_proj_w, w2h, w2l, n4);
    }
    // 1) in_proj: zx = u @ W1^T  (HMMA bf16x3)
    hgemm3<<<dim3((DPROJ + HBN - 1) / HBN, M / HBM), 512, SMEM_GEMM>>>(
        M, DPROJ, EMBED, uh, ul, w1h, w1l, zx);
    // 2) causal depthwise conv + silu
    conv_silu_k<<<(BB * LL * CONVDIM + 255) / 256, 256>>>(conv_w, conv_b);
    // 3) fused dt softplus + per-chunk cumsum (parallel scan)
    cumsum_k<<<NBC * NH, 32>>>(A_log, dt_bias);
    // 4) chunk attention scores (lower tiles)
    scores_k<<<dim3(4, 4, NBC), 256>>>();
    // 5) per-chunk end states
    states_k<<<NBC * NH, 256>>>();
    // 6) inter-chunk scan (16 slices per (b,h))
    scan_k<<<dim3(BB * NH, 16), 512>>>();
    // 7) y = intra + inter + D*x, fused gate + RMS norm (writes bf16 hi/lo)
    ych_k<<<dim3(4, NH, NBC), 256>>>(D_skip, norm_w);
    // 8) o_proj: out = yn @ W2^T  (HMMA bf16x3)
    hgemm3<<<dim3(EMBED / HBN, M / HBM), 512, SMEM_GEMM>>>(
        M, EMBED, DIN, ynh, ynl, w2h, w2l, out);
}

// round 11
// speedup vs baseline: 1.2024x; 1.0509x over previous
#include <cuda_runtime.h>
#include <cuda_bf16.h>
#include <cstdint>

#define BB 2
#define LL 4096
#define EMBED 2048
#define DIN 4096
#define NH 32
#define HD 128
#define DS 64
#define CONVDIM 4224   // DIN + 2*DS
#define DPROJ 8352     // 2*DIN + 2*DS + NH
#define CHUNK 256
#define NCH 16         // LL / CHUNK
#define NBC (BB*NCH)   // 32

// ------------------- scratch (device globals; no cudaMalloc allowed) ---------
__device__ float g_zx[(size_t)BB*LL*DPROJ];        // in_proj output
__device__ float g_xbc[(size_t)BB*LL*CONVDIM];     // conv+silu output
__device__ float g_dt[BB*LL*NH];                   // softplus(dt)
__device__ float g_a[NBC*CHUNK*NH];                // cumsum(dA) per chunk
__device__ float g_alast[NBC*NH];
__device__ float g_scores[(size_t)NBC*CHUNK*CHUNK];
__device__ float g_states[(size_t)NBC*NH*HD*DS];   // [b,c,h,p,n]
__device__ float g_prev[(size_t)NBC*NH*HD*DS];     // state entering chunk c

// bf16 hi/lo split buffers
__device__ __nv_bfloat16 g_uh[(size_t)BB*LL*EMBED];
__device__ __nv_bfloat16 g_ul[(size_t)BB*LL*EMBED];
__device__ __nv_bfloat16 g_w1h[(size_t)DPROJ*EMBED];
__device__ __nv_bfloat16 g_w1l[(size_t)DPROJ*EMBED];
__device__ __nv_bfloat16 g_w2h[(size_t)EMBED*DIN];
__device__ __nv_bfloat16 g_w2l[(size_t)EMBED*DIN];
__device__ __nv_bfloat16 g_ynh[(size_t)BB*LL*DIN];
__device__ __nv_bfloat16 g_ynl[(size_t)BB*LL*DIN];

// ------------------- PTX helpers (sm_80-era: valid on base sm_103 target) ----
__device__ __forceinline__ uint32_t s2u(const void* p) {
    uint32_t a;
    asm("{ .reg .u64 t; cvta.to.shared.u64 t, %1; cvt.u32.u64 %0, t; }" : "=r"(a) : "l"(p));
    return a;
}
__device__ __forceinline__ void cpasync16(uint32_t s, const void* g, int srcsize) {
    asm volatile("cp.async.ca.shared.global [%0], [%1], 16, %2;"
                 :: "r"(s), "l"(g), "r"(srcsize));
}
__device__ __forceinline__ void cpcommit() {
    asm volatile("cp.async.commit_group;" ::: "memory");
}
template <int N>
__device__ __forceinline__ void cpwait() {
    asm volatile("cp.async.wait_group %0;" :: "n"(N) : "memory");
}
__device__ __forceinline__ void ldsm4(uint32_t* r, uint32_t addr) {
    asm volatile("ldmatrix.sync.aligned.m8n8.x4.shared.b16 {%0,%1,%2,%3}, [%4];"
                 : "=r"(r[0]), "=r"(r[1]), "=r"(r[2]), "=r"(r[3]) : "r"(addr));
}
__device__ __forceinline__ void mma16816(float* c, const uint32_t* a, const uint32_t* b) {
    asm volatile(
        "mma.sync.aligned.m16n8k16.row.col.f32.bf16.bf16.f32 "
        "{%0,%1,%2,%3},{%4,%5,%6,%7},{%8,%9},{%0,%1,%2,%3};"
        : "+f"(c[0]), "+f"(c[1]), "+f"(c[2]), "+f"(c[3])
        : "r"(a[0]), "r"(a[1]), "r"(a[2]), "r"(a[3]), "r"(b[0]), "r"(b[1]));
}
__device__ __forceinline__ void mma_tf32(float* d, const uint32_t* a, const uint32_t* b) {
    asm volatile(
        "mma.sync.aligned.m16n8k8.row.col.f32.tf32.tf32.f32 "
        "{%0,%1,%2,%3},{%4,%5,%6,%7},{%8,%9},{%0,%1,%2,%3};"
        : "+f"(d[0]), "+f"(d[1]), "+f"(d[2]), "+f"(d[3])
        : "r"(a[0]), "r"(a[1]), "r"(a[2]), "r"(a[3]), "r"(b[0]), "r"(b[1]));
}
__device__ __forceinline__ uint32_t f2tf(float x) {
    uint32_t r; asm("cvt.rna.tf32.f32 %0, %1;" : "=r"(r) : "f"(x)); return r;
}

// ------------------- fp32 -> bf16 hi/lo split --------------------------------
__global__ void split_k(const float* __restrict__ s, __nv_bfloat16* __restrict__ hi,
                        __nv_bfloat16* __restrict__ lo, int n4)
{
    int i = blockIdx.x * 256 + threadIdx.x;
    if (i >= n4) return;
    float4 v = ((const float4*)s)[i];
    __nv_bfloat16 h0 = __float2bfloat16(v.x), h1 = __float2bfloat16(v.y);
    __nv_bfloat16 h2 = __float2bfloat16(v.z), h3 = __float2bfloat16(v.w);
    __nv_bfloat162* H = (__nv_bfloat162*)hi;
    __nv_bfloat162* L = (__nv_bfloat162*)lo;
    H[i*2+0] = __nv_bfloat162(h0, h1);
    H[i*2+1] = __nv_bfloat162(h2, h3);
    L[i*2+0] = __nv_bfloat162(__float2bfloat16(v.x - __bfloat162float(h0)),
                              __float2bfloat16(v.y - __bfloat162float(h1)));
    L[i*2+1] = __nv_bfloat162(__float2bfloat16(v.z - __bfloat162float(h2)),
                              __float2bfloat16(v.w - __bfloat162float(h3)));
}

// ------------------- HMMA bf16x3 GEMM: C[M,N] = A[M,K] @ B[N,K]^T ------------
// (EXACT round-3/7 configuration — proven fastest; FROZEN.)
#define HBM 128
#define HBN 128
#define HBK 64
#define HLD 72
#define HMATB (128*HLD*2)
#define HSTAGEB (4*HMATB)

__global__ __launch_bounds__(512) void hgemm3(
    int M, int N, int K,
    const __nv_bfloat16* __restrict__ Ah, const __nv_bfloat16* __restrict__ Al,
    const __nv_bfloat16* __restrict__ Bh, const __nv_bfloat16* __restrict__ Bl,
    float* __restrict__ C)
{
    extern __shared__ char smem[];
    const int tid = threadIdx.x;
    const int lane = tid & 31, wid = tid >> 5;
    const int wm = wid & 3, wn = wid >> 2;
    const int bm = blockIdx.y * HBM, bn = blockIdx.x * HBN;
    const uint32_t sbase = s2u(smem);

    const int arow = lane & 15, akoff = (lane >> 4) << 3;
    const int bnl = (lane & 7) + ((lane >> 4) << 3);
    const int bkl = ((lane >> 3) & 1) << 3;

    float acc[2][4][4];
    #pragma unroll
    for (int mt = 0; mt < 2; mt++)
        #pragma unroll
        for (int nt = 0; nt < 4; nt++)
            #pragma unroll
            for (int i = 0; i < 4; i++) acc[mt][nt][i] = 0.f;

    const int nk = K / HBK;

    auto load_stage = [&](int st, int k0) {
        uint32_t sb = sbase + st * HSTAGEB;
        #pragma unroll
        for (int i = 0; i < 2; i++) {
            int chunk = tid + i * 512;
            int row = chunk >> 3, c = chunk & 7;
            uint32_t so = (uint32_t)(row * HLD + c * 8) * 2;
            size_t ga = (size_t)(bm + row) * K + k0 + c * 8;
            cpasync16(sb + so,             Ah + ga, 16);
            cpasync16(sb + HMATB + so,     Al + ga, 16);
            int brow = bn + row;
            int sz = (brow < N) ? 16 : 0;
            int bcl = (brow < N) ? brow : 0;
            size_t gb = (size_t)bcl * K + k0 + c * 8;
            cpasync16(sb + 2*HMATB + so,   Bh + gb, sz);
            cpasync16(sb + 3*HMATB + so,   Bl + gb, sz);
        }
        cpcommit();
    };

    load_stage(0, 0);

    for (int kt = 0; kt < nk; ++kt) {
        if (kt + 1 < nk) {
            load_stage((kt + 1) & 1, (kt + 1) * HBK);
            cpwait<1>();
        } else {
            cpwait<0>();
        }
        __syncthreads();

        uint32_t sb = sbase + (kt & 1) * HSTAGEB;
        uint32_t sAh = sb, sAl = sb + HMATB, sBh = sb + 2*HMATB, sBl = sb + 3*HMATB;

        #pragma unroll
        for (int kh = 0; kh < 4; kh++) {
            int k = kh * 16;
            uint32_t bfh[2][4], bfl[2][4];
            #pragma unroll
            for (int ntp = 0; ntp < 2; ntp++) {
                uint32_t off = (uint32_t)((wn * 32 + ntp * 16 + bnl) * HLD + k + bkl) * 2;
                ldsm4(bfh[ntp], sBh + off);
                ldsm4(bfl[ntp], sBl + off);
            }
            #pragma unroll
            for (int mt = 0; mt < 2; mt++) {
                uint32_t aoff = (uint32_t)((wm * 32 + mt * 16 + arow) * HLD + k + akoff) * 2;
                uint32_t af[4];
                ldsm4(af, sAh + aoff);
                #pragma unroll
                for (int nt = 0; nt < 4; nt++)
                    mma16816(acc[mt][nt], af, &bfh[nt >> 1][(nt & 1) * 2]);
                #pragma unroll
                for (int nt = 0; nt < 4; nt++)
                    mma16816(acc[mt][nt], af, &bfl[nt >> 1][(nt & 1) * 2]);
                ldsm4(af, sAl + aoff);
                #pragma unroll
                for (int nt = 0; nt < 4; nt++)
                    mma16816(acc[mt][nt], af, &bfh[nt >> 1][(nt & 1) * 2]);
            }
        }
        __syncthreads();
    }

    #pragma unroll
    for (int mt = 0; mt < 2; mt++) {
        int row0 = bm + wm * 32 + mt * 16 + (lane >> 2);
        #pragma unroll
        for (int nt = 0; nt < 4; nt++) {
            int col = bn + wn * 32 + nt * 8 + (lane & 3) * 2;
            if (col < N) {
                *(float2*)&C[(size_t)row0 * N + col] =
                    make_float2(acc[mt][nt][0], acc[mt][nt][1]);
                *(float2*)&C[(size_t)(row0 + 8) * N + col] =
                    make_float2(acc[mt][nt][2], acc[mt][nt][3]);
            }
        }
    }
}

// ------------------- depthwise causal conv (k=4) + silu ----------------------
__global__ void conv_silu_k(const float* __restrict__ cw, const float* __restrict__ cb)
{
    int idx = blockIdx.x * 256 + threadIdx.x;
    const int total = BB * LL * CONVDIM;
    if (idx >= total) return;
    int ch = idx % CONVDIM;
    int bl = idx / CONVDIM;
    int l = bl % LL, b = bl / LL;
    float acc = cb[ch];
    #pragma unroll
    for (int k = 0; k < 4; k++) {
        int ll = l - 3 + k;
        if (ll >= 0)
            acc += g_zx[(size_t)(b * LL + ll) * DPROJ + DIN + ch] * cw[ch * 4 + k];
    }
    g_xbc[idx] = acc / (1.f + __expf(-acc));
}

// ------------------- per-chunk cumsum of dA (fused softplus + warp scan) -----
__global__ void cumsum_k(const float* __restrict__ A_log, const float* __restrict__ dt_bias)
{
    int bch = blockIdx.x;            // bc*NH + h
    int h = bch & 31, bc = bch >> 5;
    int b = bc / NCH, c = bc % NCH;
    int t = threadIdx.x;             // 32
    float Ah = -__expf(A_log[h]);
    float bias = dt_bias[h];
    size_t row0 = (size_t)(b * LL + c * CHUNK) + t * 8;
    float v[8];
    #pragma unroll
    for (int j = 0; j < 8; j++) {
        float x = g_zx[(row0 + j) * DPROJ + DIN + CONVDIM + h] + bias;
        float sp = (x > 20.f) ? x : log1pf(__expf(x));
        g_dt[(row0 + j) * NH + h] = sp;
        v[j] = sp * Ah;
    }
    float loc = 0.f;
    #pragma unroll
    for (int j = 0; j < 8; j++) { loc += v[j]; v[j] = loc; }
    float pre = loc;
    #pragma unroll
    for (int o = 1; o < 32; o <<= 1) {
        float nv = __shfl_up_sync(0xffffffffu, pre, o);
        if (t >= o) pre += nv;
    }
    pre -= loc;   // exclusive prefix
    #pragma unroll
    for (int j = 0; j < 8; j++) g_a[(bc * CHUNK + t * 8 + j) * NH + h] = pre + v[j];
    if (t == 31) g_alast[bc * NH + h] = pre + loc;
}

// ------------------- scores = C @ B^T per chunk (lower tiles only) -----------
__global__ __launch_bounds__(256) void scores_k()
{
    int jt = blockIdx.x, it = blockIdx.y, bc = blockIdx.z;
    if (jt > it) return;
    int b = bc / NCH, c = bc % NCH;
    __shared__ float CtT[64][65];
    __shared__ float BtT[64][65];
    int tid = threadIdx.x;
    for (int t = tid; t < 64 * 64; t += 256) {
        int r = t >> 6, n = t & 63;
        int rowC = b * LL + c * CHUNK + it * 64 + r;
        int rowB = b * LL + c * CHUNK + jt * 64 + r;
        CtT[n][r] = g_xbc[(size_t)rowC * CONVDIM + DIN + DS + n];
        BtT[n][r] = g_xbc[(size_t)rowB * CONVDIM + DIN + n];
    }
    __syncthreads();
    int ty = tid >> 4, tx = tid & 15;
    float acc[4][4];
    #pragma unroll
    for (int i = 0; i < 4; i++)
        #pragma unroll
        for (int j = 0; j < 4; j++) acc[i][j] = 0.f;
    for (int n = 0; n < 64; n++) {
        float a[4], w[4];
        #pragma unroll
        for (int i = 0; i < 4; i++) a[i] = CtT[n][ty * 4 + i];
        #pragma unroll
        for (int j = 0; j < 4; j++) w[j] = BtT[n][tx * 4 + j];
        #pragma unroll
        for (int i = 0; i < 4; i++)
            #pragma unroll
            for (int j = 0; j < 4; j++) acc[i][j] += a[i] * w[j];
    }
    #pragma unroll
    for (int i = 0; i < 4; i++)
        #pragma unroll
        for (int j = 0; j < 4; j++)
            g_scores[((size_t)bc << 16) + (it * 64 + ty * 4 + i) * 256 + jt * 64 + tx * 4 + j] = acc[i][j];
}

// ------------------- per-chunk states[h,p,n] ---------------------------------
__global__ __launch_bounds__(256) void states_k()
{
    int bch = blockIdx.x;              // bc*NH + h
    int h = bch % NH, bc = bch / NH;
    int b = bc / NCH, c = bc % NCH;
    __shared__ float Xq[32][128];
    __shared__ float Bco[32][64];
    __shared__ float coef[32];
    int tid = threadIdx.x;
    float alast = g_alast[bc * NH + h];
    int tp = tid >> 4, tn = tid & 15;
    float acc[8][4];
    #pragma unroll
    for (int i = 0; i < 8; i++)
        #pragma unroll
        for (int j = 0; j < 4; j++) acc[i][j] = 0.f;

    for (int q0 = 0; q0 < CHUNK; q0 += 32) {
        __syncthreads();
        if (tid < 32) {
            int gq = q0 + tid;
            float aq = g_a[(bc * CHUNK + gq) * NH + h];
            float dtq = g_dt[(size_t)(b * LL + c * CHUNK + gq) * NH + h];
            coef[tid] = dtq * __expf(alast - aq);
        }
        #pragma unroll
        for (int t = 0; t < 16; t++) {
            int idx = tid + t * 256;
            int q = idx >> 7, p = idx & 127;
            Xq[q][p] = g_xbc[(size_t)(b * LL + c * CHUNK + q0 + q) * CONVDIM + h * HD + p];
        }
        __syncthreads();
        #pragma unroll
        for (int t = 0; t < 8; t++) {
            int idx = tid + t * 256;
            int q = idx >> 6, n = idx & 63;
            Bco[q][n] = g_xbc[(size_t)(b * LL + c * CHUNK + q0 + q) * CONVDIM + DIN + n] * coef[q];
        }
        __syncthreads();
        for (int q = 0; q < 32; q++) {
            float xv[8], bv[4];
            #pragma unroll
            for (int i = 0; i < 8; i++) xv[i] = Xq[q][tp * 8 + i];
            #pragma unroll
            for (int j = 0; j < 4; j++) bv[j] = Bco[q][tn * 4 + j];
            #pragma unroll
            for (int i = 0; i < 8; i++)
                #pragma unroll
                for (int j = 0; j < 4; j++) acc[i][j] += xv[i] * bv[j];
        }
    }
    size_t base = (size_t)bch * HD * DS;
    #pragma unroll
    for (int i = 0; i < 8; i++)
        #pragma unroll
        for (int j = 0; j < 4; j++)
            g_states[base + (tp * 8 + i) * DS + tn * 4 + j] = acc[i][j];
}

// ------------------- sequential inter-chunk scan (split over 16 slices) ------
__global__ void scan_k()
{
    int bh = blockIdx.x;            // b*NH + h
    int b = bh >> 5, h = bh & 31;
    int e = blockIdx.y * 512 + threadIdx.x;   // element in HD*DS plane
    float s = 0.f;
    for (int c = 0; c < NCH; c++) {
        int bc = b * NCH + c;
        float dec = __expf(g_alast[bc * NH + h]);
        size_t base = (size_t)(bc * NH + h) * HD * DS;
        g_prev[base + e] = s;
        s = s * dec + g_states[base + e];
    }
}

// ------ y = intra + inter + D*x (tf32 MMA) + fused gate + per-head RMS -------
// Phase1: Y1[64,128] = W[64,K]·X[K,128] via m16n8k8 tf32 (K = (it+1)*64).
// Phase2: Y2[64,128] = C[64,64]·prev^T[64,128] via tf32 MMA.
// 8 warps = 2m x 4n; warp tile 32x32; accs in mma layout. Epilogue fused.
__global__ __launch_bounds__(256) void ych_k(const float* __restrict__ D_skip,
                                             const float* __restrict__ norm_w)
{
    int it = blockIdx.x;   // 0..3 (64-row tile)
    int h  = blockIdx.y;   // 0..31
    int bc = blockIdx.z;   // 0..31
    int b = bc / NCH, c = bc % NCH;
    __shared__ float sh[9088];
    float* ai    = sh;            // 64
    float* er    = sh + 64;       // 64
    float* Ab    = sh + 128;      // 4352: Wt[64][36] (p1) / Ct[64][68] (p2)
    float* Bb    = sh + 4480;     // 4352: Xt[32][136] (p1) / prevT[32][136] (p2)
    float* ssbuf = sh + 8832;     // 64*4
    int tid = threadIdx.x;
    const int lane = tid & 31, wid = tid >> 5;
    const int gid = lane >> 2, tig = lane & 3;
    const int wm = wid >> 2, wn = wid & 3;     // 2m x 4n
    int row0 = b * LL + c * CHUNK;
    float aref = g_a[(bc * CHUNK + it * 64) * NH + h];
    if (tid < 64) {
        float av = g_a[(bc * CHUNK + it * 64 + tid) * NH + h];
        ai[tid] = av;
        er[tid] = __expf(av - aref);
    }
    float accA[2][4][4], accB[2][4][4];
    #pragma unroll
    for (int mt = 0; mt < 2; mt++)
        #pragma unroll
        for (int nt = 0; nt < 4; nt++)
            #pragma unroll
            for (int i = 0; i < 4; i++) { accA[mt][nt][i] = 0.f; accB[mt][nt][i] = 0.f; }
    __syncthreads();

    // ================== phase 1: intra (K tiles of 32) ==================
    int jtmax = 2 * it + 1;
    for (int jt = 0; jt <= jtmax; jt++) {
        int j0 = jt * 32;
        if (jt < 2 * it) {
            // off-diagonal: factorized exp
            int j = tid & 31;
            int gj = j0 + j;
            float ec = __expf(aref - g_a[(bc * CHUNK + gj) * NH + h]) *
                       g_dt[(size_t)(row0 + gj) * NH + h];
            #pragma unroll
            for (int t = 0; t < 8; t++) {
                int i = (tid >> 5) + t * 8;
                int gi = it * 64 + i;
                Ab[i * 36 + j] =
                    g_scores[((size_t)bc << 16) + gi * 256 + gj] * er[i] * ec;
            }
        } else {
            // diagonal region: elementwise exp with causal mask
            #pragma unroll
            for (int t = 0; t < 8; t++) {
                int idx = tid + t * 256;
                int i = idx >> 5, j = idx & 31;
                int gi = it * 64 + i, gj = j0 + j;
                float w = 0.f;
                if (gj <= gi) {
                    float aj = g_a[(bc * CHUNK + gj) * NH + h];
                    float dtj = g_dt[(size_t)(row0 + gj) * NH + h];
                    w = g_scores[((size_t)bc << 16) + gi * 256 + gj] * __expf(ai[i] - aj) * dtj;
                }
                Ab[i * 36 + j] = w;
            }
        }
        #pragma unroll
        for (int t = 0; t < 16; t++) {
            int idx = tid + t * 256;
            int j = idx >> 7, p = idx & 127;
            Bb[j * 136 + p] = g_xbc[(size_t)(row0 + j0 + j) * CONVDIM + h * HD + p];
        }
        __syncthreads();
        #pragma unroll
        for (int ks = 0; ks < 4; ks++) {
            uint32_t bfr[4][2];
            #pragma unroll
            for (int ntf = 0; ntf < 4; ntf++) {
                bfr[ntf][0] = f2tf(Bb[(ks*8 + tig)     * 136 + wn*32 + ntf*8 + gid]);
                bfr[ntf][1] = f2tf(Bb[(ks*8 + tig + 4) * 136 + wn*32 + ntf*8 + gid]);
            }
            #pragma unroll
            for (int mt = 0; mt < 2; mt++) {
                int r0 = wm*32 + mt*16 + gid;
                uint32_t afr[4];
                afr[0] = f2tf(Ab[ r0      * 36 + ks*8 + tig]);
                afr[1] = f2tf(Ab[(r0 + 8) * 36 + ks*8 + tig]);
                afr[2] = f2tf(Ab[ r0      * 36 + ks*8 + tig + 4]);
                afr[3] = f2tf(Ab[(r0 + 8) * 36 + ks*8 + tig + 4]);
                #pragma unroll
                for (int ntf = 0; ntf < 4; ntf++)
                    mma_tf32(accA[mt][ntf], afr, bfr[ntf]);
            }
        }
        __syncthreads();
    }

    // ================== phase 2: inter (K = 64, 2 tiles) ==================
    // build Ct[64][68] once
    #pragma unroll
    for (int t = 0; t < 16; t++) {
        int idx = tid + t * 256;
        int i = idx >> 6, n = idx & 63;
        Ab[i * 68 + n] = g_xbc[(size_t)(row0 + it * 64 + i) * CONVDIM + DIN + DS + n];
    }
    size_t pbase = (size_t)(bc * NH + h) * HD * DS;
    for (int nt = 0; nt < 2; nt++) {
        int n0 = nt * 32;
        #pragma unroll
        for (int t = 0; t < 16; t++) {
            int idx = tid + t * 256;
            int p = idx >> 5, n = idx & 31;
            Bb[n * 136 + p] = g_prev[pbase + (size_t)p * DS + n0 + n];
        }
        __syncthreads();
        #pragma unroll
        for (int ks = 0; ks < 4; ks++) {
            uint32_t bfr[4][2];
            #pragma unroll
            for (int ntf = 0; ntf < 4; ntf++) {
                bfr[ntf][0] = f2tf(Bb[(ks*8 + tig)     * 136 + wn*32 + ntf*8 + gid]);
                bfr[ntf][1] = f2tf(Bb[(ks*8 + tig + 4) * 136 + wn*32 + ntf*8 + gid]);
            }
            #pragma unroll
            for (int mt = 0; mt < 2; mt++) {
                int r0 = wm*32 + mt*16 + gid;
                uint32_t afr[4];
                afr[0] = f2tf(Ab[ r0      * 68 + n0 + ks*8 + tig]);
                afr[1] = f2tf(Ab[(r0 + 8) * 68 + n0 + ks*8 + tig]);
                afr[2] = f2tf(Ab[ r0      * 68 + n0 + ks*8 + tig + 4]);
                afr[3] = f2tf(Ab[(r0 + 8) * 68 + n0 + ks*8 + tig + 4]);
                #pragma unroll
                for (int ntf = 0; ntf < 4; ntf++)
                    mma_tf32(accB[mt][ntf], afr, bfr[ntf]);
            }
        }
        __syncthreads();
    }

    // ====== epilogue: combine + D skip + gate + RMS (mma layout) ======
    float Dh = D_skip[h];
    #pragma unroll
    for (int mt = 0; mt < 2; mt++) {
        #pragma unroll
        for (int hf = 0; hf < 2; hf++) {
            int rl = wm*32 + mt*16 + hf*8 + gid;
            int gi = it * 64 + rl;
            float ea = __expf(ai[rl]);
            float ss = 0.f;
            #pragma unroll
            for (int ntf = 0; ntf < 4; ntf++) {
                int col = wn*32 + ntf*8 + 2*tig;
                float2 xv = *(const float2*)&g_xbc[(size_t)(row0 + gi) * CONVDIM + h * HD + col];
                float2 zv = *(const float2*)&g_zx[(size_t)(row0 + gi) * DPROJ + h * HD + col];
                float o0 = accA[mt][ntf][hf*2+0] + ea * accB[mt][ntf][hf*2+0] + Dh * xv.x;
                float o1 = accA[mt][ntf][hf*2+1] + ea * accB[mt][ntf][hf*2+1] + Dh * xv.y;
                float v0 = o0 / (1.f + __expf(-zv.x));
                float v1 = o1 / (1.f + __expf(-zv.y));
                accA[mt][ntf][hf*2+0] = v0;
                accA[mt][ntf][hf*2+1] = v1;
                ss += v0 * v0 + v1 * v1;
            }
            ss += __shfl_xor_sync(0xffffffffu, ss, 1);
            ss += __shfl_xor_sync(0xffffffffu, ss, 2);
            if (tig == 0) ssbuf[rl * 4 + wn] = ss;
        }
    }
    __syncthreads();
    #pragma unroll
    for (int mt = 0; mt < 2; mt++) {
        #pragma unroll
        for (int hf = 0; hf < 2; hf++) {
            int rl = wm*32 + mt*16 + hf*8 + gid;
            int gi = it * 64 + rl;
            float tot = ssbuf[rl*4+0] + ssbuf[rl*4+1] + ssbuf[rl*4+2] + ssbuf[rl*4+3];
            float inv = rsqrtf(tot * (1.f / HD) + 1e-6f);
            #pragma unroll
            for (int ntf = 0; ntf < 4; ntf++) {
                int col = wn*32 + ntf*8 + 2*tig;
                float2 nw = *(const float2*)&norm_w[h * HD + col];
                float r0 = accA[mt][ntf][hf*2+0] * inv * nw.x;
                float r1 = accA[mt][ntf][hf*2+1] * inv * nw.y;
                size_t oi = (size_t)(row0 + gi) * DIN + h * HD + col;
                __nv_bfloat16 h0 = __float2bfloat16(r0), h1 = __float2bfloat16(r1);
                *(__nv_bfloat162*)&g_ynh[oi] = __nv_bfloat162(h0, h1);
                *(__nv_bfloat162*)&g_ynl[oi] = __nv_bfloat162(
                    __float2bfloat16(r0 - __bfloat162float(h0)),
                    __float2bfloat16(r1 - __bfloat162float(h1)));
            }
        }
    }
}

// ------------------- launch ---------------------------------------------------
extern "C" void kernel_launch(void* const* d_in, const int* in_sizes, int n_in,
                              void* d_out, int out_size)
{
    const float* u         = (const float*)d_in[0];
    const float* in_proj_w = (const float*)d_in[1];
    const float* conv_w    = (const float*)d_in[2];
    const float* conv_b    = (const float*)d_in[3];
    const float* A_log     = (const float*)d_in[4];
    const float* dt_bias   = (const float*)d_in[5];
    const float* D_skip    = (const float*)d_in[6];
    const float* norm_w    = (const float*)d_in[7];
    const float* o_proj_w  = (const float*)d_in[8];
    float* out = (float*)d_out;

    float* zx = nullptr;
    cudaGetSymbolAddress((void**)&zx, g_zx);
    __nv_bfloat16 *uh, *ul, *w1h, *w1l, *w2h, *w2l, *ynh, *ynl;
    cudaGetSymbolAddress((void**)&uh,  g_uh);
    cudaGetSymbolAddress((void**)&ul,  g_ul);
    cudaGetSymbolAddress((void**)&w1h, g_w1h);
    cudaGetSymbolAddress((void**)&w1l, g_w1l);
    cudaGetSymbolAddress((void**)&w2h, g_w2h);
    cudaGetSymbolAddress((void**)&w2l, g_w2l);
    cudaGetSymbolAddress((void**)&ynh, g_ynh);
    cudaGetSymbolAddress((void**)&ynl, g_ynl);

    const int SMEM_GEMM = 2 * HSTAGEB;   // 147456
    cudaFuncSetAttribute(hgemm3, cudaFuncAttributeMaxDynamicSharedMemorySize, SMEM_GEMM);

    const int M = BB * LL;   // 8192

    // 0) hi/lo splits of GEMM inputs
    {
        int n4;
        n4 = (M * EMBED) / 4;
        split_k<<<(n4 + 255) / 256, 256>>>(u, uh, ul, n4);
        n4 = (DPROJ * EMBED) / 4;
        split_k<<<(n4 + 255) / 256, 256>>>(in_proj_w, w1h, w1l, n4);
        n4 = (EMBED * DIN) / 4;
        split_k<<<(n4 + 255) / 256, 256>>>(o_proj_w, w2h, w2l, n4);
    }
    // 1) in_proj: zx = u @ W1^T  (HMMA bf16x3)
    hgemm3<<<dim3((DPROJ + HBN - 1) / HBN, M / HBM), 512, SMEM_GEMM>>>(
        M, DPROJ, EMBED, uh, ul, w1h, w1l, zx);
    // 2) causal depthwise conv + silu
    conv_silu_k<<<(BB * LL * CONVDIM + 255) / 256, 256>>>(conv_w, conv_b);
    // 3) fused dt softplus + per-chunk cumsum (parallel scan)
    cumsum_k<<<NBC * NH, 32>>>(A_log, dt_bias);
    // 4) chunk attention scores (lower tiles)
    scores_k<<<dim3(4, 4, NBC), 256>>>();
    // 5) per-chunk end states
    states_k<<<NBC * NH, 256>>>();
    // 6) inter-chunk scan (16 slices per (b,h))
    scan_k<<<dim3(BB * NH, 16), 512>>>();
    // 7) y: tf32 MMA intra+inter, fused gate + RMS norm (writes bf16 hi/lo)
    ych_k<<<dim3(4, NH, NBC), 256>>>(D_skip, norm_w);
    // 8) o_proj: out = yn @ W2^T  (HMMA bf16x3)
    hgemm3<<<dim3(EMBED / HBN, M / HBM), 512, SMEM_GEMM>>>(
        M, EMBED, DIN, ynh, ynl, w2h, w2l, out);
}

// round 12
// speedup vs baseline: 1.2044x; 1.0016x over previous
#include <cuda_runtime.h>
#include <cuda_bf16.h>
#include <cstdint>

#define BB 2
#define LL 4096
#define EMBED 2048
#define DIN 4096
#define NH 32
#define HD 128
#define DS 64
#define CONVDIM 4224   // DIN + 2*DS
#define DPROJ 8352     // 2*DIN + 2*DS + NH
#define CHUNK 256
#define NCH 16         // LL / CHUNK
#define NBC (BB*NCH)   // 32

// ------------------- scratch (device globals; no cudaMalloc allowed) ---------
__device__ float g_zx[(size_t)BB*LL*DPROJ];        // in_proj output
__device__ float g_xbc[(size_t)BB*LL*CONVDIM];     // conv+silu output
__device__ float g_dt[BB*LL*NH];                   // softplus(dt)
__device__ float g_a[NBC*CHUNK*NH];                // cumsum(dA) per chunk
__device__ float g_alast[NBC*NH];
__device__ float g_scores[(size_t)NBC*CHUNK*CHUNK];
__device__ float g_states[(size_t)NBC*NH*HD*DS];   // [b,c,h,p,n]
__device__ float g_prev[(size_t)NBC*NH*HD*DS];     // state entering chunk c

// bf16 hi/lo split buffers
__device__ __nv_bfloat16 g_uh[(size_t)BB*LL*EMBED];
__device__ __nv_bfloat16 g_ul[(size_t)BB*LL*EMBED];
__device__ __nv_bfloat16 g_w1h[(size_t)DPROJ*EMBED];
__device__ __nv_bfloat16 g_w1l[(size_t)DPROJ*EMBED];
__device__ __nv_bfloat16 g_w2h[(size_t)EMBED*DIN];
__device__ __nv_bfloat16 g_w2l[(size_t)EMBED*DIN];
__device__ __nv_bfloat16 g_ynh[(size_t)BB*LL*DIN];
__device__ __nv_bfloat16 g_ynl[(size_t)BB*LL*DIN];

// ------------------- PTX helpers (sm_80-era: valid on base sm_103 target) ----
__device__ __forceinline__ uint32_t s2u(const void* p) {
    uint32_t a;
    asm("{ .reg .u64 t; cvta.to.shared.u64 t, %1; cvt.u32.u64 %0, t; }" : "=r"(a) : "l"(p));
    return a;
}
__device__ __forceinline__ void cpasync16(uint32_t s, const void* g, int srcsize) {
    asm volatile("cp.async.ca.shared.global [%0], [%1], 16, %2;"
                 :: "r"(s), "l"(g), "r"(srcsize));
}
__device__ __forceinline__ void cpcommit() {
    asm volatile("cp.async.commit_group;" ::: "memory");
}
template <int N>
__device__ __forceinline__ void cpwait() {
    asm volatile("cp.async.wait_group %0;" :: "n"(N) : "memory");
}
__device__ __forceinline__ void ldsm4(uint32_t* r, uint32_t addr) {
    asm volatile("ldmatrix.sync.aligned.m8n8.x4.shared.b16 {%0,%1,%2,%3}, [%4];"
                 : "=r"(r[0]), "=r"(r[1]), "=r"(r[2]), "=r"(r[3]) : "r"(addr));
}
__device__ __forceinline__ void mma16816(float* c, const uint32_t* a, const uint32_t* b) {
    asm volatile(
        "mma.sync.aligned.m16n8k16.row.col.f32.bf16.bf16.f32 "
        "{%0,%1,%2,%3},{%4,%5,%6,%7},{%8,%9},{%0,%1,%2,%3};"
        : "+f"(c[0]), "+f"(c[1]), "+f"(c[2]), "+f"(c[3])
        : "r"(a[0]), "r"(a[1]), "r"(a[2]), "r"(a[3]), "r"(b[0]), "r"(b[1]));
}
__device__ __forceinline__ void mma_tf32(float* d, const uint32_t* a, const uint32_t* b) {
    asm volatile(
        "mma.sync.aligned.m16n8k8.row.col.f32.tf32.tf32.f32 "
        "{%0,%1,%2,%3},{%4,%5,%6,%7},{%8,%9},{%0,%1,%2,%3};"
        : "+f"(d[0]), "+f"(d[1]), "+f"(d[2]), "+f"(d[3])
        : "r"(a[0]), "r"(a[1]), "r"(a[2]), "r"(a[3]), "r"(b[0]), "r"(b[1]));
}
__device__ __forceinline__ uint32_t f2tf(float x) {
    uint32_t r; asm("cvt.rna.tf32.f32 %0, %1;" : "=r"(r) : "f"(x)); return r;
}

// ------------------- fp32 -> bf16 hi/lo split --------------------------------
__global__ void split_k(const float* __restrict__ s, __nv_bfloat16* __restrict__ hi,
                        __nv_bfloat16* __restrict__ lo, int n4)
{
    int i = blockIdx.x * 256 + threadIdx.x;
    if (i >= n4) return;
    float4 v = ((const float4*)s)[i];
    __nv_bfloat16 h0 = __float2bfloat16(v.x), h1 = __float2bfloat16(v.y);
    __nv_bfloat16 h2 = __float2bfloat16(v.z), h3 = __float2bfloat16(v.w);
    __nv_bfloat162* H = (__nv_bfloat162*)hi;
    __nv_bfloat162* L = (__nv_bfloat162*)lo;
    H[i*2+0] = __nv_bfloat162(h0, h1);
    H[i*2+1] = __nv_bfloat162(h2, h3);
    L[i*2+0] = __nv_bfloat162(__float2bfloat16(v.x - __bfloat162float(h0)),
                              __float2bfloat16(v.y - __bfloat162float(h1)));
    L[i*2+1] = __nv_bfloat162(__float2bfloat16(v.z - __bfloat162float(h2)),
                              __float2bfloat16(v.w - __bfloat162float(h3)));
}

// ------------------- HMMA bf16x3 GEMM: C[M,N] = A[M,K] @ B[N,K]^T ------------
// (EXACT round-3/7 configuration — proven fastest; FROZEN.)
#define HBM 128
#define HBN 128
#define HBK 64
#define HLD 72
#define HMATB (128*HLD*2)
#define HSTAGEB (4*HMATB)

__global__ __launch_bounds__(512) void hgemm3(
    int M, int N, int K,
    const __nv_bfloat16* __restrict__ Ah, const __nv_bfloat16* __restrict__ Al,
    const __nv_bfloat16* __restrict__ Bh, const __nv_bfloat16* __restrict__ Bl,
    float* __restrict__ C)
{
    extern __shared__ char smem[];
    const int tid = threadIdx.x;
    const int lane = tid & 31, wid = tid >> 5;
    const int wm = wid & 3, wn = wid >> 2;
    const int bm = blockIdx.y * HBM, bn = blockIdx.x * HBN;
    const uint32_t sbase = s2u(smem);

    const int arow = lane & 15, akoff = (lane >> 4) << 3;
    const int bnl = (lane & 7) + ((lane >> 4) << 3);
    const int bkl = ((lane >> 3) & 1) << 3;

    float acc[2][4][4];
    #pragma unroll
    for (int mt = 0; mt < 2; mt++)
        #pragma unroll
        for (int nt = 0; nt < 4; nt++)
            #pragma unroll
            for (int i = 0; i < 4; i++) acc[mt][nt][i] = 0.f;

    const int nk = K / HBK;

    auto load_stage = [&](int st, int k0) {
        uint32_t sb = sbase + st * HSTAGEB;
        #pragma unroll
        for (int i = 0; i < 2; i++) {
            int chunk = tid + i * 512;
            int row = chunk >> 3, c = chunk & 7;
            uint32_t so = (uint32_t)(row * HLD + c * 8) * 2;
            size_t ga = (size_t)(bm + row) * K + k0 + c * 8;
            cpasync16(sb + so,             Ah + ga, 16);
            cpasync16(sb + HMATB + so,     Al + ga, 16);
            int brow = bn + row;
            int sz = (brow < N) ? 16 : 0;
            int bcl = (brow < N) ? brow : 0;
            size_t gb = (size_t)bcl * K + k0 + c * 8;
            cpasync16(sb + 2*HMATB + so,   Bh + gb, sz);
            cpasync16(sb + 3*HMATB + so,   Bl + gb, sz);
        }
        cpcommit();
    };

    load_stage(0, 0);

    for (int kt = 0; kt < nk; ++kt) {
        if (kt + 1 < nk) {
            load_stage((kt + 1) & 1, (kt + 1) * HBK);
            cpwait<1>();
        } else {
            cpwait<0>();
        }
        __syncthreads();

        uint32_t sb = sbase + (kt & 1) * HSTAGEB;
        uint32_t sAh = sb, sAl = sb + HMATB, sBh = sb + 2*HMATB, sBl = sb + 3*HMATB;

        #pragma unroll
        for (int kh = 0; kh < 4; kh++) {
            int k = kh * 16;
            uint32_t bfh[2][4], bfl[2][4];
            #pragma unroll
            for (int ntp = 0; ntp < 2; ntp++) {
                uint32_t off = (uint32_t)((wn * 32 + ntp * 16 + bnl) * HLD + k + bkl) * 2;
                ldsm4(bfh[ntp], sBh + off);
                ldsm4(bfl[ntp], sBl + off);
            }
            #pragma unroll
            for (int mt = 0; mt < 2; mt++) {
                uint32_t aoff = (uint32_t)((wm * 32 + mt * 16 + arow) * HLD + k + akoff) * 2;
                uint32_t af[4];
                ldsm4(af, sAh + aoff);
                #pragma unroll
                for (int nt = 0; nt < 4; nt++)
                    mma16816(acc[mt][nt], af, &bfh[nt >> 1][(nt & 1) * 2]);
                #pragma unroll
                for (int nt = 0; nt < 4; nt++)
                    mma16816(acc[mt][nt], af, &bfl[nt >> 1][(nt & 1) * 2]);
                ldsm4(af, sAl + aoff);
                #pragma unroll
                for (int nt = 0; nt < 4; nt++)
                    mma16816(acc[mt][nt], af, &bfh[nt >> 1][(nt & 1) * 2]);
            }
        }
        __syncthreads();
    }

    #pragma unroll
    for (int mt = 0; mt < 2; mt++) {
        int row0 = bm + wm * 32 + mt * 16 + (lane >> 2);
        #pragma unroll
        for (int nt = 0; nt < 4; nt++) {
            int col = bn + wn * 32 + nt * 8 + (lane & 3) * 2;
            if (col < N) {
                *(float2*)&C[(size_t)row0 * N + col] =
                    make_float2(acc[mt][nt][0], acc[mt][nt][1]);
                *(float2*)&C[(size_t)(row0 + 8) * N + col] =
                    make_float2(acc[mt][nt][2], acc[mt][nt][3]);
            }
        }
    }
}

// ------------------- depthwise causal conv (k=4) + silu ----------------------
__global__ void conv_silu_k(const float* __restrict__ cw, const float* __restrict__ cb)
{
    int idx = blockIdx.x * 256 + threadIdx.x;
    const int total = BB * LL * CONVDIM;
    if (idx >= total) return;
    int ch = idx % CONVDIM;
    int bl = idx / CONVDIM;
    int l = bl % LL, b = bl / LL;
    float acc = cb[ch];
    #pragma unroll
    for (int k = 0; k < 4; k++) {
        int ll = l - 3 + k;
        if (ll >= 0)
            acc += g_zx[(size_t)(b * LL + ll) * DPROJ + DIN + ch] * cw[ch * 4 + k];
    }
    g_xbc[idx] = acc / (1.f + __expf(-acc));
}

// ------------------- per-chunk cumsum of dA (fused softplus + warp scan) -----
__global__ void cumsum_k(const float* __restrict__ A_log, const float* __restrict__ dt_bias)
{
    int bch = blockIdx.x;            // bc*NH + h
    int h = bch & 31, bc = bch >> 5;
    int b = bc / NCH, c = bc % NCH;
    int t = threadIdx.x;             // 32
    float Ah = -__expf(A_log[h]);
    float bias = dt_bias[h];
    size_t row0 = (size_t)(b * LL + c * CHUNK) + t * 8;
    float v[8];
    #pragma unroll
    for (int j = 0; j < 8; j++) {
        float x = g_zx[(row0 + j) * DPROJ + DIN + CONVDIM + h] + bias;
        float sp = (x > 20.f) ? x : log1pf(__expf(x));
        g_dt[(row0 + j) * NH + h] = sp;
        v[j] = sp * Ah;
    }
    float loc = 0.f;
    #pragma unroll
    for (int j = 0; j < 8; j++) { loc += v[j]; v[j] = loc; }
    float pre = loc;
    #pragma unroll
    for (int o = 1; o < 32; o <<= 1) {
        float nv = __shfl_up_sync(0xffffffffu, pre, o);
        if (t >= o) pre += nv;
    }
    pre -= loc;   // exclusive prefix
    #pragma unroll
    for (int j = 0; j < 8; j++) g_a[(bc * CHUNK + t * 8 + j) * NH + h] = pre + v[j];
    if (t == 31) g_alast[bc * NH + h] = pre + loc;
}

// ------------------- scores = C @ B^T per chunk (lower tiles only) -----------
__global__ __launch_bounds__(256) void scores_k()
{
    int jt = blockIdx.x, it = blockIdx.y, bc = blockIdx.z;
    if (jt > it) return;
    int b = bc / NCH, c = bc % NCH;
    __shared__ float CtT[64][65];
    __shared__ float BtT[64][65];
    int tid = threadIdx.x;
    for (int t = tid; t < 64 * 64; t += 256) {
        int r = t >> 6, n = t & 63;
        int rowC = b * LL + c * CHUNK + it * 64 + r;
        int rowB = b * LL + c * CHUNK + jt * 64 + r;
        CtT[n][r] = g_xbc[(size_t)rowC * CONVDIM + DIN + DS + n];
        BtT[n][r] = g_xbc[(size_t)rowB * CONVDIM + DIN + n];
    }
    __syncthreads();
    int ty = tid >> 4, tx = tid & 15;
    float acc[4][4];
    #pragma unroll
    for (int i = 0; i < 4; i++)
        #pragma unroll
        for (int j = 0; j < 4; j++) acc[i][j] = 0.f;
    for (int n = 0; n < 64; n++) {
        float a[4], w[4];
        #pragma unroll
        for (int i = 0; i < 4; i++) a[i] = CtT[n][ty * 4 + i];
        #pragma unroll
        for (int j = 0; j < 4; j++) w[j] = BtT[n][tx * 4 + j];
        #pragma unroll
        for (int i = 0; i < 4; i++)
            #pragma unroll
            for (int j = 0; j < 4; j++) acc[i][j] += a[i] * w[j];
    }
    #pragma unroll
    for (int i = 0; i < 4; i++)
        #pragma unroll
        for (int j = 0; j < 4; j++)
            g_scores[((size_t)bc << 16) + (it * 64 + ty * 4 + i) * 256 + jt * 64 + tx * 4 + j] = acc[i][j];
}

// ------------- per-chunk states[h,p,n] = X^T @ Bco  (tf32 MMA) ---------------
// D[128,64] = A[128,256] @ B[64,256]^T with A[p][q]=X[q][p], B[n][q]=Bco[q][n].
// 8 warps = 4m x 2n, warp tile 32x32, m16n8k8 tf32, hand-loaded fragments.
__global__ __launch_bounds__(256) void states_k()
{
    int bch = blockIdx.x;              // bc*NH + h
    int h = bch % NH, bc = bch / NH;
    int b = bc / NCH, c = bc % NCH;
    __shared__ float sh[6688];
    float* Xs   = sh;                  // 32 x 136 (q-major, p cols)
    float* Bs   = sh + 4352;           // 32 x 72  (q-major, n cols)
    float* coef = sh + 6656;           // 32
    int tid = threadIdx.x;
    const int lane = tid & 31, wid = tid >> 5;
    const int gid = lane >> 2, tig = lane & 3;
    const int wm = wid & 3, wn = wid >> 2;    // 4m x 2n
    float alast = g_alast[bc * NH + h];
    float acc[2][4][4];
    #pragma unroll
    for (int mt = 0; mt < 2; mt++)
        #pragma unroll
        for (int nt = 0; nt < 4; nt++)
            #pragma unroll
            for (int i = 0; i < 4; i++) acc[mt][nt][i] = 0.f;

    for (int q0 = 0; q0 < CHUNK; q0 += 32) {
        __syncthreads();
        if (tid < 32) {
            int gq = q0 + tid;
            float aq = g_a[(bc * CHUNK + gq) * NH + h];
            float dtq = g_dt[(size_t)(b * LL + c * CHUNK + gq) * NH + h];
            coef[tid] = dtq * __expf(alast - aq);
        }
        #pragma unroll
        for (int t = 0; t < 16; t++) {
            int idx = tid + t * 256;
            int q = idx >> 7, p = idx & 127;
            Xs[q * 136 + p] = g_xbc[(size_t)(b * LL + c * CHUNK + q0 + q) * CONVDIM + h * HD + p];
        }
        __syncthreads();
        #pragma unroll
        for (int t = 0; t < 8; t++) {
            int idx = tid + t * 256;
            int q = idx >> 6, n = idx & 63;
            Bs[q * 72 + n] = g_xbc[(size_t)(b * LL + c * CHUNK + q0 + q) * CONVDIM + DIN + n] * coef[q];
        }
        __syncthreads();
        #pragma unroll
        for (int ks = 0; ks < 4; ks++) {
            int k8 = ks * 8;
            uint32_t bfr[4][2];
            #pragma unroll
            for (int ntf = 0; ntf < 4; ntf++) {
                int nb = wn * 32 + ntf * 8 + gid;
                bfr[ntf][0] = f2tf(Bs[(k8 + tig)     * 72 + nb]);
                bfr[ntf][1] = f2tf(Bs[(k8 + tig + 4) * 72 + nb]);
            }
            #pragma unroll
            for (int mt = 0; mt < 2; mt++) {
                int r0 = wm * 32 + mt * 16 + gid;
                uint32_t afr[4];
                afr[0] = f2tf(Xs[(k8 + tig)     * 136 + r0]);
                afr[1] = f2tf(Xs[(k8 + tig)     * 136 + r0 + 8]);
                afr[2] = f2tf(Xs[(k8 + tig + 4) * 136 + r0]);
                afr[3] = f2tf(Xs[(k8 + tig + 4) * 136 + r0 + 8]);
                #pragma unroll
                for (int ntf = 0; ntf < 4; ntf++)
                    mma_tf32(acc[mt][ntf], afr, bfr[ntf]);
            }
        }
    }
    size_t base = (size_t)bch * HD * DS;
    #pragma unroll
    for (int mt = 0; mt < 2; mt++)
        #pragma unroll
        for (int hf = 0; hf < 2; hf++) {
            int p = wm * 32 + mt * 16 + hf * 8 + gid;
            #pragma unroll
            for (int ntf = 0; ntf < 4; ntf++) {
                int n = wn * 32 + ntf * 8 + 2 * tig;
                *(float2*)&g_states[base + (size_t)p * DS + n] =
                    make_float2(acc[mt][ntf][hf * 2], acc[mt][ntf][hf * 2 + 1]);
            }
        }
}

// ------------------- sequential inter-chunk scan (split over 16 slices) ------
__global__ void scan_k()
{
    int bh = blockIdx.x;            // b*NH + h
    int b = bh >> 5, h = bh & 31;
    int e = blockIdx.y * 512 + threadIdx.x;   // element in HD*DS plane
    float s = 0.f;
    for (int c = 0; c < NCH; c++) {
        int bc = b * NCH + c;
        float dec = __expf(g_alast[bc * NH + h]);
        size_t base = (size_t)(bc * NH + h) * HD * DS;
        g_prev[base + e] = s;
        s = s * dec + g_states[base + e];
    }
}

// ------ y = intra + inter + D*x (tf32 MMA) + fused gate + per-head RMS -------
__global__ __launch_bounds__(256) void ych_k(const float* __restrict__ D_skip,
                                             const float* __restrict__ norm_w)
{
    int it = blockIdx.x;   // 0..3 (64-row tile)
    int h  = blockIdx.y;   // 0..31
    int bc = blockIdx.z;   // 0..31
    int b = bc / NCH, c = bc % NCH;
    __shared__ float sh[9088];
    float* ai    = sh;            // 64
    float* er    = sh + 64;       // 64
    float* Ab    = sh + 128;      // 4352: Wt[64][36] (p1) / Ct[64][68] (p2)
    float* Bb    = sh + 4480;     // 4352: Xt[32][136] (p1) / prevT[32][136] (p2)
    float* ssbuf = sh + 8832;     // 64*4
    int tid = threadIdx.x;
    const int lane = tid & 31, wid = tid >> 5;
    const int gid = lane >> 2, tig = lane & 3;
    const int wm = wid >> 2, wn = wid & 3;     // 2m x 4n
    int row0 = b * LL + c * CHUNK;
    float aref = g_a[(bc * CHUNK + it * 64) * NH + h];
    if (tid < 64) {
        float av = g_a[(bc * CHUNK + it * 64 + tid) * NH + h];
        ai[tid] = av;
        er[tid] = __expf(av - aref);
    }
    float accA[2][4][4], accB[2][4][4];
    #pragma unroll
    for (int mt = 0; mt < 2; mt++)
        #pragma unroll
        for (int nt = 0; nt < 4; nt++)
            #pragma unroll
            for (int i = 0; i < 4; i++) { accA[mt][nt][i] = 0.f; accB[mt][nt][i] = 0.f; }
    __syncthreads();

    // ================== phase 1: intra (K tiles of 32) ==================
    int jtmax = 2 * it + 1;
    for (int jt = 0; jt <= jtmax; jt++) {
        int j0 = jt * 32;
        if (jt < 2 * it) {
            int j = tid & 31;
            int gj = j0 + j;
            float ec = __expf(aref - g_a[(bc * CHUNK + gj) * NH + h]) *
                       g_dt[(size_t)(row0 + gj) * NH + h];
            #pragma unroll
            for (int t = 0; t < 8; t++) {
                int i = (tid >> 5) + t * 8;
                int gi = it * 64 + i;
                Ab[i * 36 + j] =
                    g_scores[((size_t)bc << 16) + gi * 256 + gj] * er[i] * ec;
            }
        } else {
            #pragma unroll
            for (int t = 0; t < 8; t++) {
                int idx = tid + t * 256;
                int i = idx >> 5, j = idx & 31;
                int gi = it * 64 + i, gj = j0 + j;
                float w = 0.f;
                if (gj <= gi) {
                    float aj = g_a[(bc * CHUNK + gj) * NH + h];
                    float dtj = g_dt[(size_t)(row0 + gj) * NH + h];
                    w = g_scores[((size_t)bc << 16) + gi * 256 + gj] * __expf(ai[i] - aj) * dtj;
                }
                Ab[i * 36 + j] = w;
            }
        }
        #pragma unroll
        for (int t = 0; t < 16; t++) {
            int idx = tid + t * 256;
            int j = idx >> 7, p = idx & 127;
            Bb[j * 136 + p] = g_xbc[(size_t)(row0 + j0 + j) * CONVDIM + h * HD + p];
        }
        __syncthreads();
        #pragma unroll
        for (int ks = 0; ks < 4; ks++) {
            uint32_t bfr[4][2];
            #pragma unroll
            for (int ntf = 0; ntf < 4; ntf++) {
                bfr[ntf][0] = f2tf(Bb[(ks*8 + tig)     * 136 + wn*32 + ntf*8 + gid]);
                bfr[ntf][1] = f2tf(Bb[(ks*8 + tig + 4) * 136 + wn*32 + ntf*8 + gid]);
            }
            #pragma unroll
            for (int mt = 0; mt < 2; mt++) {
                int r0 = wm*32 + mt*16 + gid;
                uint32_t afr[4];
                afr[0] = f2tf(Ab[ r0      * 36 + ks*8 + tig]);
                afr[1] = f2tf(Ab[(r0 + 8) * 36 + ks*8 + tig]);
                afr[2] = f2tf(Ab[ r0      * 36 + ks*8 + tig + 4]);
                afr[3] = f2tf(Ab[(r0 + 8) * 36 + ks*8 + tig + 4]);
                #pragma unroll
                for (int ntf = 0; ntf < 4; ntf++)
                    mma_tf32(accA[mt][ntf], afr, bfr[ntf]);
            }
        }
        __syncthreads();
    }

    // ================== phase 2: inter (K = 64, 2 tiles) ==================
    #pragma unroll
    for (int t = 0; t < 16; t++) {
        int idx = tid + t * 256;
        int i = idx >> 6, n = idx & 63;
        Ab[i * 68 + n] = g_xbc[(size_t)(row0 + it * 64 + i) * CONVDIM + DIN + DS + n];
    }
    size_t pbase = (size_t)(bc * NH + h) * HD * DS;
    for (int nt = 0; nt < 2; nt++) {
        int n0 = nt * 32;
        #pragma unroll
        for (int t = 0; t < 16; t++) {
            int idx = tid + t * 256;
            int p = idx >> 5, n = idx & 31;
            Bb[n * 136 + p] = g_prev[pbase + (size_t)p * DS + n0 + n];
        }
        __syncthreads();
        #pragma unroll
        for (int ks = 0; ks < 4; ks++) {
            uint32_t bfr[4][2];
            #pragma unroll
            for (int ntf = 0; ntf < 4; ntf++) {
                bfr[ntf][0] = f2tf(Bb[(ks*8 + tig)     * 136 + wn*32 + ntf*8 + gid]);
                bfr[ntf][1] = f2tf(Bb[(ks*8 + tig + 4) * 136 + wn*32 + ntf*8 + gid]);
            }
            #pragma unroll
            for (int mt = 0; mt < 2; mt++) {
                int r0 = wm*32 + mt*16 + gid;
                uint32_t afr[4];
                afr[0] = f2tf(Ab[ r0      * 68 + n0 + ks*8 + tig]);
                afr[1] = f2tf(Ab[(r0 + 8) * 68 + n0 + ks*8 + tig]);
                afr[2] = f2tf(Ab[ r0      * 68 + n0 + ks*8 + tig + 4]);
                afr[3] = f2tf(Ab[(r0 + 8) * 68 + n0 + ks*8 + tig + 4]);
                #pragma unroll
                for (int ntf = 0; ntf < 4; ntf++)
                    mma_tf32(accB[mt][ntf], afr, bfr[ntf]);
            }
        }
        __syncthreads();
    }

    // ====== epilogue: combine + D skip + gate + RMS (mma layout) ======
    float Dh = D_skip[h];
    #pragma unroll
    for (int mt = 0; mt < 2; mt++) {
        #pragma unroll
        for (int hf = 0; hf < 2; hf++) {
            int rl = wm*32 + mt*16 + hf*8 + gid;
            int gi = it * 64 + rl;
            float ea = __expf(ai[rl]);
            float ss = 0.f;
            #pragma unroll
            for (int ntf = 0; ntf < 4; ntf++) {
                int col = wn*32 + ntf*8 + 2*tig;
                float2 xv = *(const float2*)&g_xbc[(size_t)(row0 + gi) * CONVDIM + h * HD + col];
                float2 zv = *(const float2*)&g_zx[(size_t)(row0 + gi) * DPROJ + h * HD + col];
                float o0 = accA[mt][ntf][hf*2+0] + ea * accB[mt][ntf][hf*2+0] + Dh * xv.x;
                float o1 = accA[mt][ntf][hf*2+1] + ea * accB[mt][ntf][hf*2+1] + Dh * xv.y;
                float v0 = o0 / (1.f + __expf(-zv.x));
                float v1 = o1 / (1.f + __expf(-zv.y));
                accA[mt][ntf][hf*2+0] = v0;
                accA[mt][ntf][hf*2+1] = v1;
                ss += v0 * v0 + v1 * v1;
            }
            ss += __shfl_xor_sync(0xffffffffu, ss, 1);
            ss += __shfl_xor_sync(0xffffffffu, ss, 2);
            if (tig == 0) ssbuf[rl * 4 + wn] = ss;
        }
    }
    __syncthreads();
    #pragma unroll
    for (int mt = 0; mt < 2; mt++) {
        #pragma unroll
        for (int hf = 0; hf < 2; hf++) {
            int rl = wm*32 + mt*16 + hf*8 + gid;
            int gi = it * 64 + rl;
            float tot = ssbuf[rl*4+0] + ssbuf[rl*4+1] + ssbuf[rl*4+2] + ssbuf[rl*4+3];
            float inv = rsqrtf(tot * (1.f / HD) + 1e-6f);
            #pragma unroll
            for (int ntf = 0; ntf < 4; ntf++) {
                int col = wn*32 + ntf*8 + 2*tig;
                float2 nw = *(const float2*)&norm_w[h * HD + col];
                float r0 = accA[mt][ntf][hf*2+0] * inv * nw.x;
                float r1 = accA[mt][ntf][hf*2+1] * inv * nw.y;
                size_t oi = (size_t)(row0 + gi) * DIN + h * HD + col;
                __nv_bfloat16 h0 = __float2bfloat16(r0), h1 = __float2bfloat16(r1);
                *(__nv_bfloat162*)&g_ynh[oi] = __nv_bfloat162(h0, h1);
                *(__nv_bfloat162*)&g_ynl[oi] = __nv_bfloat162(
                    __float2bfloat16(r0 - __bfloat162float(h0)),
                    __float2bfloat16(r1 - __bfloat162float(h1)));
            }
        }
    }
}

// ------------------- launch ---------------------------------------------------
extern "C" void kernel_launch(void* const* d_in, const int* in_sizes, int n_in,
                              void* d_out, int out_size)
{
    const float* u         = (const float*)d_in[0];
    const float* in_proj_w = (const float*)d_in[1];
    const float* conv_w    = (const float*)d_in[2];
    const float* conv_b    = (const float*)d_in[3];
    const float* A_log     = (const float*)d_in[4];
    const float* dt_bias   = (const float*)d_in[5];
    const float* D_skip    = (const float*)d_in[6];
    const float* norm_w    = (const float*)d_in[7];
    const float* o_proj_w  = (const float*)d_in[8];
    float* out = (float*)d_out;

    float* zx = nullptr;
    cudaGetSymbolAddress((void**)&zx, g_zx);
    __nv_bfloat16 *uh, *ul, *w1h, *w1l, *w2h, *w2l, *ynh, *ynl;
    cudaGetSymbolAddress((void**)&uh,  g_uh);
    cudaGetSymbolAddress((void**)&ul,  g_ul);
    cudaGetSymbolAddress((void**)&w1h, g_w1h);
    cudaGetSymbolAddress((void**)&w1l, g_w1l);
    cudaGetSymbolAddress((void**)&w2h, g_w2h);
    cudaGetSymbolAddress((void**)&w2l, g_w2l);
    cudaGetSymbolAddress((void**)&ynh, g_ynh);
    cudaGetSymbolAddress((void**)&ynl, g_ynl);

    const int SMEM_GEMM = 2 * HSTAGEB;   // 147456
    cudaFuncSetAttribute(hgemm3, cudaFuncAttributeMaxDynamicSharedMemorySize, SMEM_GEMM);

    const int M = BB * LL;   // 8192

    // 0) hi/lo splits of GEMM inputs
    {
        int n4;
        n4 = (M * EMBED) / 4;
        split_k<<<(n4 + 255) / 256, 256>>>(u, uh, ul, n4);
        n4 = (DPROJ * EMBED) / 4;
        split_k<<<(n4 + 255) / 256, 256>>>(in_proj_w, w1h, w1l, n4);
        n4 = (EMBED * DIN) / 4;
        split_k<<<(n4 + 255) / 256, 256>>>(o_proj_w, w2h, w2l, n4);
    }
    // 1) in_proj: zx = u @ W1^T  (HMMA bf16x3)
    hgemm3<<<dim3((DPROJ + HBN - 1) / HBN, M / HBM), 512, SMEM_GEMM>>>(
        M, DPROJ, EMBED, uh, ul, w1h, w1l, zx);
    // 2) causal depthwise conv + silu
    conv_silu_k<<<(BB * LL * CONVDIM + 255) / 256, 256>>>(conv_w, conv_b);
    // 3) fused dt softplus + per-chunk cumsum (parallel scan)
    cumsum_k<<<NBC * NH, 32>>>(A_log, dt_bias);
    // 4) chunk attention scores (lower tiles)
    scores_k<<<dim3(4, 4, NBC), 256>>>();
    // 5) per-chunk end states (tf32 MMA)
    states_k<<<NBC * NH, 256>>>();
    // 6) inter-chunk scan (16 slices per (b,h))
    scan_k<<<dim3(BB * NH, 16), 512>>>();
    // 7) y: tf32 MMA intra+inter, fused gate + RMS norm (writes bf16 hi/lo)
    ych_k<<<dim3(4, NH, NBC), 256>>>(D_skip, norm_w);
    // 8) o_proj: out = yn @ W2^T  (HMMA bf16x3)
    hgemm3<<<dim3(EMBED / HBN, M / HBM), 512, SMEM_GEMM>>>(
        M, EMBED, DIN, ynh, ynl, w2h, w2l, out);
}

// round 13
// speedup vs baseline: 1.2272x; 1.0190x over previous
#include <cuda_runtime.h>
#include <cuda_bf16.h>
#include <cstdint>

#define BB 2
#define LL 4096
#define EMBED 2048
#define DIN 4096
#define NH 32
#define HD 128
#define DS 64
#define CONVDIM 4224   // DIN + 2*DS
#define DPROJ 8352     // 2*DIN + 2*DS + NH
#define CHUNK 256
#define NCH 16         // LL / CHUNK
#define NBC (BB*NCH)   // 32

// ------------------- scratch (device globals; no cudaMalloc allowed) ---------
__device__ float g_zx[(size_t)BB*LL*DPROJ];        // in_proj output
__device__ float g_xbc[(size_t)BB*LL*CONVDIM];     // conv+silu output
__device__ float g_dt[BB*LL*NH];                   // softplus(dt)
__device__ float g_a[NBC*CHUNK*NH];                // cumsum(dA) per chunk
__device__ float g_alast[NBC*NH];
__device__ float g_scores[(size_t)NBC*CHUNK*CHUNK];
__device__ float g_states[(size_t)NBC*NH*HD*DS];   // [b,c,h,p,n]
__device__ float g_prev[(size_t)NBC*NH*HD*DS];     // state entering chunk c

// bf16 hi/lo split buffers
__device__ __nv_bfloat16 g_uh[(size_t)BB*LL*EMBED];
__device__ __nv_bfloat16 g_ul[(size_t)BB*LL*EMBED];
__device__ __nv_bfloat16 g_w1h[(size_t)DPROJ*EMBED];
__device__ __nv_bfloat16 g_w1l[(size_t)DPROJ*EMBED];
__device__ __nv_bfloat16 g_w2h[(size_t)EMBED*DIN];
__device__ __nv_bfloat16 g_w2l[(size_t)EMBED*DIN];
__device__ __nv_bfloat16 g_ynh[(size_t)BB*LL*DIN];
__device__ __nv_bfloat16 g_ynl[(size_t)BB*LL*DIN];

// ------------------- PTX helpers (sm_80-era: valid on base sm_103 target) ----
__device__ __forceinline__ uint32_t s2u(const void* p) {
    uint32_t a;
    asm("{ .reg .u64 t; cvta.to.shared.u64 t, %1; cvt.u32.u64 %0, t; }" : "=r"(a) : "l"(p));
    return a;
}
__device__ __forceinline__ void cpasync16(uint32_t s, const void* g, int srcsize) {
    asm volatile("cp.async.ca.shared.global [%0], [%1], 16, %2;"
                 :: "r"(s), "l"(g), "r"(srcsize));
}
__device__ __forceinline__ void cpcommit() {
    asm volatile("cp.async.commit_group;" ::: "memory");
}
template <int N>
__device__ __forceinline__ void cpwait() {
    asm volatile("cp.async.wait_group %0;" :: "n"(N) : "memory");
}
__device__ __forceinline__ void ldsm4(uint32_t* r, uint32_t addr) {
    asm volatile("ldmatrix.sync.aligned.m8n8.x4.shared.b16 {%0,%1,%2,%3}, [%4];"
                 : "=r"(r[0]), "=r"(r[1]), "=r"(r[2]), "=r"(r[3]) : "r"(addr));
}
__device__ __forceinline__ void mma16816(float* c, const uint32_t* a, const uint32_t* b) {
    asm volatile(
        "mma.sync.aligned.m16n8k16.row.col.f32.bf16.bf16.f32 "
        "{%0,%1,%2,%3},{%4,%5,%6,%7},{%8,%9},{%0,%1,%2,%3};"
        : "+f"(c[0]), "+f"(c[1]), "+f"(c[2]), "+f"(c[3])
        : "r"(a[0]), "r"(a[1]), "r"(a[2]), "r"(a[3]), "r"(b[0]), "r"(b[1]));
}
__device__ __forceinline__ void mma_tf32(float* d, const uint32_t* a, const uint32_t* b) {
    asm volatile(
        "mma.sync.aligned.m16n8k8.row.col.f32.tf32.tf32.f32 "
        "{%0,%1,%2,%3},{%4,%5,%6,%7},{%8,%9},{%0,%1,%2,%3};"
        : "+f"(d[0]), "+f"(d[1]), "+f"(d[2]), "+f"(d[3])
        : "r"(a[0]), "r"(a[1]), "r"(a[2]), "r"(a[3]), "r"(b[0]), "r"(b[1]));
}
__device__ __forceinline__ uint32_t f2tf(float x) {
    uint32_t r; asm("cvt.rna.tf32.f32 %0, %1;" : "=r"(r) : "f"(x)); return r;
}

// ------------------- fp32 -> bf16 hi/lo split --------------------------------
__global__ void split_k(const float* __restrict__ s, __nv_bfloat16* __restrict__ hi,
                        __nv_bfloat16* __restrict__ lo, int n4)
{
    int i = blockIdx.x * 256 + threadIdx.x;
    if (i >= n4) return;
    float4 v = ((const float4*)s)[i];
    __nv_bfloat16 h0 = __float2bfloat16(v.x), h1 = __float2bfloat16(v.y);
    __nv_bfloat16 h2 = __float2bfloat16(v.z), h3 = __float2bfloat16(v.w);
    __nv_bfloat162* H = (__nv_bfloat162*)hi;
    __nv_bfloat162* L = (__nv_bfloat162*)lo;
    H[i*2+0] = __nv_bfloat162(h0, h1);
    H[i*2+1] = __nv_bfloat162(h2, h3);
    L[i*2+0] = __nv_bfloat162(__float2bfloat16(v.x - __bfloat162float(h0)),
                              __float2bfloat16(v.y - __bfloat162float(h1)));
    L[i*2+1] = __nv_bfloat162(__float2bfloat16(v.z - __bfloat162float(h2)),
                              __float2bfloat16(v.w - __bfloat162float(h3)));
}

// ------------------- HMMA bf16x3 GEMM: C[M,N] = A[M,K] @ B[N,K]^T ------------
// (EXACT round-3/7 configuration — proven fastest; FROZEN.)
#define HBM 128
#define HBN 128
#define HBK 64
#define HLD 72
#define HMATB (128*HLD*2)
#define HSTAGEB (4*HMATB)

__global__ __launch_bounds__(512) void hgemm3(
    int M, int N, int K,
    const __nv_bfloat16* __restrict__ Ah, const __nv_bfloat16* __restrict__ Al,
    const __nv_bfloat16* __restrict__ Bh, const __nv_bfloat16* __restrict__ Bl,
    float* __restrict__ C)
{
    extern __shared__ char smem[];
    const int tid = threadIdx.x;
    const int lane = tid & 31, wid = tid >> 5;
    const int wm = wid & 3, wn = wid >> 2;
    const int bm = blockIdx.y * HBM, bn = blockIdx.x * HBN;
    const uint32_t sbase = s2u(smem);

    const int arow = lane & 15, akoff = (lane >> 4) << 3;
    const int bnl = (lane & 7) + ((lane >> 4) << 3);
    const int bkl = ((lane >> 3) & 1) << 3;

    float acc[2][4][4];
    #pragma unroll
    for (int mt = 0; mt < 2; mt++)
        #pragma unroll
        for (int nt = 0; nt < 4; nt++)
            #pragma unroll
            for (int i = 0; i < 4; i++) acc[mt][nt][i] = 0.f;

    const int nk = K / HBK;

    auto load_stage = [&](int st, int k0) {
        uint32_t sb = sbase + st * HSTAGEB;
        #pragma unroll
        for (int i = 0; i < 2; i++) {
            int chunk = tid + i * 512;
            int row = chunk >> 3, c = chunk & 7;
            uint32_t so = (uint32_t)(row * HLD + c * 8) * 2;
            size_t ga = (size_t)(bm + row) * K + k0 + c * 8;
            cpasync16(sb + so,             Ah + ga, 16);
            cpasync16(sb + HMATB + so,     Al + ga, 16);
            int brow = bn + row;
            int sz = (brow < N) ? 16 : 0;
            int bcl = (brow < N) ? brow : 0;
            size_t gb = (size_t)bcl * K + k0 + c * 8;
            cpasync16(sb + 2*HMATB + so,   Bh + gb, sz);
            cpasync16(sb + 3*HMATB + so,   Bl + gb, sz);
        }
        cpcommit();
    };

    load_stage(0, 0);

    for (int kt = 0; kt < nk; ++kt) {
        if (kt + 1 < nk) {
            load_stage((kt + 1) & 1, (kt + 1) * HBK);
            cpwait<1>();
        } else {
            cpwait<0>();
        }
        __syncthreads();

        uint32_t sb = sbase + (kt & 1) * HSTAGEB;
        uint32_t sAh = sb, sAl = sb + HMATB, sBh = sb + 2*HMATB, sBl = sb + 3*HMATB;

        #pragma unroll
        for (int kh = 0; kh < 4; kh++) {
            int k = kh * 16;
            uint32_t bfh[2][4], bfl[2][4];
            #pragma unroll
            for (int ntp = 0; ntp < 2; ntp++) {
                uint32_t off = (uint32_t)((wn * 32 + ntp * 16 + bnl) * HLD + k + bkl) * 2;
                ldsm4(bfh[ntp], sBh + off);
                ldsm4(bfl[ntp], sBl + off);
            }
            #pragma unroll
            for (int mt = 0; mt < 2; mt++) {
                uint32_t aoff = (uint32_t)((wm * 32 + mt * 16 + arow) * HLD + k + akoff) * 2;
                uint32_t af[4];
                ldsm4(af, sAh + aoff);
                #pragma unroll
                for (int nt = 0; nt < 4; nt++)
                    mma16816(acc[mt][nt], af, &bfh[nt >> 1][(nt & 1) * 2]);
                #pragma unroll
                for (int nt = 0; nt < 4; nt++)
                    mma16816(acc[mt][nt], af, &bfl[nt >> 1][(nt & 1) * 2]);
                ldsm4(af, sAl + aoff);
                #pragma unroll
                for (int nt = 0; nt < 4; nt++)
                    mma16816(acc[mt][nt], af, &bfh[nt >> 1][(nt & 1) * 2]);
            }
        }
        __syncthreads();
    }

    #pragma unroll
    for (int mt = 0; mt < 2; mt++) {
        int row0 = bm + wm * 32 + mt * 16 + (lane >> 2);
        #pragma unroll
        for (int nt = 0; nt < 4; nt++) {
            int col = bn + wn * 32 + nt * 8 + (lane & 3) * 2;
            if (col < N) {
                *(float2*)&C[(size_t)row0 * N + col] =
                    make_float2(acc[mt][nt][0], acc[mt][nt][1]);
                *(float2*)&C[(size_t)(row0 + 8) * N + col] =
                    make_float2(acc[mt][nt][2], acc[mt][nt][3]);
            }
        }
    }
}

// --------- depthwise causal conv (k=4) + silu, smem-tiled (reads 1x) ---------
// Tile: 64 channels x 128 positions; loads (128+3) x 64 patch once.
__global__ __launch_bounds__(256) void conv_silu_k(const float* __restrict__ cw,
                                                   const float* __restrict__ cb)
{
    int ct = blockIdx.x;           // 0..65  (CONVDIM/64)
    int lt = blockIdx.y;           // 0..31  (LL/128)
    int b  = blockIdx.z;
    int c0 = ct * 64, l0 = lt * 128;
    __shared__ float tile[131][64];
    int tid = threadIdx.x;
    int tc = tid & 63, tg = tid >> 6;   // channel-in-tile, group 0..3
    for (int r = tg; r < 131; r += 4) {
        int l = l0 + r - 3;
        float v = 0.f;
        if (l >= 0) v = g_zx[(size_t)(b * LL + l) * DPROJ + DIN + c0 + tc];
        tile[r][tc] = v;
    }
    __syncthreads();
    int ch = c0 + tc;
    float w0 = cw[ch * 4 + 0], w1 = cw[ch * 4 + 1];
    float w2 = cw[ch * 4 + 2], w3 = cw[ch * 4 + 3];
    float bias = cb[ch];
    #pragma unroll 4
    for (int i = 0; i < 32; i++) {
        int lr = tg * 32 + i;
        float acc = bias + tile[lr][tc] * w0 + tile[lr + 1][tc] * w1
                  + tile[lr + 2][tc] * w2 + tile[lr + 3][tc] * w3;
        g_xbc[(size_t)(b * LL + l0 + lr) * CONVDIM + ch] = acc / (1.f + __expf(-acc));
    }
}

// ------------------- per-chunk cumsum of dA (fused softplus + warp scan) -----
__global__ void cumsum_k(const float* __restrict__ A_log, const float* __restrict__ dt_bias)
{
    int bch = blockIdx.x;            // bc*NH + h
    int h = bch & 31, bc = bch >> 5;
    int b = bc / NCH, c = bc % NCH;
    int t = threadIdx.x;             // 32
    float Ah = -__expf(A_log[h]);
    float bias = dt_bias[h];
    size_t row0 = (size_t)(b * LL + c * CHUNK) + t * 8;
    float v[8];
    #pragma unroll
    for (int j = 0; j < 8; j++) {
        float x = g_zx[(row0 + j) * DPROJ + DIN + CONVDIM + h] + bias;
        float sp = (x > 20.f) ? x : log1pf(__expf(x));
        g_dt[(row0 + j) * NH + h] = sp;
        v[j] = sp * Ah;
    }
    float loc = 0.f;
    #pragma unroll
    for (int j = 0; j < 8; j++) { loc += v[j]; v[j] = loc; }
    float pre = loc;
    #pragma unroll
    for (int o = 1; o < 32; o <<= 1) {
        float nv = __shfl_up_sync(0xffffffffu, pre, o);
        if (t >= o) pre += nv;
    }
    pre -= loc;   // exclusive prefix
    #pragma unroll
    for (int j = 0; j < 8; j++) g_a[(bc * CHUNK + t * 8 + j) * NH + h] = pre + v[j];
    if (t == 31) g_alast[bc * NH + h] = pre + loc;
}

// ---------- scores = C @ B^T per chunk (lower tiles, tf32 MMA) ---------------
// D[64,64] = C[64,64] @ B[64,64]^T; 8 warps = 2m x 4n, warp tile 32x16.
__global__ __launch_bounds__(256) void scores_k()
{
    int jt = blockIdx.x, it = blockIdx.y, bc = blockIdx.z;
    if (jt > it) return;
    int b = bc / NCH, c = bc % NCH;
    __shared__ float CtT[64 * 72];   // [n][r] k-major
    __shared__ float BtT[64 * 72];
    int tid = threadIdx.x;
    const int lane = tid & 31, wid = tid >> 5;
    const int gid = lane >> 2, tig = lane & 3;
    const int wm = wid >> 2, wn = wid & 3;   // 2m x 4n
    for (int t = tid; t < 64 * 64; t += 256) {
        int r = t >> 6, n = t & 63;
        int rowC = b * LL + c * CHUNK + it * 64 + r;
        int rowB = b * LL + c * CHUNK + jt * 64 + r;
        CtT[n * 72 + r] = g_xbc[(size_t)rowC * CONVDIM + DIN + DS + n];
        BtT[n * 72 + r] = g_xbc[(size_t)rowB * CONVDIM + DIN + n];
    }
    __syncthreads();
    float acc[2][2][4];
    #pragma unroll
    for (int mt = 0; mt < 2; mt++)
        #pragma unroll
        for (int nf = 0; nf < 2; nf++)
            #pragma unroll
            for (int i = 0; i < 4; i++) acc[mt][nf][i] = 0.f;
    #pragma unroll
    for (int ks = 0; ks < 8; ks++) {
        int k8 = ks * 8;
        uint32_t bfr[2][2];
        #pragma unroll
        for (int nf = 0; nf < 2; nf++) {
            int col = wn * 16 + nf * 8 + gid;
            bfr[nf][0] = f2tf(BtT[(k8 + tig)     * 72 + col]);
            bfr[nf][1] = f2tf(BtT[(k8 + tig + 4) * 72 + col]);
        }
        #pragma unroll
        for (int mt = 0; mt < 2; mt++) {
            int r0 = wm * 32 + mt * 16 + gid;
            uint32_t afr[4];
            afr[0] = f2tf(CtT[(k8 + tig)     * 72 + r0]);
            afr[1] = f2tf(CtT[(k8 + tig)     * 72 + r0 + 8]);
            afr[2] = f2tf(CtT[(k8 + tig + 4) * 72 + r0]);
            afr[3] = f2tf(CtT[(k8 + tig + 4) * 72 + r0 + 8]);
            #pragma unroll
            for (int nf = 0; nf < 2; nf++)
                mma_tf32(acc[mt][nf], afr, bfr[nf]);
        }
    }
    #pragma unroll
    for (int mt = 0; mt < 2; mt++)
        #pragma unroll
        for (int hf = 0; hf < 2; hf++) {
            int r = wm * 32 + mt * 16 + hf * 8 + gid;
            #pragma unroll
            for (int nf = 0; nf < 2; nf++) {
                int n = wn * 16 + nf * 8 + 2 * tig;
                *(float2*)&g_scores[((size_t)bc << 16) + (it * 64 + r) * 256 + jt * 64 + n] =
                    make_float2(acc[mt][nf][hf * 2], acc[mt][nf][hf * 2 + 1]);
            }
        }
}

// ------------- per-chunk states[h,p,n] = X^T @ Bco  (tf32 MMA) ---------------
__global__ __launch_bounds__(256) void states_k()
{
    int bch = blockIdx.x;              // bc*NH + h
    int h = bch % NH, bc = bch / NH;
    int b = bc / NCH, c = bc % NCH;
    __shared__ float sh[6688];
    float* Xs   = sh;                  // 32 x 136 (q-major, p cols)
    float* Bs   = sh + 4352;           // 32 x 72  (q-major, n cols)
    float* coef = sh + 6656;           // 32
    int tid = threadIdx.x;
    const int lane = tid & 31, wid = tid >> 5;
    const int gid = lane >> 2, tig = lane & 3;
    const int wm = wid & 3, wn = wid >> 2;    // 4m x 2n
    float alast = g_alast[bc * NH + h];
    float acc[2][4][4];
    #pragma unroll
    for (int mt = 0; mt < 2; mt++)
        #pragma unroll
        for (int nt = 0; nt < 4; nt++)
            #pragma unroll
            for (int i = 0; i < 4; i++) acc[mt][nt][i] = 0.f;

    for (int q0 = 0; q0 < CHUNK; q0 += 32) {
        __syncthreads();
        if (tid < 32) {
            int gq = q0 + tid;
            float aq = g_a[(bc * CHUNK + gq) * NH + h];
            float dtq = g_dt[(size_t)(b * LL + c * CHUNK + gq) * NH + h];
            coef[tid] = dtq * __expf(alast - aq);
        }
        #pragma unroll
        for (int t = 0; t < 16; t++) {
            int idx = tid + t * 256;
            int q = idx >> 7, p = idx & 127;
            Xs[q * 136 + p] = g_xbc[(size_t)(b * LL + c * CHUNK + q0 + q) * CONVDIM + h * HD + p];
        }
        __syncthreads();
        #pragma unroll
        for (int t = 0; t < 8; t++) {
            int idx = tid + t * 256;
            int q = idx >> 6, n = idx & 63;
            Bs[q * 72 + n] = g_xbc[(size_t)(b * LL + c * CHUNK + q0 + q) * CONVDIM + DIN + n] * coef[q];
        }
        __syncthreads();
        #pragma unroll
        for (int ks = 0; ks < 4; ks++) {
            int k8 = ks * 8;
            uint32_t bfr[4][2];
            #pragma unroll
            for (int ntf = 0; ntf < 4; ntf++) {
                int nb = wn * 32 + ntf * 8 + gid;
                bfr[ntf][0] = f2tf(Bs[(k8 + tig)     * 72 + nb]);
                bfr[ntf][1] = f2tf(Bs[(k8 + tig + 4) * 72 + nb]);
            }
            #pragma unroll
            for (int mt = 0; mt < 2; mt++) {
                int r0 = wm * 32 + mt * 16 + gid;
                uint32_t afr[4];
                afr[0] = f2tf(Xs[(k8 + tig)     * 136 + r0]);
                afr[1] = f2tf(Xs[(k8 + tig)     * 136 + r0 + 8]);
                afr[2] = f2tf(Xs[(k8 + tig + 4) * 136 + r0]);
                afr[3] = f2tf(Xs[(k8 + tig + 4) * 136 + r0 + 8]);
                #pragma unroll
                for (int ntf = 0; ntf < 4; ntf++)
                    mma_tf32(acc[mt][ntf], afr, bfr[ntf]);
            }
        }
    }
    size_t base = (size_t)bch * HD * DS;
    #pragma unroll
    for (int mt = 0; mt < 2; mt++)
        #pragma unroll
        for (int hf = 0; hf < 2; hf++) {
            int p = wm * 32 + mt * 16 + hf * 8 + gid;
            #pragma unroll
            for (int ntf = 0; ntf < 4; ntf++) {
                int n = wn * 32 + ntf * 8 + 2 * tig;
                *(float2*)&g_states[base + (size_t)p * DS + n] =
                    make_float2(acc[mt][ntf][hf * 2], acc[mt][ntf][hf * 2 + 1]);
            }
        }
}

// ------------------- sequential inter-chunk scan (split over 16 slices) ------
__global__ void scan_k()
{
    int bh = blockIdx.x;            // b*NH + h
    int b = bh >> 5, h = bh & 31;
    int e = blockIdx.y * 512 + threadIdx.x;   // element in HD*DS plane
    float s = 0.f;
    for (int c = 0; c < NCH; c++) {
        int bc = b * NCH + c;
        float dec = __expf(g_alast[bc * NH + h]);
        size_t base = (size_t)(bc * NH + h) * HD * DS;
        g_prev[base + e] = s;
        s = s * dec + g_states[base + e];
    }
}

// ------ y = intra + inter + D*x (tf32 MMA) + fused gate + per-head RMS -------
__global__ __launch_bounds__(256) void ych_k(const float* __restrict__ D_skip,
                                             const float* __restrict__ norm_w)
{
    int it = blockIdx.x;   // 0..3 (64-row tile)
    int h  = blockIdx.y;   // 0..31
    int bc = blockIdx.z;   // 0..31
    int b = bc / NCH, c = bc % NCH;
    __shared__ float sh[9088];
    float* ai    = sh;            // 64
    float* er    = sh + 64;       // 64
    float* Ab    = sh + 128;      // 4352: Wt[64][36] (p1) / Ct[64][68] (p2)
    float* Bb    = sh + 4480;     // 4352: Xt[32][136] (p1) / prevT[32][136] (p2)
    float* ssbuf = sh + 8832;     // 64*4
    int tid = threadIdx.x;
    const int lane = tid & 31, wid = tid >> 5;
    const int gid = lane >> 2, tig = lane & 3;
    const int wm = wid >> 2, wn = wid & 3;     // 2m x 4n
    int row0 = b * LL + c * CHUNK;
    float aref = g_a[(bc * CHUNK + it * 64) * NH + h];
    if (tid < 64) {
        float av = g_a[(bc * CHUNK + it * 64 + tid) * NH + h];
        ai[tid] = av;
        er[tid] = __expf(av - aref);
    }
    float accA[2][4][4], accB[2][4][4];
    #pragma unroll
    for (int mt = 0; mt < 2; mt++)
        #pragma unroll
        for (int nt = 0; nt < 4; nt++)
            #pragma unroll
            for (int i = 0; i < 4; i++) { accA[mt][nt][i] = 0.f; accB[mt][nt][i] = 0.f; }
    __syncthreads();

    // ================== phase 1: intra (K tiles of 32) ==================
    int jtmax = 2 * it + 1;
    for (int jt = 0; jt <= jtmax; jt++) {
        int j0 = jt * 32;
        if (jt < 2 * it) {
            int j = tid & 31;
            int gj = j0 + j;
            float ec = __expf(aref - g_a[(bc * CHUNK + gj) * NH + h]) *
                       g_dt[(size_t)(row0 + gj) * NH + h];
            #pragma unroll
            for (int t = 0; t < 8; t++) {
                int i = (tid >> 5) + t * 8;
                int gi = it * 64 + i;
                Ab[i * 36 + j] =
                    g_scores[((size_t)bc << 16) + gi * 256 + gj] * er[i] * ec;
            }
        } else {
            #pragma unroll
            for (int t = 0; t < 8; t++) {
                int idx = tid + t * 256;
                int i = idx >> 5, j = idx & 31;
                int gi = it * 64 + i, gj = j0 + j;
                float w = 0.f;
                if (gj <= gi) {
                    float aj = g_a[(bc * CHUNK + gj) * NH + h];
                    float dtj = g_dt[(size_t)(row0 + gj) * NH + h];
                    w = g_scores[((size_t)bc << 16) + gi * 256 + gj] * __expf(ai[i] - aj) * dtj;
                }
                Ab[i * 36 + j] = w;
            }
        }
        #pragma unroll
        for (int t = 0; t < 16; t++) {
            int idx = tid + t * 256;
            int j = idx >> 7, p = idx & 127;
            Bb[j * 136 + p] = g_xbc[(size_t)(row0 + j0 + j) * CONVDIM + h * HD + p];
        }
        __syncthreads();
        #pragma unroll
        for (int ks = 0; ks < 4; ks++) {
            uint32_t bfr[4][2];
            #pragma unroll
            for (int ntf = 0; ntf < 4; ntf++) {
                bfr[ntf][0] = f2tf(Bb[(ks*8 + tig)     * 136 + wn*32 + ntf*8 + gid]);
                bfr[ntf][1] = f2tf(Bb[(ks*8 + tig + 4) * 136 + wn*32 + ntf*8 + gid]);
            }
            #pragma unroll
            for (int mt = 0; mt < 2; mt++) {
                int r0 = wm*32 + mt*16 + gid;
                uint32_t afr[4];
                afr[0] = f2tf(Ab[ r0      * 36 + ks*8 + tig]);
                afr[1] = f2tf(Ab[(r0 + 8) * 36 + ks*8 + tig]);
                afr[2] = f2tf(Ab[ r0      * 36 + ks*8 + tig + 4]);
                afr[3] = f2tf(Ab[(r0 + 8) * 36 + ks*8 + tig + 4]);
                #pragma unroll
                for (int ntf = 0; ntf < 4; ntf++)
                    mma_tf32(accA[mt][ntf], afr, bfr[ntf]);
            }
        }
        __syncthreads();
    }

    // ================== phase 2: inter (K = 64, 2 tiles) ==================
    #pragma unroll
    for (int t = 0; t < 16; t++) {
        int idx = tid + t * 256;
        int i = idx >> 6, n = idx & 63;
        Ab[i * 68 + n] = g_xbc[(size_t)(row0 + it * 64 + i) * CONVDIM + DIN + DS + n];
    }
    size_t pbase = (size_t)(bc * NH + h) * HD * DS;
    for (int nt = 0; nt < 2; nt++) {
        int n0 = nt * 32;
        #pragma unroll
        for (int t = 0; t < 16; t++) {
            int idx = tid + t * 256;
            int p = idx >> 5, n = idx & 31;
            Bb[n * 136 + p] = g_prev[pbase + (size_t)p * DS + n0 + n];
        }
        __syncthreads();
        #pragma unroll
        for (int ks = 0; ks < 4; ks++) {
            uint32_t bfr[4][2];
            #pragma unroll
            for (int ntf = 0; ntf < 4; ntf++) {
                bfr[ntf][0] = f2tf(Bb[(ks*8 + tig)     * 136 + wn*32 + ntf*8 + gid]);
                bfr[ntf][1] = f2tf(Bb[(ks*8 + tig + 4) * 136 + wn*32 + ntf*8 + gid]);
            }
            #pragma unroll
            for (int mt = 0; mt < 2; mt++) {
                int r0 = wm*32 + mt*16 + gid;
                uint32_t afr[4];
                afr[0] = f2tf(Ab[ r0      * 68 + n0 + ks*8 + tig]);
                afr[1] = f2tf(Ab[(r0 + 8) * 68 + n0 + ks*8 + tig]);
                afr[2] = f2tf(Ab[ r0      * 68 + n0 + ks*8 + tig + 4]);
                afr[3] = f2tf(Ab[(r0 + 8) * 68 + n0 + ks*8 + tig + 4]);
                #pragma unroll
                for (int ntf = 0; ntf < 4; ntf++)
                    mma_tf32(accB[mt][ntf], afr, bfr[ntf]);
            }
        }
        __syncthreads();
    }

    // ====== epilogue: combine + D skip + gate + RMS (mma layout) ======
    float Dh = D_skip[h];
    #pragma unroll
    for (int mt = 0; mt < 2; mt++) {
        #pragma unroll
        for (int hf = 0; hf < 2; hf++) {
            int rl = wm*32 + mt*16 + hf*8 + gid;
            int gi = it * 64 + rl;
            float ea = __expf(ai[rl]);
            float ss = 0.f;
            #pragma unroll
            for (int ntf = 0; ntf < 4; ntf++) {
                int col = wn*32 + ntf*8 + 2*tig;
                float2 xv = *(const float2*)&g_xbc[(size_t)(row0 + gi) * CONVDIM + h * HD + col];
                float2 zv = *(const float2*)&g_zx[(size_t)(row0 + gi) * DPROJ + h * HD + col];
                float o0 = accA[mt][ntf][hf*2+0] + ea * accB[mt][ntf][hf*2+0] + Dh * xv.x;
                float o1 = accA[mt][ntf][hf*2+1] + ea * accB[mt][ntf][hf*2+1] + Dh * xv.y;
                float v0 = o0 / (1.f + __expf(-zv.x));
                float v1 = o1 / (1.f + __expf(-zv.y));
                accA[mt][ntf][hf*2+0] = v0;
                accA[mt][ntf][hf*2+1] = v1;
                ss += v0 * v0 + v1 * v1;
            }
            ss += __shfl_xor_sync(0xffffffffu, ss, 1);
            ss += __shfl_xor_sync(0xffffffffu, ss, 2);
            if (tig == 0) ssbuf[rl * 4 + wn] = ss;
        }
    }
    __syncthreads();
    #pragma unroll
    for (int mt = 0; mt < 2; mt++) {
        #pragma unroll
        for (int hf = 0; hf < 2; hf++) {
            int rl = wm*32 + mt*16 + hf*8 + gid;
            int gi = it * 64 + rl;
            float tot = ssbuf[rl*4+0] + ssbuf[rl*4+1] + ssbuf[rl*4+2] + ssbuf[rl*4+3];
            float inv = rsqrtf(tot * (1.f / HD) + 1e-6f);
            #pragma unroll
            for (int ntf = 0; ntf < 4; ntf++) {
                int col = wn*32 + ntf*8 + 2*tig;
                float2 nw = *(const float2*)&norm_w[h * HD + col];
                float r0 = accA[mt][ntf][hf*2+0] * inv * nw.x;
                float r1 = accA[mt][ntf][hf*2+1] * inv * nw.y;
                size_t oi = (size_t)(row0 + gi) * DIN + h * HD + col;
                __nv_bfloat16 h0 = __float2bfloat16(r0), h1 = __float2bfloat16(r1);
                *(__nv_bfloat162*)&g_ynh[oi] = __nv_bfloat162(h0, h1);
                *(__nv_bfloat162*)&g_ynl[oi] = __nv_bfloat162(
                    __float2bfloat16(r0 - __bfloat162float(h0)),
                    __float2bfloat16(r1 - __bfloat162float(h1)));
            }
        }
    }
}

// ------------------- launch ---------------------------------------------------
extern "C" void kernel_launch(void* const* d_in, const int* in_sizes, int n_in,
                              void* d_out, int out_size)
{
    const float* u         = (const float*)d_in[0];
    const float* in_proj_w = (const float*)d_in[1];
    const float* conv_w    = (const float*)d_in[2];
    const float* conv_b    = (const float*)d_in[3];
    const float* A_log     = (const float*)d_in[4];
    const float* dt_bias   = (const float*)d_in[5];
    const float* D_skip    = (const float*)d_in[6];
    const float* norm_w    = (const float*)d_in[7];
    const float* o_proj_w  = (const float*)d_in[8];
    float* out = (float*)d_out;

    float* zx = nullptr;
    cudaGetSymbolAddress((void**)&zx, g_zx);
    __nv_bfloat16 *uh, *ul, *w1h, *w1l, *w2h, *w2l, *ynh, *ynl;
    cudaGetSymbolAddress((void**)&uh,  g_uh);
    cudaGetSymbolAddress((void**)&ul,  g_ul);
    cudaGetSymbolAddress((void**)&w1h, g_w1h);
    cudaGetSymbolAddress((void**)&w1l, g_w1l);
    cudaGetSymbolAddress((void**)&w2h, g_w2h);
    cudaGetSymbolAddress((void**)&w2l, g_w2l);
    cudaGetSymbolAddress((void**)&ynh, g_ynh);
    cudaGetSymbolAddress((void**)&ynl, g_ynl);

    const int SMEM_GEMM = 2 * HSTAGEB;   // 147456
    cudaFuncSetAttribute(hgemm3, cudaFuncAttributeMaxDynamicSharedMemorySize, SMEM_GEMM);

    const int M = BB * LL;   // 8192

    // 0) hi/lo splits of GEMM inputs
    {
        int n4;
        n4 = (M * EMBED) / 4;
        split_k<<<(n4 + 255) / 256, 256>>>(u, uh, ul, n4);
        n4 = (DPROJ * EMBED) / 4;
        split_k<<<(n4 + 255) / 256, 256>>>(in_proj_w, w1h, w1l, n4);
        n4 = (EMBED * DIN) / 4;
        split_k<<<(n4 + 255) / 256, 256>>>(o_proj_w, w2h, w2l, n4);
    }
    // 1) in_proj: zx = u @ W1^T  (HMMA bf16x3)
    hgemm3<<<dim3((DPROJ + HBN - 1) / HBN, M / HBM), 512, SMEM_GEMM>>>(
        M, DPROJ, EMBED, uh, ul, w1h, w1l, zx);
    // 2) causal depthwise conv + silu (smem-tiled)
    conv_silu_k<<<dim3(CONVDIM / 64, LL / 128, BB), 256>>>(conv_w, conv_b);
    // 3) fused dt softplus + per-chunk cumsum (parallel scan)
    cumsum_k<<<NBC * NH, 32>>>(A_log, dt_bias);
    // 4) chunk attention scores (lower tiles, tf32 MMA)
    scores_k<<<dim3(4, 4, NBC), 256>>>();
    // 5) per-chunk end states (tf32 MMA)
    states_k<<<NBC * NH, 256>>>();
    // 6) inter-chunk scan (16 slices per (b,h))
    scan_k<<<dim3(BB * NH, 16), 512>>>();
    // 7) y: tf32 MMA intra+inter, fused gate + RMS norm (writes bf16 hi/lo)
    ych_k<<<dim3(4, NH, NBC), 256>>>(D_skip, norm_w);
    // 8) o_proj: out = yn @ W2^T  (HMMA bf16x3)
    hgemm3<<<dim3(EMBED / HBN, M / HBM), 512, SMEM_GEMM>>>(
        M, EMBED, DIN, ynh, ynl, w2h, w2l, out);
}

// round 14
// speedup vs baseline: 1.2292x; 1.0016x over previous
#include <cuda_runtime.h>
#include <cuda_bf16.h>
#include <cstdint>

#define BB 2
#define LL 4096
#define EMBED 2048
#define DIN 4096
#define NH 32
#define HD 128
#define DS 64
#define CONVDIM 4224   // DIN + 2*DS
#define DPROJ 8352     // 2*DIN + 2*DS + NH
#define CHUNK 256
#define NCH 16         // LL / CHUNK
#define NBC (BB*NCH)   // 32

// ------------------- scratch (device globals; no cudaMalloc allowed) ---------
__device__ float g_zx[(size_t)BB*LL*DPROJ];        // in_proj output
__device__ float g_xbc[(size_t)BB*LL*CONVDIM];     // conv+silu output
__device__ float g_dt[BB*LL*NH];                   // softplus(dt)
__device__ float g_a[NBC*CHUNK*NH];                // cumsum(dA) per chunk
__device__ float g_alast[NBC*NH];
__device__ float g_scores[(size_t)NBC*CHUNK*CHUNK];
__device__ float g_states[(size_t)NBC*NH*HD*DS];   // [b,c,h,p,n]
__device__ float g_prev[(size_t)NBC*NH*HD*DS];     // state entering chunk c

// bf16 hi/lo split buffers
__device__ __nv_bfloat16 g_uh[(size_t)BB*LL*EMBED];
__device__ __nv_bfloat16 g_ul[(size_t)BB*LL*EMBED];
__device__ __nv_bfloat16 g_w1h[(size_t)DPROJ*EMBED];
__device__ __nv_bfloat16 g_w1l[(size_t)DPROJ*EMBED];
__device__ __nv_bfloat16 g_w2h[(size_t)EMBED*DIN];
__device__ __nv_bfloat16 g_w2l[(size_t)EMBED*DIN];
__device__ __nv_bfloat16 g_ynh[(size_t)BB*LL*DIN];
__device__ __nv_bfloat16 g_ynl[(size_t)BB*LL*DIN];

// ------------------- PTX helpers (sm_80-era: valid on base sm_103 target) ----
__device__ __forceinline__ uint32_t s2u(const void* p) {
    uint32_t a;
    asm("{ .reg .u64 t; cvta.to.shared.u64 t, %1; cvt.u32.u64 %0, t; }" : "=r"(a) : "l"(p));
    return a;
}
__device__ __forceinline__ void cpasync16(uint32_t s, const void* g, int srcsize) {
    asm volatile("cp.async.ca.shared.global [%0], [%1], 16, %2;"
                 :: "r"(s), "l"(g), "r"(srcsize));
}
__device__ __forceinline__ void cpcommit() {
    asm volatile("cp.async.commit_group;" ::: "memory");
}
template <int N>
__device__ __forceinline__ void cpwait() {
    asm volatile("cp.async.wait_group %0;" :: "n"(N) : "memory");
}
__device__ __forceinline__ void ldsm4(uint32_t* r, uint32_t addr) {
    asm volatile("ldmatrix.sync.aligned.m8n8.x4.shared.b16 {%0,%1,%2,%3}, [%4];"
                 : "=r"(r[0]), "=r"(r[1]), "=r"(r[2]), "=r"(r[3]) : "r"(addr));
}
__device__ __forceinline__ void mma16816(float* c, const uint32_t* a, const uint32_t* b) {
    asm volatile(
        "mma.sync.aligned.m16n8k16.row.col.f32.bf16.bf16.f32 "
        "{%0,%1,%2,%3},{%4,%5,%6,%7},{%8,%9},{%0,%1,%2,%3};"
        : "+f"(c[0]), "+f"(c[1]), "+f"(c[2]), "+f"(c[3])
        : "r"(a[0]), "r"(a[1]), "r"(a[2]), "r"(a[3]), "r"(b[0]), "r"(b[1]));
}
__device__ __forceinline__ void mma_tf32(float* d, const uint32_t* a, const uint32_t* b) {
    asm volatile(
        "mma.sync.aligned.m16n8k8.row.col.f32.tf32.tf32.f32 "
        "{%0,%1,%2,%3},{%4,%5,%6,%7},{%8,%9},{%0,%1,%2,%3};"
        : "+f"(d[0]), "+f"(d[1]), "+f"(d[2]), "+f"(d[3])
        : "r"(a[0]), "r"(a[1]), "r"(a[2]), "r"(a[3]), "r"(b[0]), "r"(b[1]));
}
__device__ __forceinline__ uint32_t f2tf(float x) {
    uint32_t r; asm("cvt.rna.tf32.f32 %0, %1;" : "=r"(r) : "f"(x)); return r;
}

// ------------------- fp32 -> bf16 hi/lo split --------------------------------
__global__ void split_k(const float* __restrict__ s, __nv_bfloat16* __restrict__ hi,
                        __nv_bfloat16* __restrict__ lo, int n4)
{
    int i = blockIdx.x * 256 + threadIdx.x;
    if (i >= n4) return;
    float4 v = ((const float4*)s)[i];
    __nv_bfloat16 h0 = __float2bfloat16(v.x), h1 = __float2bfloat16(v.y);
    __nv_bfloat16 h2 = __float2bfloat16(v.z), h3 = __float2bfloat16(v.w);
    __nv_bfloat162* H = (__nv_bfloat162*)hi;
    __nv_bfloat162* L = (__nv_bfloat162*)lo;
    H[i*2+0] = __nv_bfloat162(h0, h1);
    H[i*2+1] = __nv_bfloat162(h2, h3);
    L[i*2+0] = __nv_bfloat162(__float2bfloat16(v.x - __bfloat162float(h0)),
                              __float2bfloat16(v.y - __bfloat162float(h1)));
    L[i*2+1] = __nv_bfloat162(__float2bfloat16(v.z - __bfloat162float(h2)),
                              __float2bfloat16(v.w - __bfloat162float(h3)));
}

// ------------------- HMMA bf16x3 GEMM: C[M,N] = A[M,K] @ B[N,K]^T ------------
// (EXACT round-3/7 configuration — proven fastest; FROZEN.)
#define HBM 128
#define HBN 128
#define HBK 64
#define HLD 72
#define HMATB (128*HLD*2)
#define HSTAGEB (4*HMATB)

__global__ __launch_bounds__(512) void hgemm3(
    int M, int N, int K,
    const __nv_bfloat16* __restrict__ Ah, const __nv_bfloat16* __restrict__ Al,
    const __nv_bfloat16* __restrict__ Bh, const __nv_bfloat16* __restrict__ Bl,
    float* __restrict__ C)
{
    extern __shared__ char smem[];
    const int tid = threadIdx.x;
    const int lane = tid & 31, wid = tid >> 5;
    const int wm = wid & 3, wn = wid >> 2;
    const int bm = blockIdx.y * HBM, bn = blockIdx.x * HBN;
    const uint32_t sbase = s2u(smem);

    const int arow = lane & 15, akoff = (lane >> 4) << 3;
    const int bnl = (lane & 7) + ((lane >> 4) << 3);
    const int bkl = ((lane >> 3) & 1) << 3;

    float acc[2][4][4];
    #pragma unroll
    for (int mt = 0; mt < 2; mt++)
        #pragma unroll
        for (int nt = 0; nt < 4; nt++)
            #pragma unroll
            for (int i = 0; i < 4; i++) acc[mt][nt][i] = 0.f;

    const int nk = K / HBK;

    auto load_stage = [&](int st, int k0) {
        uint32_t sb = sbase + st * HSTAGEB;
        #pragma unroll
        for (int i = 0; i < 2; i++) {
            int chunk = tid + i * 512;
            int row = chunk >> 3, c = chunk & 7;
            uint32_t so = (uint32_t)(row * HLD + c * 8) * 2;
            size_t ga = (size_t)(bm + row) * K + k0 + c * 8;
            cpasync16(sb + so,             Ah + ga, 16);
            cpasync16(sb + HMATB + so,     Al + ga, 16);
            int brow = bn + row;
            int sz = (brow < N) ? 16 : 0;
            int bcl = (brow < N) ? brow : 0;
            size_t gb = (size_t)bcl * K + k0 + c * 8;
            cpasync16(sb + 2*HMATB + so,   Bh + gb, sz);
            cpasync16(sb + 3*HMATB + so,   Bl + gb, sz);
        }
        cpcommit();
    };

    load_stage(0, 0);

    for (int kt = 0; kt < nk; ++kt) {
        if (kt + 1 < nk) {
            load_stage((kt + 1) & 1, (kt + 1) * HBK);
            cpwait<1>();
        } else {
            cpwait<0>();
        }
        __syncthreads();

        uint32_t sb = sbase + (kt & 1) * HSTAGEB;
        uint32_t sAh = sb, sAl = sb + HMATB, sBh = sb + 2*HMATB, sBl = sb + 3*HMATB;

        #pragma unroll
        for (int kh = 0; kh < 4; kh++) {
            int k = kh * 16;
            uint32_t bfh[2][4], bfl[2][4];
            #pragma unroll
            for (int ntp = 0; ntp < 2; ntp++) {
                uint32_t off = (uint32_t)((wn * 32 + ntp * 16 + bnl) * HLD + k + bkl) * 2;
                ldsm4(bfh[ntp], sBh + off);
                ldsm4(bfl[ntp], sBl + off);
            }
            #pragma unroll
            for (int mt = 0; mt < 2; mt++) {
                uint32_t aoff = (uint32_t)((wm * 32 + mt * 16 + arow) * HLD + k + akoff) * 2;
                uint32_t af[4];
                ldsm4(af, sAh + aoff);
                #pragma unroll
                for (int nt = 0; nt < 4; nt++)
                    mma16816(acc[mt][nt], af, &bfh[nt >> 1][(nt & 1) * 2]);
                #pragma unroll
                for (int nt = 0; nt < 4; nt++)
                    mma16816(acc[mt][nt], af, &bfl[nt >> 1][(nt & 1) * 2]);
                ldsm4(af, sAl + aoff);
                #pragma unroll
                for (int nt = 0; nt < 4; nt++)
                    mma16816(acc[mt][nt], af, &bfh[nt >> 1][(nt & 1) * 2]);
            }
        }
        __syncthreads();
    }

    #pragma unroll
    for (int mt = 0; mt < 2; mt++) {
        int row0 = bm + wm * 32 + mt * 16 + (lane >> 2);
        #pragma unroll
        for (int nt = 0; nt < 4; nt++) {
            int col = bn + wn * 32 + nt * 8 + (lane & 3) * 2;
            if (col < N) {
                *(float2*)&C[(size_t)row0 * N + col] =
                    make_float2(acc[mt][nt][0], acc[mt][nt][1]);
                *(float2*)&C[(size_t)(row0 + 8) * N + col] =
                    make_float2(acc[mt][nt][2], acc[mt][nt][3]);
            }
        }
    }
}

// --------- depthwise causal conv (k=4) + silu, smem-tiled (reads 1x) ---------
__global__ __launch_bounds__(256) void conv_silu_k(const float* __restrict__ cw,
                                                   const float* __restrict__ cb)
{
    int ct = blockIdx.x;           // 0..65  (CONVDIM/64)
    int lt = blockIdx.y;           // 0..31  (LL/128)
    int b  = blockIdx.z;
    int c0 = ct * 64, l0 = lt * 128;
    __shared__ float tile[131][64];
    int tid = threadIdx.x;
    int tc = tid & 63, tg = tid >> 6;   // channel-in-tile, group 0..3
    for (int r = tg; r < 131; r += 4) {
        int l = l0 + r - 3;
        float v = 0.f;
        if (l >= 0) v = g_zx[(size_t)(b * LL + l) * DPROJ + DIN + c0 + tc];
        tile[r][tc] = v;
    }
    __syncthreads();
    int ch = c0 + tc;
    float w0 = cw[ch * 4 + 0], w1 = cw[ch * 4 + 1];
    float w2 = cw[ch * 4 + 2], w3 = cw[ch * 4 + 3];
    float bias = cb[ch];
    #pragma unroll 4
    for (int i = 0; i < 32; i++) {
        int lr = tg * 32 + i;
        float acc = bias + tile[lr][tc] * w0 + tile[lr + 1][tc] * w1
                  + tile[lr + 2][tc] * w2 + tile[lr + 3][tc] * w3;
        g_xbc[(size_t)(b * LL + l0 + lr) * CONVDIM + ch] = acc / (1.f + __expf(-acc));
    }
}

// ------------------- per-chunk cumsum of dA (fused softplus + warp scan) -----
__global__ void cumsum_k(const float* __restrict__ A_log, const float* __restrict__ dt_bias)
{
    int bch = blockIdx.x;            // bc*NH + h
    int h = bch & 31, bc = bch >> 5;
    int b = bc / NCH, c = bc % NCH;
    int t = threadIdx.x;             // 32
    float Ah = -__expf(A_log[h]);
    float bias = dt_bias[h];
    size_t row0 = (size_t)(b * LL + c * CHUNK) + t * 8;
    float v[8];
    #pragma unroll
    for (int j = 0; j < 8; j++) {
        float x = g_zx[(row0 + j) * DPROJ + DIN + CONVDIM + h] + bias;
        float sp = (x > 20.f) ? x : log1pf(__expf(x));
        g_dt[(row0 + j) * NH + h] = sp;
        v[j] = sp * Ah;
    }
    float loc = 0.f;
    #pragma unroll
    for (int j = 0; j < 8; j++) { loc += v[j]; v[j] = loc; }
    float pre = loc;
    #pragma unroll
    for (int o = 1; o < 32; o <<= 1) {
        float nv = __shfl_up_sync(0xffffffffu, pre, o);
        if (t >= o) pre += nv;
    }
    pre -= loc;   // exclusive prefix
    #pragma unroll
    for (int j = 0; j < 8; j++) g_a[(bc * CHUNK + t * 8 + j) * NH + h] = pre + v[j];
    if (t == 31) g_alast[bc * NH + h] = pre + loc;
}

// ---------- scores = C @ B^T per chunk (lower tiles, tf32 MMA) ---------------
__global__ __launch_bounds__(256) void scores_k()
{
    int jt = blockIdx.x, it = blockIdx.y, bc = blockIdx.z;
    if (jt > it) return;
    int b = bc / NCH, c = bc % NCH;
    __shared__ float CtT[64 * 72];   // [n][r] k-major
    __shared__ float BtT[64 * 72];
    int tid = threadIdx.x;
    const int lane = tid & 31, wid = tid >> 5;
    const int gid = lane >> 2, tig = lane & 3;
    const int wm = wid >> 2, wn = wid & 3;   // 2m x 4n
    for (int t = tid; t < 64 * 64; t += 256) {
        int r = t >> 6, n = t & 63;
        int rowC = b * LL + c * CHUNK + it * 64 + r;
        int rowB = b * LL + c * CHUNK + jt * 64 + r;
        CtT[n * 72 + r] = g_xbc[(size_t)rowC * CONVDIM + DIN + DS + n];
        BtT[n * 72 + r] = g_xbc[(size_t)rowB * CONVDIM + DIN + n];
    }
    __syncthreads();
    float acc[2][2][4];
    #pragma unroll
    for (int mt = 0; mt < 2; mt++)
        #pragma unroll
        for (int nf = 0; nf < 2; nf++)
            #pragma unroll
            for (int i = 0; i < 4; i++) acc[mt][nf][i] = 0.f;
    #pragma unroll
    for (int ks = 0; ks < 8; ks++) {
        int k8 = ks * 8;
        uint32_t bfr[2][2];
        #pragma unroll
        for (int nf = 0; nf < 2; nf++) {
            int col = wn * 16 + nf * 8 + gid;
            bfr[nf][0] = f2tf(BtT[(k8 + tig)     * 72 + col]);
            bfr[nf][1] = f2tf(BtT[(k8 + tig + 4) * 72 + col]);
        }
        #pragma unroll
        for (int mt = 0; mt < 2; mt++) {
            int r0 = wm * 32 + mt * 16 + gid;
            uint32_t afr[4];
            afr[0] = f2tf(CtT[(k8 + tig)     * 72 + r0]);
            afr[1] = f2tf(CtT[(k8 + tig)     * 72 + r0 + 8]);
            afr[2] = f2tf(CtT[(k8 + tig + 4) * 72 + r0]);
            afr[3] = f2tf(CtT[(k8 + tig + 4) * 72 + r0 + 8]);
            #pragma unroll
            for (int nf = 0; nf < 2; nf++)
                mma_tf32(acc[mt][nf], afr, bfr[nf]);
        }
    }
    #pragma unroll
    for (int mt = 0; mt < 2; mt++)
        #pragma unroll
        for (int hf = 0; hf < 2; hf++) {
            int r = wm * 32 + mt * 16 + hf * 8 + gid;
            #pragma unroll
            for (int nf = 0; nf < 2; nf++) {
                int n = wn * 16 + nf * 8 + 2 * tig;
                *(float2*)&g_scores[((size_t)bc << 16) + (it * 64 + r) * 256 + jt * 64 + n] =
                    make_float2(acc[mt][nf][hf * 2], acc[mt][nf][hf * 2 + 1]);
            }
        }
}

// ------------- per-chunk states[h,p,n] = X^T @ Bco  (tf32 MMA) ---------------
__global__ __launch_bounds__(256) void states_k()
{
    int bch = blockIdx.x;              // bc*NH + h
    int h = bch % NH, bc = bch / NH;
    int b = bc / NCH, c = bc % NCH;
    __shared__ float sh[6688];
    float* Xs   = sh;                  // 32 x 136 (q-major, p cols)
    float* Bs   = sh + 4352;           // 32 x 72  (q-major, n cols)
    float* coef = sh + 6656;           // 32
    int tid = threadIdx.x;
    const int lane = tid & 31, wid = tid >> 5;
    const int gid = lane >> 2, tig = lane & 3;
    const int wm = wid & 3, wn = wid >> 2;    // 4m x 2n
    float alast = g_alast[bc * NH + h];
    float acc[2][4][4];
    #pragma unroll
    for (int mt = 0; mt < 2; mt++)
        #pragma unroll
        for (int nt = 0; nt < 4; nt++)
            #pragma unroll
            for (int i = 0; i < 4; i++) acc[mt][nt][i] = 0.f;

    for (int q0 = 0; q0 < CHUNK; q0 += 32) {
        __syncthreads();
        if (tid < 32) {
            int gq = q0 + tid;
            float aq = g_a[(bc * CHUNK + gq) * NH + h];
            float dtq = g_dt[(size_t)(b * LL + c * CHUNK + gq) * NH + h];
            coef[tid] = dtq * __expf(alast - aq);
        }
        #pragma unroll
        for (int t = 0; t < 16; t++) {
            int idx = tid + t * 256;
            int q = idx >> 7, p = idx & 127;
            Xs[q * 136 + p] = g_xbc[(size_t)(b * LL + c * CHUNK + q0 + q) * CONVDIM + h * HD + p];
        }
        __syncthreads();
        #pragma unroll
        for (int t = 0; t < 8; t++) {
            int idx = tid + t * 256;
            int q = idx >> 6, n = idx & 63;
            Bs[q * 72 + n] = g_xbc[(size_t)(b * LL + c * CHUNK + q0 + q) * CONVDIM + DIN + n] * coef[q];
        }
        __syncthreads();
        #pragma unroll
        for (int ks = 0; ks < 4; ks++) {
            int k8 = ks * 8;
            uint32_t bfr[4][2];
            #pragma unroll
            for (int ntf = 0; ntf < 4; ntf++) {
                int nb = wn * 32 + ntf * 8 + gid;
                bfr[ntf][0] = f2tf(Bs[(k8 + tig)     * 72 + nb]);
                bfr[ntf][1] = f2tf(Bs[(k8 + tig + 4) * 72 + nb]);
            }
            #pragma unroll
            for (int mt = 0; mt < 2; mt++) {
                int r0 = wm * 32 + mt * 16 + gid;
                uint32_t afr[4];
                afr[0] = f2tf(Xs[(k8 + tig)     * 136 + r0]);
                afr[1] = f2tf(Xs[(k8 + tig)     * 136 + r0 + 8]);
                afr[2] = f2tf(Xs[(k8 + tig + 4) * 136 + r0]);
                afr[3] = f2tf(Xs[(k8 + tig + 4) * 136 + r0 + 8]);
                #pragma unroll
                for (int ntf = 0; ntf < 4; ntf++)
                    mma_tf32(acc[mt][ntf], afr, bfr[ntf]);
            }
        }
    }
    size_t base = (size_t)bch * HD * DS;
    #pragma unroll
    for (int mt = 0; mt < 2; mt++)
        #pragma unroll
        for (int hf = 0; hf < 2; hf++) {
            int p = wm * 32 + mt * 16 + hf * 8 + gid;
            #pragma unroll
            for (int ntf = 0; ntf < 4; ntf++) {
                int n = wn * 32 + ntf * 8 + 2 * tig;
                *(float2*)&g_states[base + (size_t)p * DS + n] =
                    make_float2(acc[mt][ntf][hf * 2], acc[mt][ntf][hf * 2 + 1]);
            }
        }
}

// ------------------- sequential inter-chunk scan (split over 16 slices) ------
__global__ void scan_k()
{
    int bh = blockIdx.x;            // b*NH + h
    int b = bh >> 5, h = bh & 31;
    int e = blockIdx.y * 512 + threadIdx.x;   // element in HD*DS plane
    float s = 0.f;
    for (int c = 0; c < NCH; c++) {
        int bc = b * NCH + c;
        float dec = __expf(g_alast[bc * NH + h]);
        size_t base = (size_t)(bc * NH + h) * HD * DS;
        g_prev[base + e] = s;
        s = s * dec + g_states[base + e];
    }
}

// ------ y = intra + inter + D*x (tf32 MMA) + fused gate + per-head RMS -------
__global__ __launch_bounds__(256) void ych_k(const float* __restrict__ D_skip,
                                             const float* __restrict__ norm_w)
{
    int it = blockIdx.x;   // 0..3 (64-row tile)
    int h  = blockIdx.y;   // 0..31
    int bc = blockIdx.z;   // 0..31
    int b = bc / NCH, c = bc % NCH;
    __shared__ float sh[9088];
    float* ai    = sh;            // 64
    float* er    = sh + 64;       // 64
    float* Ab    = sh + 128;      // 4352: Wt[64][36] (p1) / Ct[64][68] (p2)
    float* Bb    = sh + 4480;     // 4352: Xt[32][136] (p1) / prevT[32][136] (p2)
    float* ssbuf = sh + 8832;     // 64*4
    int tid = threadIdx.x;
    const int lane = tid & 31, wid = tid >> 5;
    const int gid = lane >> 2, tig = lane & 3;
    const int wm = wid >> 2, wn = wid & 3;     // 2m x 4n
    int row0 = b * LL + c * CHUNK;
    float aref = g_a[(bc * CHUNK + it * 64) * NH + h];
    if (tid < 64) {
        float av = g_a[(bc * CHUNK + it * 64 + tid) * NH + h];
        ai[tid] = av;
        er[tid] = __expf(av - aref);
    }
    float accA[2][4][4], accB[2][4][4];
    #pragma unroll
    for (int mt = 0; mt < 2; mt++)
        #pragma unroll
        for (int nt = 0; nt < 4; nt++)
            #pragma unroll
            for (int i = 0; i < 4; i++) { accA[mt][nt][i] = 0.f; accB[mt][nt][i] = 0.f; }
    __syncthreads();

    // ================== phase 1: intra (K tiles of 32) ==================
    int jtmax = 2 * it + 1;
    for (int jt = 0; jt <= jtmax; jt++) {
        int j0 = jt * 32;
        if (jt < 2 * it) {
            int j = tid & 31;
            int gj = j0 + j;
            float ec = __expf(aref - g_a[(bc * CHUNK + gj) * NH + h]) *
                       g_dt[(size_t)(row0 + gj) * NH + h];
            #pragma unroll
            for (int t = 0; t < 8; t++) {
                int i = (tid >> 5) + t * 8;
                int gi = it * 64 + i;
                Ab[i * 36 + j] =
                    g_scores[((size_t)bc << 16) + gi * 256 + gj] * er[i] * ec;
            }
        } else {
            #pragma unroll
            for (int t = 0; t < 8; t++) {
                int idx = tid + t * 256;
                int i = idx >> 5, j = idx & 31;
                int gi = it * 64 + i, gj = j0 + j;
                float w = 0.f;
                if (gj <= gi) {
                    float aj = g_a[(bc * CHUNK + gj) * NH + h];
                    float dtj = g_dt[(size_t)(row0 + gj) * NH + h];
                    w = g_scores[((size_t)bc << 16) + gi * 256 + gj] * __expf(ai[i] - aj) * dtj;
                }
                Ab[i * 36 + j] = w;
            }
        }
        #pragma unroll
        for (int t = 0; t < 16; t++) {
            int idx = tid + t * 256;
            int j = idx >> 7, p = idx & 127;
            Bb[j * 136 + p] = g_xbc[(size_t)(row0 + j0 + j) * CONVDIM + h * HD + p];
        }
        __syncthreads();
        #pragma unroll
        for (int ks = 0; ks < 4; ks++) {
            uint32_t bfr[4][2];
            #pragma unroll
            for (int ntf = 0; ntf < 4; ntf++) {
                bfr[ntf][0] = f2tf(Bb[(ks*8 + tig)     * 136 + wn*32 + ntf*8 + gid]);
                bfr[ntf][1] = f2tf(Bb[(ks*8 + tig + 4) * 136 + wn*32 + ntf*8 + gid]);
            }
            #pragma unroll
            for (int mt = 0; mt < 2; mt++) {
                int r0 = wm*32 + mt*16 + gid;
                uint32_t afr[4];
                afr[0] = f2tf(Ab[ r0      * 36 + ks*8 + tig]);
                afr[1] = f2tf(Ab[(r0 + 8) * 36 + ks*8 + tig]);
                afr[2] = f2tf(Ab[ r0      * 36 + ks*8 + tig + 4]);
                afr[3] = f2tf(Ab[(r0 + 8) * 36 + ks*8 + tig + 4]);
                #pragma unroll
                for (int ntf = 0; ntf < 4; ntf++)
                    mma_tf32(accA[mt][ntf], afr, bfr[ntf]);
            }
        }
        __syncthreads();
    }

    // ================== phase 2: inter (K = 64, 2 tiles) ==================
    #pragma unroll
    for (int t = 0; t < 16; t++) {
        int idx = tid + t * 256;
        int i = idx >> 6, n = idx & 63;
        Ab[i * 68 + n] = g_xbc[(size_t)(row0 + it * 64 + i) * CONVDIM + DIN + DS + n];
    }
    size_t pbase = (size_t)(bc * NH + h) * HD * DS;
    for (int nt = 0; nt < 2; nt++) {
        int n0 = nt * 32;
        #pragma unroll
        for (int t = 0; t < 16; t++) {
            int idx = tid + t * 256;
            int p = idx >> 5, n = idx & 31;
            Bb[n * 136 + p] = g_prev[pbase + (size_t)p * DS + n0 + n];
        }
        __syncthreads();
        #pragma unroll
        for (int ks = 0; ks < 4; ks++) {
            uint32_t bfr[4][2];
            #pragma unroll
            for (int ntf = 0; ntf < 4; ntf++) {
                bfr[ntf][0] = f2tf(Bb[(ks*8 + tig)     * 136 + wn*32 + ntf*8 + gid]);
                bfr[ntf][1] = f2tf(Bb[(ks*8 + tig + 4) * 136 + wn*32 + ntf*8 + gid]);
            }
            #pragma unroll
            for (int mt = 0; mt < 2; mt++) {
                int r0 = wm*32 + mt*16 + gid;
                uint32_t afr[4];
                afr[0] = f2tf(Ab[ r0      * 68 + n0 + ks*8 + tig]);
                afr[1] = f2tf(Ab[(r0 + 8) * 68 + n0 + ks*8 + tig]);
                afr[2] = f2tf(Ab[ r0      * 68 + n0 + ks*8 + tig + 4]);
                afr[3] = f2tf(Ab[(r0 + 8) * 68 + n0 + ks*8 + tig + 4]);
                #pragma unroll
                for (int ntf = 0; ntf < 4; ntf++)
                    mma_tf32(accB[mt][ntf], afr, bfr[ntf]);
            }
        }
        __syncthreads();
    }

    // ====== epilogue: combine + D skip + gate + RMS (mma layout) ======
    float Dh = D_skip[h];
    #pragma unroll
    for (int mt = 0; mt < 2; mt++) {
        #pragma unroll
        for (int hf = 0; hf < 2; hf++) {
            int rl = wm*32 + mt*16 + hf*8 + gid;
            int gi = it * 64 + rl;
            float ea = __expf(ai[rl]);
            float ss = 0.f;
            #pragma unroll
            for (int ntf = 0; ntf < 4; ntf++) {
                int col = wn*32 + ntf*8 + 2*tig;
                float2 xv = *(const float2*)&g_xbc[(size_t)(row0 + gi) * CONVDIM + h * HD + col];
                float2 zv = *(const float2*)&g_zx[(size_t)(row0 + gi) * DPROJ + h * HD + col];
                float o0 = accA[mt][ntf][hf*2+0] + ea * accB[mt][ntf][hf*2+0] + Dh * xv.x;
                float o1 = accA[mt][ntf][hf*2+1] + ea * accB[mt][ntf][hf*2+1] + Dh * xv.y;
                float v0 = o0 / (1.f + __expf(-zv.x));
                float v1 = o1 / (1.f + __expf(-zv.y));
                accA[mt][ntf][hf*2+0] = v0;
                accA[mt][ntf][hf*2+1] = v1;
                ss += v0 * v0 + v1 * v1;
            }
            ss += __shfl_xor_sync(0xffffffffu, ss, 1);
            ss += __shfl_xor_sync(0xffffffffu, ss, 2);
            if (tig == 0) ssbuf[rl * 4 + wn] = ss;
        }
    }
    __syncthreads();
    #pragma unroll
    for (int mt = 0; mt < 2; mt++) {
        #pragma unroll
        for (int hf = 0; hf < 2; hf++) {
            int rl = wm*32 + mt*16 + hf*8 + gid;
            int gi = it * 64 + rl;
            float tot = ssbuf[rl*4+0] + ssbuf[rl*4+1] + ssbuf[rl*4+2] + ssbuf[rl*4+3];
            float inv = rsqrtf(tot * (1.f / HD) + 1e-6f);
            #pragma unroll
            for (int ntf = 0; ntf < 4; ntf++) {
                int col = wn*32 + ntf*8 + 2*tig;
                float2 nw = *(const float2*)&norm_w[h * HD + col];
                float r0 = accA[mt][ntf][hf*2+0] * inv * nw.x;
                float r1 = accA[mt][ntf][hf*2+1] * inv * nw.y;
                size_t oi = (size_t)(row0 + gi) * DIN + h * HD + col;
                __nv_bfloat16 h0 = __float2bfloat16(r0), h1 = __float2bfloat16(r1);
                *(__nv_bfloat162*)&g_ynh[oi] = __nv_bfloat162(h0, h1);
                *(__nv_bfloat162*)&g_ynl[oi] = __nv_bfloat162(
                    __float2bfloat16(r0 - __bfloat162float(h0)),
                    __float2bfloat16(r1 - __bfloat162float(h1)));
            }
        }
    }
}

// ------------------- launch ---------------------------------------------------
extern "C" void kernel_launch(void* const* d_in, const int* in_sizes, int n_in,
                              void* d_out, int out_size)
{
    const float* u         = (const float*)d_in[0];
    const float* in_proj_w = (const float*)d_in[1];
    const float* conv_w    = (const float*)d_in[2];
    const float* conv_b    = (const float*)d_in[3];
    const float* A_log     = (const float*)d_in[4];
    const float* dt_bias   = (const float*)d_in[5];
    const float* D_skip    = (const float*)d_in[6];
    const float* norm_w    = (const float*)d_in[7];
    const float* o_proj_w  = (const float*)d_in[8];
    float* out = (float*)d_out;

    float* zx = nullptr;
    cudaGetSymbolAddress((void**)&zx, g_zx);
    __nv_bfloat16 *uh, *ul, *w1h, *w1l, *w2h, *w2l, *ynh, *ynl;
    cudaGetSymbolAddress((void**)&uh,  g_uh);
    cudaGetSymbolAddress((void**)&ul,  g_ul);
    cudaGetSymbolAddress((void**)&w1h, g_w1h);
    cudaGetSymbolAddress((void**)&w1l, g_w1l);
    cudaGetSymbolAddress((void**)&w2h, g_w2h);
    cudaGetSymbolAddress((void**)&w2l, g_w2l);
    cudaGetSymbolAddress((void**)&ynh, g_ynh);
    cudaGetSymbolAddress((void**)&ynl, g_ynl);

    const int SMEM_GEMM = 2 * HSTAGEB;   // 147456
    cudaFuncSetAttribute(hgemm3, cudaFuncAttributeMaxDynamicSharedMemorySize, SMEM_GEMM);

    // Side streams + events (created once; resources only — captured work is
    // identical and deterministic on every call).
    static cudaStream_t sW2 = nullptr, sCS = nullptr, sSC = nullptr;
    static cudaEvent_t evStart, evW2, evZX, evCum, evXBC, evScores;
    if (!sW2) {
        cudaStreamCreateWithFlags(&sW2, cudaStreamNonBlocking);
        cudaStreamCreateWithFlags(&sCS, cudaStreamNonBlocking);
        cudaStreamCreateWithFlags(&sSC, cudaStreamNonBlocking);
        cudaEventCreateWithFlags(&evStart,  cudaEventDisableTiming);
        cudaEventCreateWithFlags(&evW2,     cudaEventDisableTiming);
        cudaEventCreateWithFlags(&evZX,     cudaEventDisableTiming);
        cudaEventCreateWithFlags(&evCum,    cudaEventDisableTiming);
        cudaEventCreateWithFlags(&evXBC,    cudaEventDisableTiming);
        cudaEventCreateWithFlags(&evScores, cudaEventDisableTiming);
    }

    const int M = BB * LL;   // 8192

    // fork point for the w2 split (needed only by the final o_proj)
    cudaEventRecord(evStart, 0);
    cudaStreamWaitEvent(sW2, evStart, 0);
    {
        int n4 = (EMBED * DIN) / 4;
        split_k<<<(n4 + 255) / 256, 256, 0, sW2>>>(o_proj_w, w2h, w2l, n4);
        cudaEventRecord(evW2, sW2);
    }

    // critical path: splits for in_proj
    {
        int n4 = (M * EMBED) / 4;
        split_k<<<(n4 + 255) / 256, 256>>>(u, uh, ul, n4);
        n4 = (DPROJ * EMBED) / 4;
        split_k<<<(n4 + 255) / 256, 256>>>(in_proj_w, w1h, w1l, n4);
    }
    // 1) in_proj: zx = u @ W1^T  (HMMA bf16x3)
    hgemm3<<<dim3((DPROJ + HBN - 1) / HBN, M / HBM), 512, SMEM_GEMM>>>(
        M, DPROJ, EMBED, uh, ul, w1h, w1l, zx);
    cudaEventRecord(evZX, 0);

    // side: fused dt softplus + cumsum (depends only on zx)
    cudaStreamWaitEvent(sCS, evZX, 0);
    cumsum_k<<<NBC * NH, 32, 0, sCS>>>(A_log, dt_bias);
    cudaEventRecord(evCum, sCS);

    // 2) causal depthwise conv + silu (smem-tiled)
    conv_silu_k<<<dim3(CONVDIM / 64, LL / 128, BB), 256>>>(conv_w, conv_b);
    cudaEventRecord(evXBC, 0);

    // side: scores (depends only on xbc; feeds only ych)
    cudaStreamWaitEvent(sSC, evXBC, 0);
    scores_k<<<dim3(4, 4, NBC), 256, 0, sSC>>>();
    cudaEventRecord(evScores, sSC);

    // critical path: states (needs cumsum) -> scan
    cudaStreamWaitEvent(0, evCum, 0);
    states_k<<<NBC * NH, 256>>>();
    scan_k<<<dim3(BB * NH, 16), 512>>>();

    // join scores, then ych
    cudaStreamWaitEvent(0, evScores, 0);
    ych_k<<<dim3(4, NH, NBC), 256>>>(D_skip, norm_w);

    // join w2 split, then o_proj
    cudaStreamWaitEvent(0, evW2, 0);
    hgemm3<<<dim3(EMBED / HBN, M / HBM), 512, SMEM_GEMM>>>(
        M, EMBED, DIN, ynh, ynl, w2h, w2l, out);
}

// round 15
// speedup vs baseline: 1.6216x; 1.3192x over previous
#include <cuda_runtime.h>
#include <cuda_bf16.h>
#include <cuda_fp16.h>
#include <cstdint>

#define BB 2
#define LL 4096
#define EMBED 2048
#define DIN 4096
#define NH 32
#define HD 128
#define DS 64
#define CONVDIM 4224   // DIN + 2*DS
#define DPROJ 8352     // 2*DIN + 2*DS + NH
#define CHUNK 256
#define NCH 16         // LL / CHUNK
#define NBC (BB*NCH)   // 32

// ------------------- scratch (device globals; no cudaMalloc allowed) ---------
__device__ float g_zx[(size_t)BB*LL*DPROJ];        // in_proj output
__device__ float g_xbc[(size_t)BB*LL*CONVDIM];     // conv+silu output
__device__ float g_dt[BB*LL*NH];                   // softplus(dt)
__device__ float g_a[NBC*CHUNK*NH];                // cumsum(dA) per chunk
__device__ float g_alast[NBC*NH];
__device__ float g_scores[(size_t)NBC*CHUNK*CHUNK];
__device__ float g_states[(size_t)NBC*NH*HD*DS];   // [b,c,h,p,n]
__device__ float g_prev[(size_t)NBC*NH*HD*DS];     // state entering chunk c

// fp16 hi/lo (activations) and fp16 (weights) buffers
__device__ __half g_uh[(size_t)BB*LL*EMBED];
__device__ __half g_ul[(size_t)BB*LL*EMBED];
__device__ __half g_w1h[(size_t)DPROJ*EMBED];
__device__ __half g_w2h[(size_t)EMBED*DIN];
__device__ __half g_ynh[(size_t)BB*LL*DIN];
__device__ __half g_ynl[(size_t)BB*LL*DIN];

// ------------------- PTX helpers (sm_80-era: valid on base sm_103 target) ----
__device__ __forceinline__ uint32_t s2u(const void* p) {
    uint32_t a;
    asm("{ .reg .u64 t; cvta.to.shared.u64 t, %1; cvt.u32.u64 %0, t; }" : "=r"(a) : "l"(p));
    return a;
}
__device__ __forceinline__ void cpasync16(uint32_t s, const void* g, int srcsize) {
    asm volatile("cp.async.ca.shared.global [%0], [%1], 16, %2;"
                 :: "r"(s), "l"(g), "r"(srcsize));
}
__device__ __forceinline__ void cpcommit() {
    asm volatile("cp.async.commit_group;" ::: "memory");
}
template <int N>
__device__ __forceinline__ void cpwait() {
    asm volatile("cp.async.wait_group %0;" :: "n"(N) : "memory");
}
__device__ __forceinline__ void ldsm4(uint32_t* r, uint32_t addr) {
    asm volatile("ldmatrix.sync.aligned.m8n8.x4.shared.b16 {%0,%1,%2,%3}, [%4];"
                 : "=r"(r[0]), "=r"(r[1]), "=r"(r[2]), "=r"(r[3]) : "r"(addr));
}
__device__ __forceinline__ void mma16816h(float* c, const uint32_t* a, const uint32_t* b) {
    asm volatile(
        "mma.sync.aligned.m16n8k16.row.col.f32.f16.f16.f32 "
        "{%0,%1,%2,%3},{%4,%5,%6,%7},{%8,%9},{%0,%1,%2,%3};"
        : "+f"(c[0]), "+f"(c[1]), "+f"(c[2]), "+f"(c[3])
        : "r"(a[0]), "r"(a[1]), "r"(a[2]), "r"(a[3]), "r"(b[0]), "r"(b[1]));
}
__device__ __forceinline__ void mma_tf32(float* d, const uint32_t* a, const uint32_t* b) {
    asm volatile(
        "mma.sync.aligned.m16n8k8.row.col.f32.tf32.tf32.f32 "
        "{%0,%1,%2,%3},{%4,%5,%6,%7},{%8,%9},{%0,%1,%2,%3};"
        : "+f"(d[0]), "+f"(d[1]), "+f"(d[2]), "+f"(d[3])
        : "r"(a[0]), "r"(a[1]), "r"(a[2]), "r"(a[3]), "r"(b[0]), "r"(b[1]));
}
__device__ __forceinline__ uint32_t f2tf(float x) {
    uint32_t r; asm("cvt.rna.tf32.f32 %0, %1;" : "=r"(r) : "f"(x)); return r;
}

// ------------------- fp32 -> fp16 hi/lo split (activations) ------------------
__global__ void split2h(const float* __restrict__ s, __half* __restrict__ hi,
                        __half* __restrict__ lo, int n4)
{
    int i = blockIdx.x * 256 + threadIdx.x;
    if (i >= n4) return;
    float4 v = ((const float4*)s)[i];
    __half h0 = __float2half(v.x), h1 = __float2half(v.y);
    __half h2 = __float2half(v.z), h3 = __float2half(v.w);
    __half2* H = (__half2*)hi;
    __half2* L = (__half2*)lo;
    H[i*2+0] = __halves2half2(h0, h1);
    H[i*2+1] = __halves2half2(h2, h3);
    L[i*2+0] = __halves2half2(__float2half(v.x - __half2float(h0)),
                              __float2half(v.y - __half2float(h1)));
    L[i*2+1] = __halves2half2(__float2half(v.z - __half2float(h2)),
                              __float2half(v.w - __half2float(h3)));
}

// ------------------- fp32 -> fp16 convert (weights) --------------------------
__global__ void cvt_h(const float* __restrict__ s, __half* __restrict__ d, int n4)
{
    int i = blockIdx.x * 256 + threadIdx.x;
    if (i >= n4) return;
    float4 v = ((const float4*)s)[i];
    __half2* D = (__half2*)d;
    D[i*2+0] = __halves2half2(__float2half(v.x), __float2half(v.y));
    D[i*2+1] = __halves2half2(__float2half(v.z), __float2half(v.w));
}

// ------------- HMMA fp16x2 GEMM: C[M,N] = (Ah+Al)[M,K] @ Bh[N,K]^T -----------
// CTA tile 128x128, BK=64, 512 threads = 4x4 warps, warp tile 32x32.
// Same skeleton as the proven bf16x3 kernel; 3 matrices/stage, 2 MMA passes.
#define HBM 128
#define HBN 128
#define HBK 64
#define HLD 72
#define HMATB (128*HLD*2)            // 18432
#define HSTAGEB (3*HMATB)            // 55296

__global__ __launch_bounds__(512) void hgemm2(
    int M, int N, int K,
    const __half* __restrict__ Ah, const __half* __restrict__ Al,
    const __half* __restrict__ Bh, float* __restrict__ C)
{
    extern __shared__ char smem[];
    const int tid = threadIdx.x;
    const int lane = tid & 31, wid = tid >> 5;
    const int wm = wid & 3, wn = wid >> 2;
    const int bm = blockIdx.y * HBM, bn = blockIdx.x * HBN;
    const uint32_t sbase = s2u(smem);

    const int arow = lane & 15, akoff = (lane >> 4) << 3;
    const int bnl = (lane & 7) + ((lane >> 4) << 3);
    const int bkl = ((lane >> 3) & 1) << 3;

    float acc[2][4][4];
    #pragma unroll
    for (int mt = 0; mt < 2; mt++)
        #pragma unroll
        for (int nt = 0; nt < 4; nt++)
            #pragma unroll
            for (int i = 0; i < 4; i++) acc[mt][nt][i] = 0.f;

    const int nk = K / HBK;

    auto load_stage = [&](int st, int k0) {
        uint32_t sb = sbase + st * HSTAGEB;
        #pragma unroll
        for (int i = 0; i < 2; i++) {
            int chunk = tid + i * 512;
            int row = chunk >> 3, c = chunk & 7;
            uint32_t so = (uint32_t)(row * HLD + c * 8) * 2;
            size_t ga = (size_t)(bm + row) * K + k0 + c * 8;
            cpasync16(sb + so,             Ah + ga, 16);
            cpasync16(sb + HMATB + so,     Al + ga, 16);
            int brow = bn + row;
            int sz = (brow < N) ? 16 : 0;
            int bcl = (brow < N) ? brow : 0;
            size_t gb = (size_t)bcl * K + k0 + c * 8;
            cpasync16(sb + 2*HMATB + so,   Bh + gb, sz);
        }
        cpcommit();
    };

    load_stage(0, 0);

    for (int kt = 0; kt < nk; ++kt) {
        if (kt + 1 < nk) {
            load_stage((kt + 1) & 1, (kt + 1) * HBK);
            cpwait<1>();
        } else {
            cpwait<0>();
        }
        __syncthreads();

        uint32_t sb = sbase + (kt & 1) * HSTAGEB;
        uint32_t sAh = sb, sAl = sb + HMATB, sBh = sb + 2*HMATB;

        #pragma unroll
        for (int kh = 0; kh < 4; kh++) {
            int k = kh * 16;
            uint32_t bfh[2][4];
            #pragma unroll
            for (int ntp = 0; ntp < 2; ntp++) {
                uint32_t off = (uint32_t)((wn * 32 + ntp * 16 + bnl) * HLD + k + bkl) * 2;
                ldsm4(bfh[ntp], sBh + off);
            }
            #pragma unroll
            for (int mt = 0; mt < 2; mt++) {
                uint32_t aoff = (uint32_t)((wm * 32 + mt * 16 + arow) * HLD + k + akoff) * 2;
                uint32_t af[4];
                ldsm4(af, sAh + aoff);
                #pragma unroll
                for (int nt = 0; nt < 4; nt++)
                    mma16816h(acc[mt][nt], af, &bfh[nt >> 1][(nt & 1) * 2]);
                ldsm4(af, sAl + aoff);
                #pragma unroll
                for (int nt = 0; nt < 4; nt++)
                    mma16816h(acc[mt][nt], af, &bfh[nt >> 1][(nt & 1) * 2]);
            }
        }
        __syncthreads();
    }

    #pragma unroll
    for (int mt = 0; mt < 2; mt++) {
        int row0 = bm + wm * 32 + mt * 16 + (lane >> 2);
        #pragma unroll
        for (int nt = 0; nt < 4; nt++) {
            int col = bn + wn * 32 + nt * 8 + (lane & 3) * 2;
            if (col < N) {
                *(float2*)&C[(size_t)row0 * N + col] =
                    make_float2(acc[mt][nt][0], acc[mt][nt][1]);
                *(float2*)&C[(size_t)(row0 + 8) * N + col] =
                    make_float2(acc[mt][nt][2], acc[mt][nt][3]);
            }
        }
    }
}

// --------- depthwise causal conv (k=4) + silu, smem-tiled (reads 1x) ---------
__global__ __launch_bounds__(256) void conv_silu_k(const float* __restrict__ cw,
                                                   const float* __restrict__ cb)
{
    int ct = blockIdx.x;           // 0..65  (CONVDIM/64)
    int lt = blockIdx.y;           // 0..31  (LL/128)
    int b  = blockIdx.z;
    int c0 = ct * 64, l0 = lt * 128;
    __shared__ float tile[131][64];
    int tid = threadIdx.x;
    int tc = tid & 63, tg = tid >> 6;   // channel-in-tile, group 0..3
    for (int r = tg; r < 131; r += 4) {
        int l = l0 + r - 3;
        float v = 0.f;
        if (l >= 0) v = g_zx[(size_t)(b * LL + l) * DPROJ + DIN + c0 + tc];
        tile[r][tc] = v;
    }
    __syncthreads();
    int ch = c0 + tc;
    float w0 = cw[ch * 4 + 0], w1 = cw[ch * 4 + 1];
    float w2 = cw[ch * 4 + 2], w3 = cw[ch * 4 + 3];
    float bias = cb[ch];
    #pragma unroll 4
    for (int i = 0; i < 32; i++) {
        int lr = tg * 32 + i;
        float acc = bias + tile[lr][tc] * w0 + tile[lr + 1][tc] * w1
                  + tile[lr + 2][tc] * w2 + tile[lr + 3][tc] * w3;
        g_xbc[(size_t)(b * LL + l0 + lr) * CONVDIM + ch] = acc / (1.f + __expf(-acc));
    }
}

// ------------------- per-chunk cumsum of dA (fused softplus + warp scan) -----
__global__ void cumsum_k(const float* __restrict__ A_log, const float* __restrict__ dt_bias)
{
    int bch = blockIdx.x;            // bc*NH + h
    int h = bch & 31, bc = bch >> 5;
    int b = bc / NCH, c = bc % NCH;
    int t = threadIdx.x;             // 32
    float Ah = -__expf(A_log[h]);
    float bias = dt_bias[h];
    size_t row0 = (size_t)(b * LL + c * CHUNK) + t * 8;
    float v[8];
    #pragma unroll
    for (int j = 0; j < 8; j++) {
        float x = g_zx[(row0 + j) * DPROJ + DIN + CONVDIM + h] + bias;
        float sp = (x > 20.f) ? x : log1pf(__expf(x));
        g_dt[(row0 + j) * NH + h] = sp;
        v[j] = sp * Ah;
    }
    float loc = 0.f;
    #pragma unroll
    for (int j = 0; j < 8; j++) { loc += v[j]; v[j] = loc; }
    float pre = loc;
    #pragma unroll
    for (int o = 1; o < 32; o <<= 1) {
        float nv = __shfl_up_sync(0xffffffffu, pre, o);
        if (t >= o) pre += nv;
    }
    pre -= loc;   // exclusive prefix
    #pragma unroll
    for (int j = 0; j < 8; j++) g_a[(bc * CHUNK + t * 8 + j) * NH + h] = pre + v[j];
    if (t == 31) g_alast[bc * NH + h] = pre + loc;
}

// ---------- scores = C @ B^T per chunk (lower tiles, tf32 MMA) ---------------
__global__ __launch_bounds__(256) void scores_k()
{
    int jt = blockIdx.x, it = blockIdx.y, bc = blockIdx.z;
    if (jt > it) return;
    int b = bc / NCH, c = bc % NCH;
    __shared__ float CtT[64 * 72];   // [n][r] k-major
    __shared__ float BtT[64 * 72];
    int tid = threadIdx.x;
    const int lane = tid & 31, wid = tid >> 5;
    const int gid = lane >> 2, tig = lane & 3;
    const int wm = wid >> 2, wn = wid & 3;   // 2m x 4n
    for (int t = tid; t < 64 * 64; t += 256) {
        int r = t >> 6, n = t & 63;
        int rowC = b * LL + c * CHUNK + it * 64 + r;
        int rowB = b * LL + c * CHUNK + jt * 64 + r;
        CtT[n * 72 + r] = g_xbc[(size_t)rowC * CONVDIM + DIN + DS + n];
        BtT[n * 72 + r] = g_xbc[(size_t)rowB * CONVDIM + DIN + n];
    }
    __syncthreads();
    float acc[2][2][4];
    #pragma unroll
    for (int mt = 0; mt < 2; mt++)
        #pragma unroll
        for (int nf = 0; nf < 2; nf++)
            #pragma unroll
            for (int i = 0; i < 4; i++) acc[mt][nf][i] = 0.f;
    #pragma unroll
    for (int ks = 0; ks < 8; ks++) {
        int k8 = ks * 8;
        uint32_t bfr[2][2];
        #pragma unroll
        for (int nf = 0; nf < 2; nf++) {
            int col = wn * 16 + nf * 8 + gid;
            bfr[nf][0] = f2tf(BtT[(k8 + tig)     * 72 + col]);
            bfr[nf][1] = f2tf(BtT[(k8 + tig + 4) * 72 + col]);
        }
        #pragma unroll
        for (int mt = 0; mt < 2; mt++) {
            int r0 = wm * 32 + mt * 16 + gid;
            uint32_t afr[4];
            afr[0] = f2tf(CtT[(k8 + tig)     * 72 + r0]);
            afr[1] = f2tf(CtT[(k8 + tig)     * 72 + r0 + 8]);
            afr[2] = f2tf(CtT[(k8 + tig + 4) * 72 + r0]);
            afr[3] = f2tf(CtT[(k8 + tig + 4) * 72 + r0 + 8]);
            #pragma unroll
            for (int nf = 0; nf < 2; nf++)
                mma_tf32(acc[mt][nf], afr, bfr[nf]);
        }
    }
    #pragma unroll
    for (int mt = 0; mt < 2; mt++)
        #pragma unroll
        for (int hf = 0; hf < 2; hf++) {
            int r = wm * 32 + mt * 16 + hf * 8 + gid;
            #pragma unroll
            for (int nf = 0; nf < 2; nf++) {
                int n = wn * 16 + nf * 8 + 2 * tig;
                *(float2*)&g_scores[((size_t)bc << 16) + (it * 64 + r) * 256 + jt * 64 + n] =
                    make_float2(acc[mt][nf][hf * 2], acc[mt][nf][hf * 2 + 1]);
            }
        }
}

// ------------- per-chunk states[h,p,n] = X^T @ Bco  (tf32 MMA) ---------------
__global__ __launch_bounds__(256) void states_k()
{
    int bch = blockIdx.x;              // bc*NH + h
    int h = bch % NH, bc = bch / NH;
    int b = bc / NCH, c = bc % NCH;
    __shared__ float sh[6688];
    float* Xs   = sh;                  // 32 x 136 (q-major, p cols)
    float* Bs   = sh + 4352;           // 32 x 72  (q-major, n cols)
    float* coef = sh + 6656;           // 32
    int tid = threadIdx.x;
    const int lane = tid & 31, wid = tid >> 5;
    const int gid = lane >> 2, tig = lane & 3;
    const int wm = wid & 3, wn = wid >> 2;    // 4m x 2n
    float alast = g_alast[bc * NH + h];
    float acc[2][4][4];
    #pragma unroll
    for (int mt = 0; mt < 2; mt++)
        #pragma unroll
        for (int nt = 0; nt < 4; nt++)
            #pragma unroll
            for (int i = 0; i < 4; i++) acc[mt][nt][i] = 0.f;

    for (int q0 = 0; q0 < CHUNK; q0 += 32) {
        __syncthreads();
        if (tid < 32) {
            int gq = q0 + tid;
            float aq = g_a[(bc * CHUNK + gq) * NH + h];
            float dtq = g_dt[(size_t)(b * LL + c * CHUNK + gq) * NH + h];
            coef[tid] = dtq * __expf(alast - aq);
        }
        #pragma unroll
        for (int t = 0; t < 16; t++) {
            int idx = tid + t * 256;
            int q = idx >> 7, p = idx & 127;
            Xs[q * 136 + p] = g_xbc[(size_t)(b * LL + c * CHUNK + q0 + q) * CONVDIM + h * HD + p];
        }
        __syncthreads();
        #pragma unroll
        for (int t = 0; t < 8; t++) {
            int idx = tid + t * 256;
            int q = idx >> 6, n = idx & 63;
            Bs[q * 72 + n] = g_xbc[(size_t)(b * LL + c * CHUNK + q0 + q) * CONVDIM + DIN + n] * coef[q];
        }
        __syncthreads();
        #pragma unroll
        for (int ks = 0; ks < 4; ks++) {
            int k8 = ks * 8;
            uint32_t bfr[4][2];
            #pragma unroll
            for (int ntf = 0; ntf < 4; ntf++) {
                int nb = wn * 32 + ntf * 8 + gid;
                bfr[ntf][0] = f2tf(Bs[(k8 + tig)     * 72 + nb]);
                bfr[ntf][1] = f2tf(Bs[(k8 + tig + 4) * 72 + nb]);
            }
            #pragma unroll
            for (int mt = 0; mt < 2; mt++) {
                int r0 = wm * 32 + mt * 16 + gid;
                uint32_t afr[4];
                afr[0] = f2tf(Xs[(k8 + tig)     * 136 + r0]);
                afr[1] = f2tf(Xs[(k8 + tig)     * 136 + r0 + 8]);
                afr[2] = f2tf(Xs[(k8 + tig + 4) * 136 + r0]);
                afr[3] = f2tf(Xs[(k8 + tig + 4) * 136 + r0 + 8]);
                #pragma unroll
                for (int ntf = 0; ntf < 4; ntf++)
                    mma_tf32(acc[mt][ntf], afr, bfr[ntf]);
            }
        }
    }
    size_t base = (size_t)bch * HD * DS;
    #pragma unroll
    for (int mt = 0; mt < 2; mt++)
        #pragma unroll
        for (int hf = 0; hf < 2; hf++) {
            int p = wm * 32 + mt * 16 + hf * 8 + gid;
            #pragma unroll
            for (int ntf = 0; ntf < 4; ntf++) {
                int n = wn * 32 + ntf * 8 + 2 * tig;
                *(float2*)&g_states[base + (size_t)p * DS + n] =
                    make_float2(acc[mt][ntf][hf * 2], acc[mt][ntf][hf * 2 + 1]);
            }
        }
}

// ------------------- sequential inter-chunk scan (split over 16 slices) ------
__global__ void scan_k()
{
    int bh = blockIdx.x;            // b*NH + h
    int b = bh >> 5, h = bh & 31;
    int e = blockIdx.y * 512 + threadIdx.x;   // element in HD*DS plane
    float s = 0.f;
    for (int c = 0; c < NCH; c++) {
        int bc = b * NCH + c;
        float dec = __expf(g_alast[bc * NH + h]);
        size_t base = (size_t)(bc * NH + h) * HD * DS;
        g_prev[base + e] = s;
        s = s * dec + g_states[base + e];
    }
}

// ------ y = intra + inter + D*x (tf32 MMA) + fused gate + per-head RMS -------
__global__ __launch_bounds__(256) void ych_k(const float* __restrict__ D_skip,
                                             const float* __restrict__ norm_w)
{
    int it = blockIdx.x;   // 0..3 (64-row tile)
    int h  = blockIdx.y;   // 0..31
    int bc = blockIdx.z;   // 0..31
    int b = bc / NCH, c = bc % NCH;
    __shared__ float sh[9088];
    float* ai    = sh;            // 64
    float* er    = sh + 64;       // 64
    float* Ab    = sh + 128;      // 4352: Wt[64][36] (p1) / Ct[64][68] (p2)
    float* Bb    = sh + 4480;     // 4352: Xt[32][136] (p1) / prevT[32][136] (p2)
    float* ssbuf = sh + 8832;     // 64*4
    int tid = threadIdx.x;
    const int lane = tid & 31, wid = tid >> 5;
    const int gid = lane >> 2, tig = lane & 3;
    const int wm = wid >> 2, wn = wid & 3;     // 2m x 4n
    int row0 = b * LL + c * CHUNK;
    float aref = g_a[(bc * CHUNK + it * 64) * NH + h];
    if (tid < 64) {
        float av = g_a[(bc * CHUNK + it * 64 + tid) * NH + h];
        ai[tid] = av;
        er[tid] = __expf(av - aref);
    }
    float accA[2][4][4], accB[2][4][4];
    #pragma unroll
    for (int mt = 0; mt < 2; mt++)
        #pragma unroll
        for (int nt = 0; nt < 4; nt++)
            #pragma unroll
            for (int i = 0; i < 4; i++) { accA[mt][nt][i] = 0.f; accB[mt][nt][i] = 0.f; }
    __syncthreads();

    // ================== phase 1: intra (K tiles of 32) ==================
    int jtmax = 2 * it + 1;
    for (int jt = 0; jt <= jtmax; jt++) {
        int j0 = jt * 32;
        if (jt < 2 * it) {
            int j = tid & 31;
            int gj = j0 + j;
            float ec = __expf(aref - g_a[(bc * CHUNK + gj) * NH + h]) *
                       g_dt[(size_t)(row0 + gj) * NH + h];
            #pragma unroll
            for (int t = 0; t < 8; t++) {
                int i = (tid >> 5) + t * 8;
                int gi = it * 64 + i;
                Ab[i * 36 + j] =
                    g_scores[((size_t)bc << 16) + gi * 256 + gj] * er[i] * ec;
            }
        } else {
            #pragma unroll
            for (int t = 0; t < 8; t++) {
                int idx = tid + t * 256;
                int i = idx >> 5, j = idx & 31;
                int gi = it * 64 + i, gj = j0 + j;
                float w = 0.f;
                if (gj <= gi) {
                    float aj = g_a[(bc * CHUNK + gj) * NH + h];
                    float dtj = g_dt[(size_t)(row0 + gj) * NH + h];
                    w = g_scores[((size_t)bc << 16) + gi * 256 + gj] * __expf(ai[i] - aj) * dtj;
                }
                Ab[i * 36 + j] = w;
            }
        }
        #pragma unroll
        for (int t = 0; t < 16; t++) {
            int idx = tid + t * 256;
            int j = idx >> 7, p = idx & 127;
            Bb[j * 136 + p] = g_xbc[(size_t)(row0 + j0 + j) * CONVDIM + h * HD + p];
        }
        __syncthreads();
        #pragma unroll
        for (int ks = 0; ks < 4; ks++) {
            uint32_t bfr[4][2];
            #pragma unroll
            for (int ntf = 0; ntf < 4; ntf++) {
                bfr[ntf][0] = f2tf(Bb[(ks*8 + tig)     * 136 + wn*32 + ntf*8 + gid]);
                bfr[ntf][1] = f2tf(Bb[(ks*8 + tig + 4) * 136 + wn*32 + ntf*8 + gid]);
            }
            #pragma unroll
            for (int mt = 0; mt < 2; mt++) {
                int r0 = wm*32 + mt*16 + gid;
                uint32_t afr[4];
                afr[0] = f2tf(Ab[ r0      * 36 + ks*8 + tig]);
                afr[1] = f2tf(Ab[(r0 + 8) * 36 + ks*8 + tig]);
                afr[2] = f2tf(Ab[ r0      * 36 + ks*8 + tig + 4]);
                afr[3] = f2tf(Ab[(r0 + 8) * 36 + ks*8 + tig + 4]);
                #pragma unroll
                for (int ntf = 0; ntf < 4; ntf++)
                    mma_tf32(accA[mt][ntf], afr, bfr[ntf]);
            }
        }
        __syncthreads();
    }

    // ================== phase 2: inter (K = 64, 2 tiles) ==================
    #pragma unroll
    for (int t = 0; t < 16; t++) {
        int idx = tid + t * 256;
        int i = idx >> 6, n = idx & 63;
        Ab[i * 68 + n] = g_xbc[(size_t)(row0 + it * 64 + i) * CONVDIM + DIN + DS + n];
    }
    size_t pbase = (size_t)(bc * NH + h) * HD * DS;
    for (int nt = 0; nt < 2; nt++) {
        int n0 = nt * 32;
        #pragma unroll
        for (int t = 0; t < 16; t++) {
            int idx = tid + t * 256;
            int p = idx >> 5, n = idx & 31;
            Bb[n * 136 + p] = g_prev[pbase + (size_t)p * DS + n0 + n];
        }
        __syncthreads();
        #pragma unroll
        for (int ks = 0; ks < 4; ks++) {
            uint32_t bfr[4][2];
            #pragma unroll
            for (int ntf = 0; ntf < 4; ntf++) {
                bfr[ntf][0] = f2tf(Bb[(ks*8 + tig)     * 136 + wn*32 + ntf*8 + gid]);
                bfr[ntf][1] = f2tf(Bb[(ks*8 + tig + 4) * 136 + wn*32 + ntf*8 + gid]);
            }
            #pragma unroll
            for (int mt = 0; mt < 2; mt++) {
                int r0 = wm*32 + mt*16 + gid;
                uint32_t afr[4];
                afr[0] = f2tf(Ab[ r0      * 68 + n0 + ks*8 + tig]);
                afr[1] = f2tf(Ab[(r0 + 8) * 68 + n0 + ks*8 + tig]);
                afr[2] = f2tf(Ab[ r0      * 68 + n0 + ks*8 + tig + 4]);
                afr[3] = f2tf(Ab[(r0 + 8) * 68 + n0 + ks*8 + tig + 4]);
                #pragma unroll
                for (int ntf = 0; ntf < 4; ntf++)
                    mma_tf32(accB[mt][ntf], afr, bfr[ntf]);
            }
        }
        __syncthreads();
    }

    // ====== epilogue: combine + D skip + gate + RMS (mma layout) ======
    float Dh = D_skip[h];
    #pragma unroll
    for (int mt = 0; mt < 2; mt++) {
        #pragma unroll
        for (int hf = 0; hf < 2; hf++) {
            int rl = wm*32 + mt*16 + hf*8 + gid;
            int gi = it * 64 + rl;
            float ea = __expf(ai[rl]);
            float ss = 0.f;
            #pragma unroll
            for (int ntf = 0; ntf < 4; ntf++) {
                int col = wn*32 + ntf*8 + 2*tig;
                float2 xv = *(const float2*)&g_xbc[(size_t)(row0 + gi) * CONVDIM + h * HD + col];
                float2 zv = *(const float2*)&g_zx[(size_t)(row0 + gi) * DPROJ + h * HD + col];
                float o0 = accA[mt][ntf][hf*2+0] + ea * accB[mt][ntf][hf*2+0] + Dh * xv.x;
                float o1 = accA[mt][ntf][hf*2+1] + ea * accB[mt][ntf][hf*2+1] + Dh * xv.y;
                float v0 = o0 / (1.f + __expf(-zv.x));
                float v1 = o1 / (1.f + __expf(-zv.y));
                accA[mt][ntf][hf*2+0] = v0;
                accA[mt][ntf][hf*2+1] = v1;
                ss += v0 * v0 + v1 * v1;
            }
            ss += __shfl_xor_sync(0xffffffffu, ss, 1);
            ss += __shfl_xor_sync(0xffffffffu, ss, 2);
            if (tig == 0) ssbuf[rl * 4 + wn] = ss;
        }
    }
    __syncthreads();
    #pragma unroll
    for (int mt = 0; mt < 2; mt++) {
        #pragma unroll
        for (int hf = 0; hf < 2; hf++) {
            int rl = wm*32 + mt*16 + hf*8 + gid;
            int gi = it * 64 + rl;
            float tot = ssbuf[rl*4+0] + ssbuf[rl*4+1] + ssbuf[rl*4+2] + ssbuf[rl*4+3];
            float inv = rsqrtf(tot * (1.f / HD) + 1e-6f);
            #pragma unroll
            for (int ntf = 0; ntf < 4; ntf++) {
                int col = wn*32 + ntf*8 + 2*tig;
                float2 nw = *(const float2*)&norm_w[h * HD + col];
                float r0 = accA[mt][ntf][hf*2+0] * inv * nw.x;
                float r1 = accA[mt][ntf][hf*2+1] * inv * nw.y;
                size_t oi = (size_t)(row0 + gi) * DIN + h * HD + col;
                __half h0 = __float2half(r0), h1 = __float2half(r1);
                *(__half2*)&g_ynh[oi] = __halves2half2(h0, h1);
                *(__half2*)&g_ynl[oi] = __halves2half2(
                    __float2half(r0 - __half2float(h0)),
                    __float2half(r1 - __half2float(h1)));
            }
        }
    }
}

// ------------------- launch ---------------------------------------------------
extern "C" void kernel_launch(void* const* d_in, const int* in_sizes, int n_in,
                              void* d_out, int out_size)
{
    const float* u         = (const float*)d_in[0];
    const float* in_proj_w = (const float*)d_in[1];
    const float* conv_w    = (const float*)d_in[2];
    const float* conv_b    = (const float*)d_in[3];
    const float* A_log     = (const float*)d_in[4];
    const float* dt_bias   = (const float*)d_in[5];
    const float* D_skip    = (const float*)d_in[6];
    const float* norm_w    = (const float*)d_in[7];
    const float* o_proj_w  = (const float*)d_in[8];
    float* out = (float*)d_out;

    float* zx = nullptr;
    cudaGetSymbolAddress((void**)&zx, g_zx);
    __half *uh, *ul, *w1h, *w2h, *ynh, *ynl;
    cudaGetSymbolAddress((void**)&uh,  g_uh);
    cudaGetSymbolAddress((void**)&ul,  g_ul);
    cudaGetSymbolAddress((void**)&w1h, g_w1h);
    cudaGetSymbolAddress((void**)&w2h, g_w2h);
    cudaGetSymbolAddress((void**)&ynh, g_ynh);
    cudaGetSymbolAddress((void**)&ynl, g_ynl);

    const int SMEM_GEMM = 2 * HSTAGEB;   // 110592
    cudaFuncSetAttribute(hgemm2, cudaFuncAttributeMaxDynamicSharedMemorySize, SMEM_GEMM);

    // Side streams + events (created once; resources only).
    static cudaStream_t sW2 = nullptr, sCS = nullptr, sSC = nullptr;
    static cudaEvent_t evStart, evW2, evZX, evCum, evXBC, evScores;
    if (!sW2) {
        cudaStreamCreateWithFlags(&sW2, cudaStreamNonBlocking);
        cudaStreamCreateWithFlags(&sCS, cudaStreamNonBlocking);
        cudaStreamCreateWithFlags(&sSC, cudaStreamNonBlocking);
        cudaEventCreateWithFlags(&evStart,  cudaEventDisableTiming);
        cudaEventCreateWithFlags(&evW2,     cudaEventDisableTiming);
        cudaEventCreateWithFlags(&evZX,     cudaEventDisableTiming);
        cudaEventCreateWithFlags(&evCum,    cudaEventDisableTiming);
        cudaEventCreateWithFlags(&evXBC,    cudaEventDisableTiming);
        cudaEventCreateWithFlags(&evScores, cudaEventDisableTiming);
    }

    const int M = BB * LL;   // 8192

    // fork point for the w2 convert (needed only by the final o_proj)
    cudaEventRecord(evStart, 0);
    cudaStreamWaitEvent(sW2, evStart, 0);
    {
        int n4 = (EMBED * DIN) / 4;
        cvt_h<<<(n4 + 255) / 256, 256, 0, sW2>>>(o_proj_w, w2h, n4);
        cudaEventRecord(evW2, sW2);
    }

    // critical path: split u (hi/lo), convert w1
    {
        int n4 = (M * EMBED) / 4;
        split2h<<<(n4 + 255) / 256, 256>>>(u, uh, ul, n4);
        n4 = (DPROJ * EMBED) / 4;
        cvt_h<<<(n4 + 255) / 256, 256>>>(in_proj_w, w1h, n4);
    }
    // 1) in_proj: zx = u @ W1^T  (HMMA fp16x2)
    hgemm2<<<dim3((DPROJ + HBN - 1) / HBN, M / HBM), 512, SMEM_GEMM>>>(
        M, DPROJ, EMBED, uh, ul, w1h, zx);
    cudaEventRecord(evZX, 0);

    // side: fused dt softplus + cumsum (depends only on zx)
    cudaStreamWaitEvent(sCS, evZX, 0);
    cumsum_k<<<NBC * NH, 32, 0, sCS>>>(A_log, dt_bias);
    cudaEventRecord(evCum, sCS);

    // 2) causal depthwise conv + silu (smem-tiled)
    conv_silu_k<<<dim3(CONVDIM / 64, LL / 128, BB), 256>>>(conv_w, conv_b);
    cudaEventRecord(evXBC, 0);

    // side: scores (depends only on xbc; feeds only ych)
    cudaStreamWaitEvent(sSC, evXBC, 0);
    scores_k<<<dim3(4, 4, NBC), 256, 0, sSC>>>();
    cudaEventRecord(evScores, sSC);

    // critical path: states (needs cumsum) -> scan
    cudaStreamWaitEvent(0, evCum, 0);
    states_k<<<NBC * NH, 256>>>();
    scan_k<<<dim3(BB * NH, 16), 512>>>();

    // join scores, then ych
    cudaStreamWaitEvent(0, evScores, 0);
    ych_k<<<dim3(4, NH, NBC), 256>>>(D_skip, norm_w);

    // join w2 convert, then o_proj
    cudaStreamWaitEvent(0, evW2, 0);
    hgemm2<<<dim3(EMBED / HBN, M / HBM), 512, SMEM_GEMM>>>(
        M, EMBED, DIN, ynh, ynl, w2h, out);
}

// round 16
// speedup vs baseline: 1.6636x; 1.0259x over previous
#include <cuda_runtime.h>
#include <cuda_bf16.h>
#include <cuda_fp16.h>
#include <cstdint>

#define BB 2
#define LL 4096
#define EMBED 2048
#define DIN 4096
#define NH 32
#define HD 128
#define DS 64
#define CONVDIM 4224   // DIN + 2*DS
#define DPROJ 8352     // 2*DIN + 2*DS + NH
#define CHUNK 256
#define NCH 16         // LL / CHUNK
#define NBC (BB*NCH)   // 32

// ------------------- scratch (device globals; no cudaMalloc allowed) ---------
__device__ float g_zx[(size_t)BB*LL*DPROJ];        // in_proj output
__device__ float g_xbc[(size_t)BB*LL*CONVDIM];     // conv+silu output
__device__ float g_dt[BB*LL*NH];                   // softplus(dt)
__device__ float g_a[NBC*CHUNK*NH];                // cumsum(dA) per chunk
__device__ float g_alast[NBC*NH];
__device__ float g_scores[(size_t)NBC*CHUNK*CHUNK];
__device__ float g_states[(size_t)NBC*NH*HD*DS];   // [b,c,h,p,n]
__device__ float g_prev[(size_t)NBC*NH*HD*DS];     // state entering chunk c

// fp16 hi/lo (activations) and fp16 (weights) buffers
__device__ __half g_uh[(size_t)BB*LL*EMBED];
__device__ __half g_ul[(size_t)BB*LL*EMBED];
__device__ __half g_w1h[(size_t)DPROJ*EMBED];
__device__ __half g_w2h[(size_t)EMBED*DIN];
__device__ __half g_ynh[(size_t)BB*LL*DIN];
__device__ __half g_ynl[(size_t)BB*LL*DIN];

// ------------------- PTX helpers (sm_80-era: valid on base sm_103 target) ----
__device__ __forceinline__ uint32_t s2u(const void* p) {
    uint32_t a;
    asm("{ .reg .u64 t; cvta.to.shared.u64 t, %1; cvt.u32.u64 %0, t; }" : "=r"(a) : "l"(p));
    return a;
}
__device__ __forceinline__ void cpasync16(uint32_t s, const void* g, int srcsize) {
    asm volatile("cp.async.cg.shared.global [%0], [%1], 16, %2;"
                 :: "r"(s), "l"(g), "r"(srcsize));
}
__device__ __forceinline__ void cpcommit() {
    asm volatile("cp.async.commit_group;" ::: "memory");
}
template <int N>
__device__ __forceinline__ void cpwait() {
    asm volatile("cp.async.wait_group %0;" :: "n"(N) : "memory");
}
__device__ __forceinline__ void ldsm4(uint32_t* r, uint32_t addr) {
    asm volatile("ldmatrix.sync.aligned.m8n8.x4.shared.b16 {%0,%1,%2,%3}, [%4];"
                 : "=r"(r[0]), "=r"(r[1]), "=r"(r[2]), "=r"(r[3]) : "r"(addr));
}
__device__ __forceinline__ void mma16816h(float* c, const uint32_t* a, const uint32_t* b) {
    asm volatile(
        "mma.sync.aligned.m16n8k16.row.col.f32.f16.f16.f32 "
        "{%0,%1,%2,%3},{%4,%5,%6,%7},{%8,%9},{%0,%1,%2,%3};"
        : "+f"(c[0]), "+f"(c[1]), "+f"(c[2]), "+f"(c[3])
        : "r"(a[0]), "r"(a[1]), "r"(a[2]), "r"(a[3]), "r"(b[0]), "r"(b[1]));
}
__device__ __forceinline__ void mma_tf32(float* d, const uint32_t* a, const uint32_t* b) {
    asm volatile(
        "mma.sync.aligned.m16n8k8.row.col.f32.tf32.tf32.f32 "
        "{%0,%1,%2,%3},{%4,%5,%6,%7},{%8,%9},{%0,%1,%2,%3};"
        : "+f"(d[0]), "+f"(d[1]), "+f"(d[2]), "+f"(d[3])
        : "r"(a[0]), "r"(a[1]), "r"(a[2]), "r"(a[3]), "r"(b[0]), "r"(b[1]));
}
__device__ __forceinline__ uint32_t f2tf(float x) {
    uint32_t r; asm("cvt.rna.tf32.f32 %0, %1;" : "=r"(r) : "f"(x)); return r;
}

// ------------------- fp32 -> fp16 hi/lo split (activations) ------------------
__global__ void split2h(const float* __restrict__ s, __half* __restrict__ hi,
                        __half* __restrict__ lo, int n4)
{
    int i = blockIdx.x * 256 + threadIdx.x;
    if (i >= n4) return;
    float4 v = ((const float4*)s)[i];
    __half h0 = __float2half(v.x), h1 = __float2half(v.y);
    __half h2 = __float2half(v.z), h3 = __float2half(v.w);
    __half2* H = (__half2*)hi;
    __half2* L = (__half2*)lo;
    H[i*2+0] = __halves2half2(h0, h1);
    H[i*2+1] = __halves2half2(h2, h3);
    L[i*2+0] = __halves2half2(__float2half(v.x - __half2float(h0)),
                              __float2half(v.y - __half2float(h1)));
    L[i*2+1] = __halves2half2(__float2half(v.z - __half2float(h2)),
                              __float2half(v.w - __half2float(h3)));
}

// ------------------- fp32 -> fp16 convert (weights) --------------------------
__global__ void cvt_h(const float* __restrict__ s, __half* __restrict__ d, int n4)
{
    int i = blockIdx.x * 256 + threadIdx.x;
    if (i >= n4) return;
    float4 v = ((const float4*)s)[i];
    __half2* D = (__half2*)d;
    D[i*2+0] = __halves2half2(__float2half(v.x), __float2half(v.y));
    D[i*2+1] = __halves2half2(__float2half(v.z), __float2half(v.w));
}

// ------------- HMMA fp16x2 GEMM: C[M,N] = (Ah+Al)[M,K] @ Bh[N,K]^T -----------
// CTA tile 128x128, BK=64, 512 threads = 4x4 warps, warp tile 32x32.
// 3 matrices/stage, 2 MMA passes, 2 CTAs/SM. cp.async.cg (L1-bypass fills).
#define HBM 128
#define HBN 128
#define HBK 64
#define HLD 72
#define HMATB (128*HLD*2)            // 18432
#define HSTAGEB (3*HMATB)            // 55296

__global__ __launch_bounds__(512) void hgemm2(
    int M, int N, int K,
    const __half* __restrict__ Ah, const __half* __restrict__ Al,
    const __half* __restrict__ Bh, float* __restrict__ C)
{
    extern __shared__ char smem[];
    const int tid = threadIdx.x;
    const int lane = tid & 31, wid = tid >> 5;
    const int wm = wid & 3, wn = wid >> 2;
    const int bm = blockIdx.y * HBM, bn = blockIdx.x * HBN;
    const uint32_t sbase = s2u(smem);

    const int arow = lane & 15, akoff = (lane >> 4) << 3;
    const int bnl = (lane & 7) + ((lane >> 4) << 3);
    const int bkl = ((lane >> 3) & 1) << 3;

    float acc[2][4][4];
    #pragma unroll
    for (int mt = 0; mt < 2; mt++)
        #pragma unroll
        for (int nt = 0; nt < 4; nt++)
            #pragma unroll
            for (int i = 0; i < 4; i++) acc[mt][nt][i] = 0.f;

    const int nk = K / HBK;

    auto load_stage = [&](int st, int k0) {
        uint32_t sb = sbase + st * HSTAGEB;
        #pragma unroll
        for (int i = 0; i < 2; i++) {
            int chunk = tid + i * 512;
            int row = chunk >> 3, c = chunk & 7;
            uint32_t so = (uint32_t)(row * HLD + c * 8) * 2;
            size_t ga = (size_t)(bm + row) * K + k0 + c * 8;
            cpasync16(sb + so,             Ah + ga, 16);
            cpasync16(sb + HMATB + so,     Al + ga, 16);
            int brow = bn + row;
            int sz = (brow < N) ? 16 : 0;
            int bcl = (brow < N) ? brow : 0;
            size_t gb = (size_t)bcl * K + k0 + c * 8;
            cpasync16(sb + 2*HMATB + so,   Bh + gb, sz);
        }
        cpcommit();
    };

    load_stage(0, 0);

    for (int kt = 0; kt < nk; ++kt) {
        if (kt + 1 < nk) {
            load_stage((kt + 1) & 1, (kt + 1) * HBK);
            cpwait<1>();
        } else {
            cpwait<0>();
        }
        __syncthreads();

        uint32_t sb = sbase + (kt & 1) * HSTAGEB;
        uint32_t sAh = sb, sAl = sb + HMATB, sBh = sb + 2*HMATB;

        #pragma unroll
        for (int kh = 0; kh < 4; kh++) {
            int k = kh * 16;
            uint32_t bfh[2][4];
            #pragma unroll
            for (int ntp = 0; ntp < 2; ntp++) {
                uint32_t off = (uint32_t)((wn * 32 + ntp * 16 + bnl) * HLD + k + bkl) * 2;
                ldsm4(bfh[ntp], sBh + off);
            }
            #pragma unroll
            for (int mt = 0; mt < 2; mt++) {
                uint32_t aoff = (uint32_t)((wm * 32 + mt * 16 + arow) * HLD + k + akoff) * 2;
                uint32_t af[4];
                ldsm4(af, sAh + aoff);
                #pragma unroll
                for (int nt = 0; nt < 4; nt++)
                    mma16816h(acc[mt][nt], af, &bfh[nt >> 1][(nt & 1) * 2]);
                ldsm4(af, sAl + aoff);
                #pragma unroll
                for (int nt = 0; nt < 4; nt++)
                    mma16816h(acc[mt][nt], af, &bfh[nt >> 1][(nt & 1) * 2]);
            }
        }
        __syncthreads();
    }

    #pragma unroll
    for (int mt = 0; mt < 2; mt++) {
        int row0 = bm + wm * 32 + mt * 16 + (lane >> 2);
        #pragma unroll
        for (int nt = 0; nt < 4; nt++) {
            int col = bn + wn * 32 + nt * 8 + (lane & 3) * 2;
            if (col < N) {
                *(float2*)&C[(size_t)row0 * N + col] =
                    make_float2(acc[mt][nt][0], acc[mt][nt][1]);
                *(float2*)&C[(size_t)(row0 + 8) * N + col] =
                    make_float2(acc[mt][nt][2], acc[mt][nt][3]);
            }
        }
    }
}

// --------- depthwise causal conv (k=4) + silu, smem-tiled (reads 1x) ---------
__global__ __launch_bounds__(256) void conv_silu_k(const float* __restrict__ cw,
                                                   const float* __restrict__ cb)
{
    int ct = blockIdx.x;           // 0..65  (CONVDIM/64)
    int lt = blockIdx.y;           // 0..31  (LL/128)
    int b  = blockIdx.z;
    int c0 = ct * 64, l0 = lt * 128;
    __shared__ float tile[131][64];
    int tid = threadIdx.x;
    int tc = tid & 63, tg = tid >> 6;   // channel-in-tile, group 0..3
    for (int r = tg; r < 131; r += 4) {
        int l = l0 + r - 3;
        float v = 0.f;
        if (l >= 0) v = g_zx[(size_t)(b * LL + l) * DPROJ + DIN + c0 + tc];
        tile[r][tc] = v;
    }
    __syncthreads();
    int ch = c0 + tc;
    float w0 = cw[ch * 4 + 0], w1 = cw[ch * 4 + 1];
    float w2 = cw[ch * 4 + 2], w3 = cw[ch * 4 + 3];
    float bias = cb[ch];
    #pragma unroll 4
    for (int i = 0; i < 32; i++) {
        int lr = tg * 32 + i;
        float acc = bias + tile[lr][tc] * w0 + tile[lr + 1][tc] * w1
                  + tile[lr + 2][tc] * w2 + tile[lr + 3][tc] * w3;
        g_xbc[(size_t)(b * LL + l0 + lr) * CONVDIM + ch] = acc / (1.f + __expf(-acc));
    }
}

// ------------------- per-chunk cumsum of dA (fused softplus + warp scan) -----
__global__ void cumsum_k(const float* __restrict__ A_log, const float* __restrict__ dt_bias)
{
    int bch = blockIdx.x;            // bc*NH + h
    int h = bch & 31, bc = bch >> 5;
    int b = bc / NCH, c = bc % NCH;
    int t = threadIdx.x;             // 32
    float Ah = -__expf(A_log[h]);
    float bias = dt_bias[h];
    size_t row0 = (size_t)(b * LL + c * CHUNK) + t * 8;
    float v[8];
    #pragma unroll
    for (int j = 0; j < 8; j++) {
        float x = g_zx[(row0 + j) * DPROJ + DIN + CONVDIM + h] + bias;
        float sp = (x > 20.f) ? x : log1pf(__expf(x));
        g_dt[(row0 + j) * NH + h] = sp;
        v[j] = sp * Ah;
    }
    float loc = 0.f;
    #pragma unroll
    for (int j = 0; j < 8; j++) { loc += v[j]; v[j] = loc; }
    float pre = loc;
    #pragma unroll
    for (int o = 1; o < 32; o <<= 1) {
        float nv = __shfl_up_sync(0xffffffffu, pre, o);
        if (t >= o) pre += nv;
    }
    pre -= loc;   // exclusive prefix
    #pragma unroll
    for (int j = 0; j < 8; j++) g_a[(bc * CHUNK + t * 8 + j) * NH + h] = pre + v[j];
    if (t == 31) g_alast[bc * NH + h] = pre + loc;
}

// ---------- scores = C @ B^T per chunk (lower tiles, tf32 MMA) ---------------
__global__ __launch_bounds__(256) void scores_k()
{
    int jt = blockIdx.x, it = blockIdx.y, bc = blockIdx.z;
    if (jt > it) return;
    int b = bc / NCH, c = bc % NCH;
    __shared__ float CtT[64 * 72];   // [n][r] k-major
    __shared__ float BtT[64 * 72];
    int tid = threadIdx.x;
    const int lane = tid & 31, wid = tid >> 5;
    const int gid = lane >> 2, tig = lane & 3;
    const int wm = wid >> 2, wn = wid & 3;   // 2m x 4n
    for (int t = tid; t < 64 * 64; t += 256) {
        int r = t >> 6, n = t & 63;
        int rowC = b * LL + c * CHUNK + it * 64 + r;
        int rowB = b * LL + c * CHUNK + jt * 64 + r;
        CtT[n * 72 + r] = g_xbc[(size_t)rowC * CONVDIM + DIN + DS + n];
        BtT[n * 72 + r] = g_xbc[(size_t)rowB * CONVDIM + DIN + n];
    }
    __syncthreads();
    float acc[2][2][4];
    #pragma unroll
    for (int mt = 0; mt < 2; mt++)
        #pragma unroll
        for (int nf = 0; nf < 2; nf++)
            #pragma unroll
            for (int i = 0; i < 4; i++) acc[mt][nf][i] = 0.f;
    #pragma unroll
    for (int ks = 0; ks < 8; ks++) {
        int k8 = ks * 8;
        uint32_t bfr[2][2];
        #pragma unroll
        for (int nf = 0; nf < 2; nf++) {
            int col = wn * 16 + nf * 8 + gid;
            bfr[nf][0] = f2tf(BtT[(k8 + tig)     * 72 + col]);
            bfr[nf][1] = f2tf(BtT[(k8 + tig + 4) * 72 + col]);
        }
        #pragma unroll
        for (int mt = 0; mt < 2; mt++) {
            int r0 = wm * 32 + mt * 16 + gid;
            uint32_t afr[4];
            afr[0] = f2tf(CtT[(k8 + tig)     * 72 + r0]);
            afr[1] = f2tf(CtT[(k8 + tig)     * 72 + r0 + 8]);
            afr[2] = f2tf(CtT[(k8 + tig + 4) * 72 + r0]);
            afr[3] = f2tf(CtT[(k8 + tig + 4) * 72 + r0 + 8]);
            #pragma unroll
            for (int nf = 0; nf < 2; nf++)
                mma_tf32(acc[mt][nf], afr, bfr[nf]);
        }
    }
    #pragma unroll
    for (int mt = 0; mt < 2; mt++)
        #pragma unroll
        for (int hf = 0; hf < 2; hf++) {
            int r = wm * 32 + mt * 16 + hf * 8 + gid;
            #pragma unroll
            for (int nf = 0; nf < 2; nf++) {
                int n = wn * 16 + nf * 8 + 2 * tig;
                *(float2*)&g_scores[((size_t)bc << 16) + (it * 64 + r) * 256 + jt * 64 + n] =
                    make_float2(acc[mt][nf][hf * 2], acc[mt][nf][hf * 2 + 1]);
            }
        }
}

// ------------- per-chunk states[h,p,n] = X^T @ Bco  (tf32 MMA) ---------------
__global__ __launch_bounds__(256) void states_k()
{
    int bch = blockIdx.x;              // bc*NH + h
    int h = bch % NH, bc = bch / NH;
    int b = bc / NCH, c = bc % NCH;
    __shared__ float sh[6688];
    float* Xs   = sh;                  // 32 x 136 (q-major, p cols)
    float* Bs   = sh + 4352;           // 32 x 72  (q-major, n cols)
    float* coef = sh + 6656;           // 32
    int tid = threadIdx.x;
    const int lane = tid & 31, wid = tid >> 5;
    const int gid = lane >> 2, tig = lane & 3;
    const int wm = wid & 3, wn = wid >> 2;    // 4m x 2n
    float alast = g_alast[bc * NH + h];
    float acc[2][4][4];
    #pragma unroll
    for (int mt = 0; mt < 2; mt++)
        #pragma unroll
        for (int nt = 0; nt < 4; nt++)
            #pragma unroll
            for (int i = 0; i < 4; i++) acc[mt][nt][i] = 0.f;

    for (int q0 = 0; q0 < CHUNK; q0 += 32) {
        __syncthreads();
        if (tid < 32) {
            int gq = q0 + tid;
            float aq = g_a[(bc * CHUNK + gq) * NH + h];
            float dtq = g_dt[(size_t)(b * LL + c * CHUNK + gq) * NH + h];
            coef[tid] = dtq * __expf(alast - aq);
        }
        #pragma unroll
        for (int t = 0; t < 16; t++) {
            int idx = tid + t * 256;
            int q = idx >> 7, p = idx & 127;
            Xs[q * 136 + p] = g_xbc[(size_t)(b * LL + c * CHUNK + q0 + q) * CONVDIM + h * HD + p];
        }
        __syncthreads();
        #pragma unroll
        for (int t = 0; t < 8; t++) {
            int idx = tid + t * 256;
            int q = idx >> 6, n = idx & 63;
            Bs[q * 72 + n] = g_xbc[(size_t)(b * LL + c * CHUNK + q0 + q) * CONVDIM + DIN + n] * coef[q];
        }
        __syncthreads();
        #pragma unroll
        for (int ks = 0; ks < 4; ks++) {
            int k8 = ks * 8;
            uint32_t bfr[4][2];
            #pragma unroll
            for (int ntf = 0; ntf < 4; ntf++) {
                int nb = wn * 32 + ntf * 8 + gid;
                bfr[ntf][0] = f2tf(Bs[(k8 + tig)     * 72 + nb]);
                bfr[ntf][1] = f2tf(Bs[(k8 + tig + 4) * 72 + nb]);
            }
            #pragma unroll
            for (int mt = 0; mt < 2; mt++) {
                int r0 = wm * 32 + mt * 16 + gid;
                uint32_t afr[4];
                afr[0] = f2tf(Xs[(k8 + tig)     * 136 + r0]);
                afr[1] = f2tf(Xs[(k8 + tig)     * 136 + r0 + 8]);
                afr[2] = f2tf(Xs[(k8 + tig + 4) * 136 + r0]);
                afr[3] = f2tf(Xs[(k8 + tig + 4) * 136 + r0 + 8]);
                #pragma unroll
                for (int ntf = 0; ntf < 4; ntf++)
                    mma_tf32(acc[mt][ntf], afr, bfr[ntf]);
            }
        }
    }
    size_t base = (size_t)bch * HD * DS;
    #pragma unroll
    for (int mt = 0; mt < 2; mt++)
        #pragma unroll
        for (int hf = 0; hf < 2; hf++) {
            int p = wm * 32 + mt * 16 + hf * 8 + gid;
            #pragma unroll
            for (int ntf = 0; ntf < 4; ntf++) {
                int n = wn * 32 + ntf * 8 + 2 * tig;
                *(float2*)&g_states[base + (size_t)p * DS + n] =
                    make_float2(acc[mt][ntf][hf * 2], acc[mt][ntf][hf * 2 + 1]);
            }
        }
}

// ------------------- sequential inter-chunk scan (split over 16 slices) ------
__global__ void scan_k()
{
    int bh = blockIdx.x;            // b*NH + h
    int b = bh >> 5, h = bh & 31;
    int e = blockIdx.y * 512 + threadIdx.x;   // element in HD*DS plane
    float s = 0.f;
    for (int c = 0; c < NCH; c++) {
        int bc = b * NCH + c;
        float dec = __expf(g_alast[bc * NH + h]);
        size_t base = (size_t)(bc * NH + h) * HD * DS;
        g_prev[base + e] = s;
        s = s * dec + g_states[base + e];
    }
}

// ------ y = intra + inter + D*x (tf32 MMA) + fused gate + per-head RMS -------
__global__ __launch_bounds__(256) void ych_k(const float* __restrict__ D_skip,
                                             const float* __restrict__ norm_w)
{
    int it = blockIdx.x;   // 0..3 (64-row tile)
    int h  = blockIdx.y;   // 0..31
    int bc = blockIdx.z;   // 0..31
    int b = bc / NCH, c = bc % NCH;
    __shared__ float sh[9088];
    float* ai    = sh;            // 64
    float* er    = sh + 64;       // 64
    float* Ab    = sh + 128;      // 4352: Wt[64][36] (p1) / Ct[64][68] (p2)
    float* Bb    = sh + 4480;     // 4352: Xt[32][136] (p1) / prevT[32][136] (p2)
    float* ssbuf = sh + 8832;     // 64*4
    int tid = threadIdx.x;
    const int lane = tid & 31, wid = tid >> 5;
    const int gid = lane >> 2, tig = lane & 3;
    const int wm = wid >> 2, wn = wid & 3;     // 2m x 4n
    int row0 = b * LL + c * CHUNK;
    float aref = g_a[(bc * CHUNK + it * 64) * NH + h];
    if (tid < 64) {
        float av = g_a[(bc * CHUNK + it * 64 + tid) * NH + h];
        ai[tid] = av;
        er[tid] = __expf(av - aref);
    }
    float accA[2][4][4], accB[2][4][4];
    #pragma unroll
    for (int mt = 0; mt < 2; mt++)
        #pragma unroll
        for (int nt = 0; nt < 4; nt++)
            #pragma unroll
            for (int i = 0; i < 4; i++) { accA[mt][nt][i] = 0.f; accB[mt][nt][i] = 0.f; }
    __syncthreads();

    // ================== phase 1: intra (K tiles of 32) ==================
    int jtmax = 2 * it + 1;
    for (int jt = 0; jt <= jtmax; jt++) {
        int j0 = jt * 32;
        if (jt < 2 * it) {
            int j = tid & 31;
            int gj = j0 + j;
            float ec = __expf(aref - g_a[(bc * CHUNK + gj) * NH + h]) *
                       g_dt[(size_t)(row0 + gj) * NH + h];
            #pragma unroll
            for (int t = 0; t < 8; t++) {
                int i = (tid >> 5) + t * 8;
                int gi = it * 64 + i;
                Ab[i * 36 + j] =
                    g_scores[((size_t)bc << 16) + gi * 256 + gj] * er[i] * ec;
            }
        } else {
            #pragma unroll
            for (int t = 0; t < 8; t++) {
                int idx = tid + t * 256;
                int i = idx >> 5, j = idx & 31;
                int gi = it * 64 + i, gj = j0 + j;
                float w = 0.f;
                if (gj <= gi) {
                    float aj = g_a[(bc * CHUNK + gj) * NH + h];
                    float dtj = g_dt[(size_t)(row0 + gj) * NH + h];
                    w = g_scores[((size_t)bc << 16) + gi * 256 + gj] * __expf(ai[i] - aj) * dtj;
                }
                Ab[i * 36 + j] = w;
            }
        }
        #pragma unroll
        for (int t = 0; t < 16; t++) {
            int idx = tid + t * 256;
            int j = idx >> 7, p = idx & 127;
            Bb[j * 136 + p] = g_xbc[(size_t)(row0 + j0 + j) * CONVDIM + h * HD + p];
        }
        __syncthreads();
        #pragma unroll
        for (int ks = 0; ks < 4; ks++) {
            uint32_t bfr[4][2];
            #pragma unroll
            for (int ntf = 0; ntf < 4; ntf++) {
                bfr[ntf][0] = f2tf(Bb[(ks*8 + tig)     * 136 + wn*32 + ntf*8 + gid]);
                bfr[ntf][1] = f2tf(Bb[(ks*8 + tig + 4) * 136 + wn*32 + ntf*8 + gid]);
            }
            #pragma unroll
            for (int mt = 0; mt < 2; mt++) {
                int r0 = wm*32 + mt*16 + gid;
                uint32_t afr[4];
                afr[0] = f2tf(Ab[ r0      * 36 + ks*8 + tig]);
                afr[1] = f2tf(Ab[(r0 + 8) * 36 + ks*8 + tig]);
                afr[2] = f2tf(Ab[ r0      * 36 + ks*8 + tig + 4]);
                afr[3] = f2tf(Ab[(r0 + 8) * 36 + ks*8 + tig + 4]);
                #pragma unroll
                for (int ntf = 0; ntf < 4; ntf++)
                    mma_tf32(accA[mt][ntf], afr, bfr[ntf]);
            }
        }
        __syncthreads();
    }

    // ================== phase 2: inter (K = 64, 2 tiles) ==================
    #pragma unroll
    for (int t = 0; t < 16; t++) {
        int idx = tid + t * 256;
        int i = idx >> 6, n = idx & 63;
        Ab[i * 68 + n] = g_xbc[(size_t)(row0 + it * 64 + i) * CONVDIM + DIN + DS + n];
    }
    size_t pbase = (size_t)(bc * NH + h) * HD * DS;
    for (int nt = 0; nt < 2; nt++) {
        int n0 = nt * 32;
        #pragma unroll
        for (int t = 0; t < 16; t++) {
            int idx = tid + t * 256;
            int p = idx >> 5, n = idx & 31;
            Bb[n * 136 + p] = g_prev[pbase + (size_t)p * DS + n0 + n];
        }
        __syncthreads();
        #pragma unroll
        for (int ks = 0; ks < 4; ks++) {
            uint32_t bfr[4][2];
            #pragma unroll
            for (int ntf = 0; ntf < 4; ntf++) {
                bfr[ntf][0] = f2tf(Bb[(ks*8 + tig)     * 136 + wn*32 + ntf*8 + gid]);
                bfr[ntf][1] = f2tf(Bb[(ks*8 + tig + 4) * 136 + wn*32 + ntf*8 + gid]);
            }
            #pragma unroll
            for (int mt = 0; mt < 2; mt++) {
                int r0 = wm*32 + mt*16 + gid;
                uint32_t afr[4];
                afr[0] = f2tf(Ab[ r0      * 68 + n0 + ks*8 + tig]);
                afr[1] = f2tf(Ab[(r0 + 8) * 68 + n0 + ks*8 + tig]);
                afr[2] = f2tf(Ab[ r0      * 68 + n0 + ks*8 + tig + 4]);
                afr[3] = f2tf(Ab[(r0 + 8) * 68 + n0 + ks*8 + tig + 4]);
                #pragma unroll
                for (int ntf = 0; ntf < 4; ntf++)
                    mma_tf32(accB[mt][ntf], afr, bfr[ntf]);
            }
        }
        __syncthreads();
    }

    // ====== epilogue: combine + D skip + gate + RMS (mma layout) ======
    float Dh = D_skip[h];
    #pragma unroll
    for (int mt = 0; mt < 2; mt++) {
        #pragma unroll
        for (int hf = 0; hf < 2; hf++) {
            int rl = wm*32 + mt*16 + hf*8 + gid;
            int gi = it * 64 + rl;
            float ea = __expf(ai[rl]);
            float ss = 0.f;
            #pragma unroll
            for (int ntf = 0; ntf < 4; ntf++) {
                int col = wn*32 + ntf*8 + 2*tig;
                float2 xv = *(const float2*)&g_xbc[(size_t)(row0 + gi) * CONVDIM + h * HD + col];
                float2 zv = *(const float2*)&g_zx[(size_t)(row0 + gi) * DPROJ + h * HD + col];
                float o0 = accA[mt][ntf][hf*2+0] + ea * accB[mt][ntf][hf*2+0] + Dh * xv.x;
                float o1 = accA[mt][ntf][hf*2+1] + ea * accB[mt][ntf][hf*2+1] + Dh * xv.y;
                float v0 = o0 / (1.f + __expf(-zv.x));
                float v1 = o1 / (1.f + __expf(-zv.y));
                accA[mt][ntf][hf*2+0] = v0;
                accA[mt][ntf][hf*2+1] = v1;
                ss += v0 * v0 + v1 * v1;
            }
            ss += __shfl_xor_sync(0xffffffffu, ss, 1);
            ss += __shfl_xor_sync(0xffffffffu, ss, 2);
            if (tig == 0) ssbuf[rl * 4 + wn] = ss;
        }
    }
    __syncthreads();
    #pragma unroll
    for (int mt = 0; mt < 2; mt++) {
        #pragma unroll
        for (int hf = 0; hf < 2; hf++) {
            int rl = wm*32 + mt*16 + hf*8 + gid;
            int gi = it * 64 + rl;
            float tot = ssbuf[rl*4+0] + ssbuf[rl*4+1] + ssbuf[rl*4+2] + ssbuf[rl*4+3];
            float inv = rsqrtf(tot * (1.f / HD) + 1e-6f);
            #pragma unroll
            for (int ntf = 0; ntf < 4; ntf++) {
                int col = wn*32 + ntf*8 + 2*tig;
                float2 nw = *(const float2*)&norm_w[h * HD + col];
                float r0 = accA[mt][ntf][hf*2+0] * inv * nw.x;
                float r1 = accA[mt][ntf][hf*2+1] * inv * nw.y;
                size_t oi = (size_t)(row0 + gi) * DIN + h * HD + col;
                __half h0 = __float2half(r0), h1 = __float2half(r1);
                *(__half2*)&g_ynh[oi] = __halves2half2(h0, h1);
                *(__half2*)&g_ynl[oi] = __halves2half2(
                    __float2half(r0 - __half2float(h0)),
                    __float2half(r1 - __half2float(h1)));
            }
        }
    }
}

// ------------------- launch ---------------------------------------------------
extern "C" void kernel_launch(void* const* d_in, const int* in_sizes, int n_in,
                              void* d_out, int out_size)
{
    const float* u         = (const float*)d_in[0];
    const float* in_proj_w = (const float*)d_in[1];
    const float* conv_w    = (const float*)d_in[2];
    const float* conv_b    = (const float*)d_in[3];
    const float* A_log     = (const float*)d_in[4];
    const float* dt_bias   = (const float*)d_in[5];
    const float* D_skip    = (const float*)d_in[6];
    const float* norm_w    = (const float*)d_in[7];
    const float* o_proj_w  = (const float*)d_in[8];
    float* out = (float*)d_out;

    float* zx = nullptr;
    cudaGetSymbolAddress((void**)&zx, g_zx);
    __half *uh, *ul, *w1h, *w2h, *ynh, *ynl;
    cudaGetSymbolAddress((void**)&uh,  g_uh);
    cudaGetSymbolAddress((void**)&ul,  g_ul);
    cudaGetSymbolAddress((void**)&w1h, g_w1h);
    cudaGetSymbolAddress((void**)&w2h, g_w2h);
    cudaGetSymbolAddress((void**)&ynh, g_ynh);
    cudaGetSymbolAddress((void**)&ynl, g_ynl);

    const int SMEM_GEMM = 2 * HSTAGEB;   // 110592
    cudaFuncSetAttribute(hgemm2, cudaFuncAttributeMaxDynamicSharedMemorySize, SMEM_GEMM);

    // Side streams + events (created once; resources only).
    static cudaStream_t sW2 = nullptr, sCS = nullptr, sSC = nullptr;
    static cudaEvent_t evStart, evW2, evZX, evCum, evXBC, evScores;
    if (!sW2) {
        cudaStreamCreateWithFlags(&sW2, cudaStreamNonBlocking);
        cudaStreamCreateWithFlags(&sCS, cudaStreamNonBlocking);
        cudaStreamCreateWithFlags(&sSC, cudaStreamNonBlocking);
        cudaEventCreateWithFlags(&evStart,  cudaEventDisableTiming);
        cudaEventCreateWithFlags(&evW2,     cudaEventDisableTiming);
        cudaEventCreateWithFlags(&evZX,     cudaEventDisableTiming);
        cudaEventCreateWithFlags(&evCum,    cudaEventDisableTiming);
        cudaEventCreateWithFlags(&evXBC,    cudaEventDisableTiming);
        cudaEventCreateWithFlags(&evScores, cudaEventDisableTiming);
    }

    const int M = BB * LL;   // 8192

    // fork point for the w2 convert (needed only by the final o_proj)
    cudaEventRecord(evStart, 0);
    cudaStreamWaitEvent(sW2, evStart, 0);
    {
        int n4 = (EMBED * DIN) / 4;
        cvt_h<<<(n4 + 255) / 256, 256, 0, sW2>>>(o_proj_w, w2h, n4);
        cudaEventRecord(evW2, sW2);
    }

    // critical path: split u (hi/lo), convert w1
    {
        int n4 = (M * EMBED) / 4;
        split2h<<<(n4 + 255) / 256, 256>>>(u, uh, ul, n4);
        n4 = (DPROJ * EMBED) / 4;
        cvt_h<<<(n4 + 255) / 256, 256>>>(in_proj_w, w1h, n4);
    }
    // 1) in_proj: zx = u @ W1^T  (HMMA fp16x2)
    hgemm2<<<dim3((DPROJ + HBN - 1) / HBN, M / HBM), 512, SMEM_GEMM>>>(
        M, DPROJ, EMBED, uh, ul, w1h, zx);
    cudaEventRecord(evZX, 0);

    // side: fused dt softplus + cumsum (depends only on zx)
    cudaStreamWaitEvent(sCS, evZX, 0);
    cumsum_k<<<NBC * NH, 32, 0, sCS>>>(A_log, dt_bias);
    cudaEventRecord(evCum, sCS);

    // 2) causal depthwise conv + silu (smem-tiled)
    conv_silu_k<<<dim3(CONVDIM / 64, LL / 128, BB), 256>>>(conv_w, conv_b);
    cudaEventRecord(evXBC, 0);

    // side: scores (depends only on xbc; feeds only ych)
    cudaStreamWaitEvent(sSC, evXBC, 0);
    scores_k<<<dim3(4, 4, NBC), 256, 0, sSC>>>();
    cudaEventRecord(evScores, sSC);

    // critical path: states (needs cumsum) -> scan
    cudaStreamWaitEvent(0, evCum, 0);
    states_k<<<NBC * NH, 256>>>();
    scan_k<<<dim3(BB * NH, 16), 512>>>();

    // join scores, then ych
    cudaStreamWaitEvent(0, evScores, 0);
    ych_k<<<dim3(4, NH, NBC), 256>>>(D_skip, norm_w);

    // join w2 convert, then o_proj
    cudaStreamWaitEvent(0, evW2, 0);
    hgemm2<<<dim3(EMBED / HBN, M / HBM), 512, SMEM_GEMM>>>(
        M, EMBED, DIN, ynh, ynl, w2h, out);
}